// round 6
// baseline (speedup 1.0000x reference)
#include <cuda_runtime.h>
#include <math.h>

#define N_  50000
#define T_  25
#define A_  16
#define H_  128
#define I_  64
#define E_  800000
#define G3_ 384   // 3*H
#define K_  144   // H + A

// Scratch (no allocations allowed): device globals.
__device__ float g_xln[N_ * H_];     // layernormed + src-norm-scaled features
__device__ float g_agg[N_ * H_];     // scatter-add accumulator
__device__ float g_deg_out[N_];
__device__ float g_deg_in[N_];

__device__ __forceinline__ float softplusf(float x) {
    return x > 0.f ? x + log1pf(expf(-x)) : log1pf(expf(x));
}

// ---------------------------------------------------------------------------
// GRU: 16 rows per block, all 25 steps in-block. W (transposed k-major) and the
// [h | x_t] tile live in smem. Thread tile: 4 rows x 2 cols x {r,z,hn,in}.
// smem = 144*384*4 + 16*144*4 = 230400 bytes.
// ---------------------------------------------------------------------------
__global__ void __launch_bounds__(256, 1) gru_kernel(
    const float* __restrict__ actions,  // (N, T, A)
    const float* __restrict__ hidden,   // (1, N, H)
    const float* __restrict__ W_ih,     // (3H, A)
    const float* __restrict__ W_hh,     // (3H, H)
    const float* __restrict__ b_ih,     // (3H)
    const float* __restrict__ b_hh,     // (3H)
    float* __restrict__ h_out)          // (N, H) -> d_out tail region
{
    extern __shared__ float sm[];
    float* Ws = sm;               // [K_][G3_]  (k-major transposed weights)
    float* hx = sm + K_ * G3_;    // [16][K_]   (h in cols 0..127, x in 128..143)

    const int tid   = threadIdx.x;
    const int rowg  = tid >> 6;        // 0..3  (constant within a warp)
    const int l2    = tid & 63;        // 0..63
    const int c0    = l2 << 1;         // column base, 0..126 (even)
    const int r0    = rowg << 2;       // local row base
    const int grow0 = blockIdx.x << 4; // global row base (16 rows/block)

    // Stage W_hh: [g][k] -> Ws[k][g], k in [0,128)
    for (int idx = tid; idx < G3_ * (H_ / 4); idx += 256) {
        int g  = idx >> 5;
        int k  = (idx & 31) << 2;
        float4 w = __ldg(reinterpret_cast<const float4*>(W_hh) + idx);
        Ws[(k + 0) * G3_ + g] = w.x;
        Ws[(k + 1) * G3_ + g] = w.y;
        Ws[(k + 2) * G3_ + g] = w.z;
        Ws[(k + 3) * G3_ + g] = w.w;
    }
    // Stage W_ih: [g][a] -> Ws[128+a][g]
    for (int idx = tid; idx < G3_ * (A_ / 4); idx += 256) {
        int g = idx >> 2;
        int k = 128 + ((idx & 3) << 2);
        float4 w = __ldg(reinterpret_cast<const float4*>(W_ih) + idx);
        Ws[(k + 0) * G3_ + g] = w.x;
        Ws[(k + 1) * G3_ + g] = w.y;
        Ws[(k + 2) * G3_ + g] = w.z;
        Ws[(k + 3) * G3_ + g] = w.w;
    }
    // Stage h0
    for (int idx = tid; idx < 16 * (H_ / 4); idx += 256) {
        int r  = idx >> 5;
        int k4 = idx & 31;
        float4 v = __ldg(reinterpret_cast<const float4*>(hidden + (grow0 + r) * H_) + k4);
        *reinterpret_cast<float4*>(&hx[r * K_ + (k4 << 2)]) = v;
    }
    // Biases for this thread's two columns (gate order r,z,n)
    float br0 = __ldg(b_ih + c0)       + __ldg(b_hh + c0);
    float br1 = __ldg(b_ih + c0 + 1)   + __ldg(b_hh + c0 + 1);
    float bz0 = __ldg(b_ih + 128 + c0)     + __ldg(b_hh + 128 + c0);
    float bz1 = __ldg(b_ih + 128 + c0 + 1) + __ldg(b_hh + 128 + c0 + 1);
    float bi0 = __ldg(b_ih + 256 + c0);
    float bi1 = __ldg(b_ih + 256 + c0 + 1);
    float bh0 = __ldg(b_hh + 256 + c0);
    float bh1 = __ldg(b_hh + 256 + c0 + 1);
    __syncthreads();

    const float* act_base = actions + (long long)grow0 * (T_ * A_);

    for (int t = 0; t < T_; ++t) {
        // load x_t tile (16 rows x 16) into hx[.][128..143]
        {
            int r = tid >> 4, a = tid & 15;
            hx[r * K_ + 128 + a] = __ldg(act_base + r * (T_ * A_) + t * A_ + a);
        }
        __syncthreads();

        float ar[4][2], az[4][2], ahn[4][2], ain[4][2];
        #pragma unroll
        for (int m = 0; m < 4; ++m) {
            ar[m][0] = br0;  ar[m][1] = br1;
            az[m][0] = bz0;  az[m][1] = bz1;
            ahn[m][0] = bh0; ahn[m][1] = bh1;
            ain[m][0] = bi0; ain[m][1] = bi1;
        }

        // recurrent part: k in [0,128)
        #pragma unroll 4
        for (int k = 0; k < 128; ++k) {
            float2 wr = *reinterpret_cast<const float2*>(&Ws[k * G3_ + c0]);
            float2 wz = *reinterpret_cast<const float2*>(&Ws[k * G3_ + 128 + c0]);
            float2 wn = *reinterpret_cast<const float2*>(&Ws[k * G3_ + 256 + c0]);
            #pragma unroll
            for (int m = 0; m < 4; ++m) {
                float h = hx[(r0 + m) * K_ + k];
                ar[m][0]  += h * wr.x;  ar[m][1]  += h * wr.y;
                az[m][0]  += h * wz.x;  az[m][1]  += h * wz.y;
                ahn[m][0] += h * wn.x;  ahn[m][1] += h * wn.y;
            }
        }
        // input part: k in [128,144) -> r,z merged; n goes to ain (separate!)
        #pragma unroll
        for (int k = 128; k < 144; ++k) {
            float2 wr = *reinterpret_cast<const float2*>(&Ws[k * G3_ + c0]);
            float2 wz = *reinterpret_cast<const float2*>(&Ws[k * G3_ + 128 + c0]);
            float2 wn = *reinterpret_cast<const float2*>(&Ws[k * G3_ + 256 + c0]);
            #pragma unroll
            for (int m = 0; m < 4; ++m) {
                float xv = hx[(r0 + m) * K_ + k];
                ar[m][0]  += xv * wr.x;  ar[m][1]  += xv * wr.y;
                az[m][0]  += xv * wz.x;  az[m][1]  += xv * wz.y;
                ain[m][0] += xv * wn.x;  ain[m][1] += xv * wn.y;
            }
        }

        // read h_old (before anyone overwrites), then sync, then write h_new
        float hold[4][2];
        #pragma unroll
        for (int m = 0; m < 4; ++m) {
            hold[m][0] = hx[(r0 + m) * K_ + c0];
            hold[m][1] = hx[(r0 + m) * K_ + c0 + 1];
        }
        __syncthreads();

        #pragma unroll
        for (int m = 0; m < 4; ++m) {
            #pragma unroll
            for (int jc = 0; jc < 2; ++jc) {
                float r = 1.f / (1.f + expf(-ar[m][jc]));
                float z = 1.f / (1.f + expf(-az[m][jc]));
                float n = tanhf(ain[m][jc] + r * ahn[m][jc]);
                float hnew = (1.f - z) * n + z * hold[m][jc];
                if (t == T_ - 1)
                    h_out[(grow0 + r0 + m) * H_ + c0 + jc] = hnew;
                else
                    hx[(r0 + m) * K_ + c0 + jc] = hnew;
            }
        }
        // next iteration's __syncthreads (after x load) orders hnew writes
    }
}

// ---------------------------------------------------------------------------
// LayerNorm + scale by src-norm (deg_out^-0.5). One warp per row.
// ---------------------------------------------------------------------------
__global__ void __launch_bounds__(256) ln_scale_kernel(
    const float* __restrict__ h, const float* __restrict__ ln_g,
    const float* __restrict__ ln_b)
{
    int row  = (blockIdx.x << 3) + (threadIdx.x >> 5);
    int lane = threadIdx.x & 31;
    float4 v = __ldg(reinterpret_cast<const float4*>(h + row * H_) + lane);
    float s  = v.x + v.y + v.z + v.w;
    float ss = v.x * v.x + v.y * v.y + v.z * v.z + v.w * v.w;
    #pragma unroll
    for (int o = 16; o > 0; o >>= 1) {
        s  += __shfl_xor_sync(0xffffffffu, s, o);
        ss += __shfl_xor_sync(0xffffffffu, ss, o);
    }
    float mu  = s * (1.f / 128.f);
    float var = ss * (1.f / 128.f) - mu * mu;
    float inv = rsqrtf(var + 1e-5f);
    float dg  = g_deg_out[row];
    float ns  = dg > 0.f ? rsqrtf(dg) : 1.f;
    float4 g4 = __ldg(reinterpret_cast<const float4*>(ln_g) + lane);
    float4 b4 = __ldg(reinterpret_cast<const float4*>(ln_b) + lane);
    float4 o4;
    o4.x = ((v.x - mu) * inv * g4.x + b4.x) * ns;
    o4.y = ((v.y - mu) * inv * g4.y + b4.y) * ns;
    o4.z = ((v.z - mu) * inv * g4.z + b4.z) * ns;
    o4.w = ((v.w - mu) * inv * g4.w + b4.w) * ns;
    *reinterpret_cast<float4*>(g_xln + row * H_ + (lane << 2)) = o4;
}

__global__ void zero_deg_kernel() {
    int i = blockIdx.x * 256 + threadIdx.x;
    if (i < N_) { g_deg_in[i] = 0.f; g_deg_out[i] = 0.f; }
}

__global__ void zero_agg_kernel() {
    int i = blockIdx.x * 256 + threadIdx.x;   // N_*H_/4 = 1,600,000 exact
    reinterpret_cast<float4*>(g_agg)[i] = make_float4(0.f, 0.f, 0.f, 0.f);
}

__global__ void degree_kernel(const int* __restrict__ src, const int* __restrict__ dst) {
    int e = blockIdx.x * 256 + threadIdx.x;   // grid exact: E_/256
    atomicAdd(&g_deg_out[__ldg(src + e)], 1.f);
    atomicAdd(&g_deg_in[__ldg(dst + e)], 1.f);
}

// One warp per edge; lane handles a float4 column chunk. float4 atomics (sm_90+).
__global__ void scatter_kernel(const int* __restrict__ src, const int* __restrict__ dst) {
    int gid = blockIdx.x * 256 + threadIdx.x;
    int e = gid >> 5, c = gid & 31;
    int s = __ldg(src + e), d = __ldg(dst + e);
    float4 v = *reinterpret_cast<const float4*>(g_xln + s * H_ + (c << 2));
    atomicAdd(reinterpret_cast<float4*>(g_agg + d * H_ + (c << 2)), v);
}

// ---------------------------------------------------------------------------
// Fused: y = (agg * deg_in^-0.5) @ Wg + bg ; 4 heads with softplus on stds.
// 8 rows per block (warp per row). Head weights staged transposed in smem.
// smem = (4*128*64 + 8*128 + 8*128)*4 = 139264 bytes.
// ---------------------------------------------------------------------------
__global__ void __launch_bounds__(256) final_kernel(
    const float* __restrict__ Wg,    const float* __restrict__ bg,
    const float* __restrict__ Wa_mu, const float* __restrict__ ba_mu,
    const float* __restrict__ Wa_sd, const float* __restrict__ ba_sd,
    const float* __restrict__ Wz_mu, const float* __restrict__ bz_mu,
    const float* __restrict__ Wz_sd, const float* __restrict__ bz_sd,
    float* __restrict__ out)
{
    extern __shared__ float fsm[];
    float* Wt = fsm;                 // [4][128][64] transposed head weights
    float* tb = fsm + 4 * 128 * 64;  // [8][128]
    float* yb = tb + 8 * 128;        // [8][128]

    // stage head weights transposed: Wt[head][k][i] = W[head][i][k]
    for (int idx = threadIdx.x; idx < 4 * I_ * H_; idx += 256) {
        int head = idx >> 13;
        int rem  = idx & 8191;
        int i    = rem >> 7;
        int k    = rem & 127;
        const float* W = head == 0 ? Wa_mu : head == 1 ? Wa_sd
                       : head == 2 ? Wz_mu : Wz_sd;
        Wt[(head << 13) + (k << 6) + i] = __ldg(W + rem);
    }

    int rw   = threadIdx.x >> 5;
    int lane = threadIdx.x & 31;
    int row  = (blockIdx.x << 3) + rw;

    // phase 1: t = agg * dst-norm
    {
        float dg = g_deg_in[row];
        float nd = dg > 0.f ? rsqrtf(dg) : 1.f;
        float4 v = *reinterpret_cast<const float4*>(g_agg + row * H_ + (lane << 2));
        v.x *= nd; v.y *= nd; v.z *= nd; v.w *= nd;
        *reinterpret_cast<float4*>(&tb[(rw << 7) + (lane << 2)]) = v;
    }
    __syncthreads();

    // phase 2: y = t @ Wg + bg   (Wg is (in,out): Wg[k*128 + j])
    float acc[4] = {0.f, 0.f, 0.f, 0.f};
    for (int k = 0; k < 128; ++k) {
        float tv = tb[(rw << 7) + k];
        #pragma unroll
        for (int q = 0; q < 4; ++q)
            acc[q] += tv * __ldg(Wg + (k << 7) + lane + (q << 5));
    }
    #pragma unroll
    for (int q = 0; q < 4; ++q)
        yb[(rw << 7) + lane + (q << 5)] = acc[q] + __ldg(bg + lane + (q << 5));
    __syncthreads();

    // phase 3: heads
    float ha0[2] = {0.f, 0.f}, ha1[2] = {0.f, 0.f};
    float hz0[2] = {0.f, 0.f}, hz1[2] = {0.f, 0.f};
    for (int k = 0; k < 128; ++k) {
        float yv = yb[(rw << 7) + k];
        int base = (k << 6) + lane;
        ha0[0] += yv * Wt[0 * 8192 + base];      ha0[1] += yv * Wt[0 * 8192 + base + 32];
        ha1[0] += yv * Wt[1 * 8192 + base];      ha1[1] += yv * Wt[1 * 8192 + base + 32];
        hz0[0] += yv * Wt[2 * 8192 + base];      hz0[1] += yv * Wt[2 * 8192 + base + 32];
        hz1[0] += yv * Wt[3 * 8192 + base];      hz1[1] += yv * Wt[3 * 8192 + base + 32];
    }
    // output order: zIG_mu | zIG_std | zIA_mu | zIA_std | h
    const int NI = N_ * I_;
    #pragma unroll
    for (int q = 0; q < 2; ++q) {
        int i = lane + (q << 5);
        out[2 * NI + row * I_ + i] = ha0[q] + __ldg(ba_mu + i);
        out[3 * NI + row * I_ + i] = softplusf(ha1[q] + __ldg(ba_sd + i));
        out[0      + row * I_ + i] = hz0[q] + __ldg(bz_mu + i);
        out[1 * NI + row * I_ + i] = softplusf(hz1[q] + __ldg(bz_sd + i));
    }
}

// ---------------------------------------------------------------------------
extern "C" void kernel_launch(void* const* d_in, const int* in_sizes, int n_in,
                              void* d_out, int out_size) {
    const float* actions = (const float*)d_in[0];
    const float* hidden  = (const float*)d_in[1];
    const int*   src     = (const int*)d_in[2];
    const int*   dst     = (const int*)d_in[3];
    const float* W_ih    = (const float*)d_in[4];
    const float* W_hh    = (const float*)d_in[5];
    const float* b_ih    = (const float*)d_in[6];
    const float* b_hh    = (const float*)d_in[7];
    const float* ln_g    = (const float*)d_in[8];
    const float* ln_b    = (const float*)d_in[9];
    const float* Wg      = (const float*)d_in[10];
    const float* bg      = (const float*)d_in[11];
    const float* Wa_mu   = (const float*)d_in[12];
    const float* ba_mu   = (const float*)d_in[13];
    const float* Wa_sd   = (const float*)d_in[14];
    const float* ba_sd   = (const float*)d_in[15];
    const float* Wz_mu   = (const float*)d_in[16];
    const float* bz_mu   = (const float*)d_in[17];
    const float* Wz_sd   = (const float*)d_in[18];
    const float* bz_sd   = (const float*)d_in[19];

    float* out   = (float*)d_out;
    float* h_out = out + 4 * N_ * I_;   // h region at tail

    const int GRU_SMEM = (K_ * G3_ + 16 * K_) * 4;             // 230400
    const int FIN_SMEM = (4 * I_ * H_ + 8 * H_ + 8 * H_) * 4;  // 139264
    cudaFuncSetAttribute(gru_kernel, cudaFuncAttributeMaxDynamicSharedMemorySize, GRU_SMEM);
    cudaFuncSetAttribute(final_kernel, cudaFuncAttributeMaxDynamicSharedMemorySize, FIN_SMEM);

    gru_kernel<<<N_ / 16, 256, GRU_SMEM>>>(actions, hidden, W_ih, W_hh, b_ih, b_hh, h_out);
    zero_deg_kernel<<<(N_ + 255) / 256, 256>>>();
    zero_agg_kernel<<<N_ * H_ / 4 / 256, 256>>>();
    degree_kernel<<<E_ / 256, 256>>>(src, dst);
    ln_scale_kernel<<<N_ / 8, 256>>>(h_out, ln_g, ln_b);
    scatter_kernel<<<E_ * 32 / 256, 256>>>(src, dst);
    final_kernel<<<N_ / 8, 256, FIN_SMEM>>>(Wg, bg, Wa_mu, ba_mu, Wa_sd, ba_sd,
                                            Wz_mu, bz_mu, Wz_sd, bz_sd, out);
}

// round 8
// speedup vs baseline: 1.3822x; 1.3822x over previous
#include <cuda_runtime.h>
#include <cuda_bf16.h>
#include <math.h>

#define N_  50000
#define T_  25
#define A_  16
#define H_  128
#define I_  64
#define E_  800000

// Scratch (no allocations allowed): device globals.
__device__ float g_xln[N_ * H_];
__device__ float g_agg[N_ * H_];
__device__ float g_deg_out[N_];
__device__ float g_deg_in[N_];

__device__ __forceinline__ float softplusf(float x) {
    return x > 0.f ? x + log1pf(expf(-x)) : log1pf(expf(x));
}

// ===========================================================================
// GRU via warp-level mma.sync bf16 (HMMA), split-bf16 3-pass for fp32-class
// accuracy. 16 rows/block, 8 warps, 384 output cols ordered per-warp as
// [r(16) | z(16) | n(16)] so gate math stays warp-local.
// smem layout (bytes):
//   WHI 0..98304        : W_hh hi, k-major [k 0..127][col 0..383], swizzled
//   WLO 98304..196608   : W_hh lo
//   BX  196608..221184  : rows 0..15 = W_ih hi, 16..31 = W_ih lo (k-major)
//   AHHI 221184..225280 : h hi, 16 rows x 128 k
//   AHLO 225280..229376 : h lo
//   AX  229376..230400  : x tile, 16 rows x 32 k (0..15 hi, 16..31 lo)
// ===========================================================================
#define OFF_WHI   0
#define OFF_WLO   98304
#define OFF_BX    196608
#define OFF_AHHI  221184
#define OFF_AHLO  225280
#define OFF_AX    229376
#define GRU_SMEM  230400

__device__ __forceinline__ unsigned s2u(const void* p) {
    unsigned a;
    asm("{ .reg .u64 t; cvta.to.shared.u64 t, %1; cvt.u32.u64 %0, t; }"
        : "=r"(a) : "l"(p));
    return a;
}

// store offsets (element granularity)
__device__ __forceinline__ int offW(int k, int c) {   // row stride 768B
    return k * 768 + ((((c >> 3) ^ (k & 7)) << 4) + ((c & 7) << 1));
}
__device__ __forceinline__ int offA(int r, int k) {   // row stride 256B
    return r * 256 + ((((k >> 3) ^ (r & 7)) << 4) + ((k & 7) << 1));
}
__device__ __forceinline__ int offX(int r, int k) {   // row stride 64B
    return r * 64 + ((((k >> 3) ^ (r & 3)) << 4) + ((k & 7) << 1));
}

__device__ __forceinline__ void ldmA(unsigned addr, unsigned& a0, unsigned& a1,
                                     unsigned& a2, unsigned& a3) {
    asm volatile("ldmatrix.sync.aligned.m8n8.x4.shared.b16 {%0,%1,%2,%3}, [%4];"
                 : "=r"(a0), "=r"(a1), "=r"(a2), "=r"(a3) : "r"(addr));
}
__device__ __forceinline__ void ldmB(unsigned addr, unsigned& b0, unsigned& b1) {
    asm volatile("ldmatrix.sync.aligned.m8n8.x2.trans.shared.b16 {%0,%1}, [%2];"
                 : "=r"(b0), "=r"(b1) : "r"(addr));
}
__device__ __forceinline__ void mma16816(float d[4], unsigned a0, unsigned a1,
                                         unsigned a2, unsigned a3,
                                         unsigned b0, unsigned b1) {
    asm volatile(
        "mma.sync.aligned.m16n8k16.row.col.f32.bf16.bf16.f32 "
        "{%0,%1,%2,%3},{%4,%5,%6,%7},{%8,%9},{%0,%1,%2,%3};"
        : "+f"(d[0]), "+f"(d[1]), "+f"(d[2]), "+f"(d[3])
        : "r"(a0), "r"(a1), "r"(a2), "r"(a3), "r"(b0), "r"(b1));
}

__device__ __forceinline__ unsigned short bfh(float x) {
    return __bfloat16_as_ushort(__float2bfloat16(x));
}
__device__ __forceinline__ float bfhf(float x) {
    return __bfloat162float(__float2bfloat16(x));
}
__device__ __forceinline__ float u16f(unsigned short u) {
    return __bfloat162float(__ushort_as_bfloat16(u));
}

__global__ void __launch_bounds__(256, 1) gru_mma_kernel(
    const float* __restrict__ actions,  // (N, T, A)
    const float* __restrict__ hidden,   // (1, N, H)
    const float* __restrict__ W_ih,     // (3H, A)
    const float* __restrict__ W_hh,     // (3H, H)
    const float* __restrict__ b_ih,     // (3H)
    const float* __restrict__ b_hh,     // (3H)
    float* __restrict__ h_out)          // (N, H)
{
    extern __shared__ char sm[];
    const unsigned sb = s2u(sm);
    const int tid  = threadIdx.x;
    const int w    = tid >> 5;        // warp 0..7
    const int lane = tid & 31;
    const int grow0 = blockIdx.x << 4;

    // ---- stage W_hh hi/lo (col c -> warp-blocked gate layout) ----
    // c = wgrp*48 + g*16 + u ; unit j = wgrp*16+u ; W row = g*128 + j
    for (int idx = tid; idx < 128 * 384; idx += 256) {
        int k = idx / 384, c = idx - k * 384;
        int wgrp = c / 48, rem = c - wgrp * 48;
        int g = rem >> 4, u = rem & 15;
        int j = (wgrp << 4) + u;
        float v = __ldg(W_hh + (g * 128 + j) * 128 + k);
        float hf = bfhf(v);
        int o = offW(k, c);
        *(unsigned short*)(sm + OFF_WHI + o) = bfh(v);
        *(unsigned short*)(sm + OFF_WLO + o) = bfh(v - hf);
    }
    // ---- stage W_ih hi/lo ----
    for (int idx = tid; idx < 16 * 384; idx += 256) {
        int a = idx / 384, c = idx - a * 384;
        int wgrp = c / 48, rem = c - wgrp * 48;
        int g = rem >> 4, u = rem & 15;
        int j = (wgrp << 4) + u;
        float v = __ldg(W_ih + (g * 128 + j) * 16 + a);
        float hf = bfhf(v);
        *(unsigned short*)(sm + OFF_BX + offW(a, c))      = bfh(v);
        *(unsigned short*)(sm + OFF_BX + offW(a + 16, c)) = bfh(v - hf);
    }
    // ---- stage h0 hi/lo ----
    for (int idx = tid; idx < 16 * 128; idx += 256) {
        int r = idx >> 7, k = idx & 127;
        float v = __ldg(hidden + (size_t)(grow0 + r) * H_ + k);
        float hf = bfhf(v);
        int o = offA(r, k);
        *(unsigned short*)(sm + OFF_AHHI + o) = bfh(v);
        *(unsigned short*)(sm + OFF_AHLO + o) = bfh(v - hf);
    }

    // ---- per-thread biases for its 4 units ----
    const int tr = lane >> 2;
    const int uc = (lane & 3) << 1;
    float br[4], bz[4], bin[4], bhn[4];
    #pragma unroll
    for (int p = 0; p < 2; ++p)
        #pragma unroll
        for (int q = 0; q < 2; ++q) {
            int j = (w << 4) + (p << 3) + uc + q;
            int u = p * 2 + q;
            br[u]  = __ldg(b_ih + j)       + __ldg(b_hh + j);
            bz[u]  = __ldg(b_ih + 128 + j) + __ldg(b_hh + 128 + j);
            bin[u] = __ldg(b_ih + 256 + j);
            bhn[u] = __ldg(b_hh + 256 + j);
        }

    // per-lane address pieces
    const int l15 = lane & 15, l7 = lane & 7, hb = lane >> 4;  // hb in {0,1}
    const unsigned aRow = sb + (unsigned)(l15 * 256);          // + region off
    const unsigned bRow = (unsigned)(l15 * 768);
    int ctile[6];
    #pragma unroll
    for (int t6 = 0; t6 < 6; ++t6) ctile[t6] = ((w * 6 + t6) ^ l7) << 4;

    __syncthreads();

    for (int t = 0; t < T_; ++t) {
        // stage x_t hi/lo (exactly 256 elements)
        {
            int r = tid >> 4, a = tid & 15;
            float v = __ldg(actions + (size_t)(grow0 + r) * 400 + t * 16 + a);
            float hf = bfhf(v);
            *(unsigned short*)(sm + OFF_AX + offX(r, a))      = bfh(v);
            *(unsigned short*)(sm + OFF_AX + offX(r, 16 + a)) = bfh(v - hf);
        }
        __syncthreads();   // x ready; prev-step h writes visible

        float hacc[6][4] = {};   // [r0 r1 z0 z1 n0 n1][4]
        float niacc[2][4] = {};  // gi_n tiles

        // ---- h passes: hi*Whi + lo*Whi + hi*Wlo over 8 ksteps ----
        #pragma unroll
        for (int ks = 0; ks < 8; ++ks) {
            unsigned ah0, ah1, ah2, ah3, al0, al1, al2, al3;
            unsigned aoff = (unsigned)((((ks << 1) + hb) ^ l7) << 4);
            ldmA(aRow + OFF_AHHI + aoff, ah0, ah1, ah2, ah3);
            ldmA(aRow + OFF_AHLO + aoff, al0, al1, al2, al3);
            unsigned kb = sb + bRow + (unsigned)(ks * 12288);
            #pragma unroll
            for (int t6 = 0; t6 < 6; ++t6) {
                unsigned b0, b1;
                ldmB(kb + OFF_WHI + ctile[t6], b0, b1);
                mma16816(hacc[t6], ah0, ah1, ah2, ah3, b0, b1);
                mma16816(hacc[t6], al0, al1, al2, al3, b0, b1);
                ldmB(kb + OFF_WLO + ctile[t6], b0, b1);
                mma16816(hacc[t6], ah0, ah1, ah2, ah3, b0, b1);
            }
        }
        // ---- x pass: xhi*Wxhi + xlo*Wxhi + xhi*Wxlo ----
        {
            unsigned xh0, xh1, xh2, xh3, xl0, xl1, xl2, xl3;
            unsigned axh = sb + OFF_AX + (unsigned)(l15 * 64) +
                           (unsigned)(((hb) ^ (lane & 3)) << 4);
            unsigned axl = sb + OFF_AX + (unsigned)(l15 * 64) +
                           (unsigned)(((2 + hb) ^ (lane & 3)) << 4);
            ldmA(axh, xh0, xh1, xh2, xh3);
            ldmA(axl, xl0, xl1, xl2, xl3);
            unsigned kbh = sb + OFF_BX + bRow;            // rows 0..15 (hi)
            unsigned kbl = kbh + 16 * 768;                // rows 16..31 (lo)
            #pragma unroll
            for (int t6 = 0; t6 < 6; ++t6) {
                float* dst = (t6 < 4) ? hacc[t6] : niacc[t6 - 4];
                unsigned b0, b1;
                ldmB(kbh + ctile[t6], b0, b1);
                mma16816(dst, xh0, xh1, xh2, xh3, b0, b1);
                mma16816(dst, xl0, xl1, xl2, xl3, b0, b1);
                ldmB(kbl + ctile[t6], b0, b1);
                mma16816(dst, xh0, xh1, xh2, xh3, b0, b1);
            }
        }

        // ---- read h_old (hi+lo) for this thread's 8 elems ----
        float hold[8];
        #pragma unroll
        for (int p = 0; p < 2; ++p)
            #pragma unroll
            for (int s = 0; s < 2; ++s)
                #pragma unroll
                for (int q = 0; q < 2; ++q) {
                    int row = tr + (s << 3);
                    int j = (w << 4) + (p << 3) + uc + q;
                    int o = offA(row, j);
                    hold[p * 4 + s * 2 + q] =
                        u16f(*(unsigned short*)(sm + OFF_AHHI + o)) +
                        u16f(*(unsigned short*)(sm + OFF_AHLO + o));
                }

        __syncthreads();   // all reads of AH/AX complete before overwrite

        // ---- gate math + write h_new ----
        #pragma unroll
        for (int p = 0; p < 2; ++p)
            #pragma unroll
            for (int s = 0; s < 2; ++s)
                #pragma unroll
                for (int q = 0; q < 2; ++q) {
                    int i = s * 2 + q;
                    int u = p * 2 + q;
                    float pr = hacc[p][i]     + br[u];
                    float pz = hacc[2 + p][i] + bz[u];
                    float gn = hacc[4 + p][i] + bhn[u];
                    float gi = niacc[p][i]    + bin[u];
                    float rg = 1.f / (1.f + __expf(-pr));
                    float zg = 1.f / (1.f + __expf(-pz));
                    float pre = fmaf(rg, gn, gi);
                    float e2 = __expf(2.f * pre);
                    float ng = 1.f - 2.f / (e2 + 1.f);
                    float hn = ng + zg * (hold[p * 4 + i] - ng);
                    int row = tr + (s << 3);
                    int j = (w << 4) + (p << 3) + uc + q;
                    if (t == T_ - 1) {
                        h_out[(size_t)(grow0 + row) * H_ + j] = hn;
                    } else {
                        float hf = bfhf(hn);
                        int o = offA(row, j);
                        *(unsigned short*)(sm + OFF_AHHI + o) = bfh(hn);
                        *(unsigned short*)(sm + OFF_AHLO + o) = bfh(hn - hf);
                    }
                }
    }
}

// ===========================================================================
// Post-GRU kernels (unchanged from passing round)
// ===========================================================================
__global__ void __launch_bounds__(256) ln_scale_kernel(
    const float* __restrict__ h, const float* __restrict__ ln_g,
    const float* __restrict__ ln_b)
{
    int row  = (blockIdx.x << 3) + (threadIdx.x >> 5);
    int lane = threadIdx.x & 31;
    float4 v = __ldg(reinterpret_cast<const float4*>(h + row * H_) + lane);
    float s  = v.x + v.y + v.z + v.w;
    float ss = v.x * v.x + v.y * v.y + v.z * v.z + v.w * v.w;
    #pragma unroll
    for (int o = 16; o > 0; o >>= 1) {
        s  += __shfl_xor_sync(0xffffffffu, s, o);
        ss += __shfl_xor_sync(0xffffffffu, ss, o);
    }
    float mu  = s * (1.f / 128.f);
    float var = ss * (1.f / 128.f) - mu * mu;
    float inv = rsqrtf(var + 1e-5f);
    float dg  = g_deg_out[row];
    float ns  = dg > 0.f ? rsqrtf(dg) : 1.f;
    float4 g4 = __ldg(reinterpret_cast<const float4*>(ln_g) + lane);
    float4 b4 = __ldg(reinterpret_cast<const float4*>(ln_b) + lane);
    float4 o4;
    o4.x = ((v.x - mu) * inv * g4.x + b4.x) * ns;
    o4.y = ((v.y - mu) * inv * g4.y + b4.y) * ns;
    o4.z = ((v.z - mu) * inv * g4.z + b4.z) * ns;
    o4.w = ((v.w - mu) * inv * g4.w + b4.w) * ns;
    *reinterpret_cast<float4*>(g_xln + row * H_ + (lane << 2)) = o4;
}

__global__ void zero_deg_kernel() {
    int i = blockIdx.x * 256 + threadIdx.x;
    if (i < N_) { g_deg_in[i] = 0.f; g_deg_out[i] = 0.f; }
}
__global__ void zero_agg_kernel() {
    int i = blockIdx.x * 256 + threadIdx.x;
    reinterpret_cast<float4*>(g_agg)[i] = make_float4(0.f, 0.f, 0.f, 0.f);
}
__global__ void degree_kernel(const int* __restrict__ src, const int* __restrict__ dst) {
    int e = blockIdx.x * 256 + threadIdx.x;
    atomicAdd(&g_deg_out[__ldg(src + e)], 1.f);
    atomicAdd(&g_deg_in[__ldg(dst + e)], 1.f);
}
__global__ void scatter_kernel(const int* __restrict__ src, const int* __restrict__ dst) {
    int gid = blockIdx.x * 256 + threadIdx.x;
    int e = gid >> 5, c = gid & 31;
    int s = __ldg(src + e), d = __ldg(dst + e);
    float4 v = *reinterpret_cast<const float4*>(g_xln + s * H_ + (c << 2));
    atomicAdd(reinterpret_cast<float4*>(g_agg + d * H_ + (c << 2)), v);
}

__global__ void __launch_bounds__(256) final_kernel(
    const float* __restrict__ Wg,    const float* __restrict__ bg,
    const float* __restrict__ Wa_mu, const float* __restrict__ ba_mu,
    const float* __restrict__ Wa_sd, const float* __restrict__ ba_sd,
    const float* __restrict__ Wz_mu, const float* __restrict__ bz_mu,
    const float* __restrict__ Wz_sd, const float* __restrict__ bz_sd,
    float* __restrict__ out)
{
    extern __shared__ float fsm[];
    float* Wt = fsm;
    float* tb = fsm + 4 * 128 * 64;
    float* yb = tb + 8 * 128;

    for (int idx = threadIdx.x; idx < 4 * I_ * H_; idx += 256) {
        int head = idx >> 13;
        int rem  = idx & 8191;
        int i    = rem >> 7;
        int k    = rem & 127;
        const float* W = head == 0 ? Wa_mu : head == 1 ? Wa_sd
                       : head == 2 ? Wz_mu : Wz_sd;
        Wt[(head << 13) + (k << 6) + i] = __ldg(W + rem);
    }
    int rw   = threadIdx.x >> 5;
    int lane = threadIdx.x & 31;
    int row  = (blockIdx.x << 3) + rw;
    {
        float dg = g_deg_in[row];
        float nd = dg > 0.f ? rsqrtf(dg) : 1.f;
        float4 v = *reinterpret_cast<const float4*>(g_agg + row * H_ + (lane << 2));
        v.x *= nd; v.y *= nd; v.z *= nd; v.w *= nd;
        *reinterpret_cast<float4*>(&tb[(rw << 7) + (lane << 2)]) = v;
    }
    __syncthreads();
    float acc[4] = {0.f, 0.f, 0.f, 0.f};
    for (int k = 0; k < 128; ++k) {
        float tv = tb[(rw << 7) + k];
        #pragma unroll
        for (int q = 0; q < 4; ++q)
            acc[q] += tv * __ldg(Wg + (k << 7) + lane + (q << 5));
    }
    #pragma unroll
    for (int q = 0; q < 4; ++q)
        yb[(rw << 7) + lane + (q << 5)] = acc[q] + __ldg(bg + lane + (q << 5));
    __syncthreads();
    float ha0[2] = {0.f, 0.f}, ha1[2] = {0.f, 0.f};
    float hz0[2] = {0.f, 0.f}, hz1[2] = {0.f, 0.f};
    for (int k = 0; k < 128; ++k) {
        float yv = yb[(rw << 7) + k];
        int base = (k << 6) + lane;
        ha0[0] += yv * Wt[0 * 8192 + base];      ha0[1] += yv * Wt[0 * 8192 + base + 32];
        ha1[0] += yv * Wt[1 * 8192 + base];      ha1[1] += yv * Wt[1 * 8192 + base + 32];
        hz0[0] += yv * Wt[2 * 8192 + base];      hz0[1] += yv * Wt[2 * 8192 + base + 32];
        hz1[0] += yv * Wt[3 * 8192 + base];      hz1[1] += yv * Wt[3 * 8192 + base + 32];
    }
    const int NI = N_ * I_;
    #pragma unroll
    for (int q = 0; q < 2; ++q) {
        int i = lane + (q << 5);
        out[2 * NI + row * I_ + i] = ha0[q] + __ldg(ba_mu + i);
        out[3 * NI + row * I_ + i] = softplusf(ha1[q] + __ldg(ba_sd + i));
        out[0      + row * I_ + i] = hz0[q] + __ldg(bz_mu + i);
        out[1 * NI + row * I_ + i] = softplusf(hz1[q] + __ldg(bz_sd + i));
    }
}

// ---------------------------------------------------------------------------
extern "C" void kernel_launch(void* const* d_in, const int* in_sizes, int n_in,
                              void* d_out, int out_size) {
    const float* actions = (const float*)d_in[0];
    const float* hidden  = (const float*)d_in[1];
    const int*   src     = (const int*)d_in[2];
    const int*   dst     = (const int*)d_in[3];
    const float* W_ih    = (const float*)d_in[4];
    const float* W_hh    = (const float*)d_in[5];
    const float* b_ih    = (const float*)d_in[6];
    const float* b_hh    = (const float*)d_in[7];
    const float* ln_g    = (const float*)d_in[8];
    const float* ln_b    = (const float*)d_in[9];
    const float* Wg      = (const float*)d_in[10];
    const float* bg      = (const float*)d_in[11];
    const float* Wa_mu   = (const float*)d_in[12];
    const float* ba_mu   = (const float*)d_in[13];
    const float* Wa_sd   = (const float*)d_in[14];
    const float* ba_sd   = (const float*)d_in[15];
    const float* Wz_mu   = (const float*)d_in[16];
    const float* bz_mu   = (const float*)d_in[17];
    const float* Wz_sd   = (const float*)d_in[18];
    const float* bz_sd   = (const float*)d_in[19];

    float* out   = (float*)d_out;
    float* h_out = out + 4 * N_ * I_;

    const int FIN_SMEM = (4 * I_ * H_ + 8 * H_ + 8 * H_) * 4;
    cudaFuncSetAttribute(gru_mma_kernel, cudaFuncAttributeMaxDynamicSharedMemorySize, GRU_SMEM);
    cudaFuncSetAttribute(final_kernel, cudaFuncAttributeMaxDynamicSharedMemorySize, FIN_SMEM);

    gru_mma_kernel<<<N_ / 16, 256, GRU_SMEM>>>(actions, hidden, W_ih, W_hh, b_ih, b_hh, h_out);
    zero_deg_kernel<<<(N_ + 255) / 256, 256>>>();
    zero_agg_kernel<<<N_ * H_ / 4 / 256, 256>>>();
    degree_kernel<<<E_ / 256, 256>>>(src, dst);
    ln_scale_kernel<<<N_ / 8, 256>>>(h_out, ln_g, ln_b);
    scatter_kernel<<<E_ * 32 / 256, 256>>>(src, dst);
    final_kernel<<<N_ / 8, 256, FIN_SMEM>>>(Wg, bg, Wa_mu, ba_mu, Wa_sd, ba_sd,
                                            Wz_mu, bz_mu, Wz_sd, bz_sd, out);
}

// round 9
// speedup vs baseline: 1.8083x; 1.3082x over previous
#include <cuda_runtime.h>
#include <cuda_bf16.h>
#include <math.h>

#define N_  50000
#define T_  25
#define A_  16
#define H_  128
#define I_  64
#define E_  800000

// Scratch (no allocations allowed): device globals.
__device__ float g_xln[N_ * H_];
__device__ float g_agg[N_ * H_];
__device__ float g_deg_out[N_];
__device__ float g_deg_in[N_];

__device__ __forceinline__ float softplusf(float x) {
    return x > 0.f ? x + log1pf(expf(-x)) : log1pf(expf(x));
}

// ===========================================================================
// GRU via mma.sync bf16 (HMMA), split-bf16 3-pass. 16 rows/block, 16 warps.
// Column layout: c = gate*128 + j (gate 0=r,1=z,2=n). Warp w owns units
// 8w..8w+7 -> tiles cb = {w, 16+w, 32+w}. W_hh-hi fragments hoisted to regs.
// h state kept in fp32 registers across steps (thread->D map is fixed).
// smem:
//   WHI 0       : W_hh hi  [k 0..127][c 0..383] swizzled, 98304 B
//   WLO 98304   : W_hh lo                           98304 B
//   BX  196608  : rows 0..15 W_ih hi, 16..31 W_ih lo, 24576 B
//   AHHI 221184 : h hi, 16r x 128k, 4096 B
//   AHLO 225280 : h lo, 4096 B
//   AX   229376 : x, 16r x 32k (hi k0..15, lo k16..31), 1024 B
// ===========================================================================
#define OFF_WHI   0
#define OFF_WLO   98304
#define OFF_BX    196608
#define OFF_AHHI  221184
#define OFF_AHLO  225280
#define OFF_AX    229376
#define GRU_SMEM  230400

__device__ __forceinline__ unsigned s2u(const void* p) {
    unsigned a;
    asm("{ .reg .u64 t; cvta.to.shared.u64 t, %1; cvt.u32.u64 %0, t; }"
        : "=r"(a) : "l"(p));
    return a;
}
__device__ __forceinline__ int offW(int k, int c) {   // row stride 768B
    return k * 768 + ((((c >> 3) ^ (k & 7)) << 4) + ((c & 7) << 1));
}
__device__ __forceinline__ int offA(int r, int k) {   // row stride 256B
    return r * 256 + ((((k >> 3) ^ (r & 7)) << 4) + ((k & 7) << 1));
}
__device__ __forceinline__ int offX(int r, int k) {   // row stride 64B
    return r * 64 + ((((k >> 3) ^ (r & 3)) << 4) + ((k & 7) << 1));
}

__device__ __forceinline__ void ldmA(unsigned addr, unsigned& a0, unsigned& a1,
                                     unsigned& a2, unsigned& a3) {
    asm volatile("ldmatrix.sync.aligned.m8n8.x4.shared.b16 {%0,%1,%2,%3}, [%4];"
                 : "=r"(a0), "=r"(a1), "=r"(a2), "=r"(a3) : "r"(addr));
}
__device__ __forceinline__ void ldmB(unsigned addr, unsigned& b0, unsigned& b1) {
    asm volatile("ldmatrix.sync.aligned.m8n8.x2.trans.shared.b16 {%0,%1}, [%2];"
                 : "=r"(b0), "=r"(b1) : "r"(addr));
}
__device__ __forceinline__ void mma16816(float d[4], unsigned a0, unsigned a1,
                                         unsigned a2, unsigned a3,
                                         unsigned b0, unsigned b1) {
    asm volatile(
        "mma.sync.aligned.m16n8k16.row.col.f32.bf16.bf16.f32 "
        "{%0,%1,%2,%3},{%4,%5,%6,%7},{%8,%9},{%0,%1,%2,%3};"
        : "+f"(d[0]), "+f"(d[1]), "+f"(d[2]), "+f"(d[3])
        : "r"(a0), "r"(a1), "r"(a2), "r"(a3), "r"(b0), "r"(b1));
}

__device__ __forceinline__ unsigned short bfh(float x) {
    return __bfloat16_as_ushort(__float2bfloat16(x));
}
__device__ __forceinline__ float bfhf(float x) {
    return __bfloat162float(__float2bfloat16(x));
}

__global__ void __launch_bounds__(512, 1) gru_mma_kernel(
    const float* __restrict__ actions,  // (N, T, A)
    const float* __restrict__ hidden,   // (1, N, H)
    const float* __restrict__ W_ih,     // (3H, A)
    const float* __restrict__ W_hh,     // (3H, H)
    const float* __restrict__ b_ih,     // (3H)
    const float* __restrict__ b_hh,     // (3H)
    float* __restrict__ h_out)          // (N, H)
{
    extern __shared__ char sm[];
    const unsigned sb = s2u(sm);
    const int tid  = threadIdx.x;
    const int w    = tid >> 5;        // warp 0..15
    const int lane = tid & 31;
    const int grow0 = blockIdx.x << 4;

    // ---- stage W_hh hi/lo: column c == W_hh row c (coalesced) ----
    for (int idx = tid; idx < 384 * 128; idx += 512) {
        int c = idx >> 7, k = idx & 127;
        float v = __ldg(W_hh + idx);
        float hf = bfhf(v);
        int o = offW(k, c);
        *(unsigned short*)(sm + OFF_WHI + o) = bfh(v);
        *(unsigned short*)(sm + OFF_WLO + o) = bfh(v - hf);
    }
    // ---- stage W_ih hi/lo ----
    for (int idx = tid; idx < 384 * 16; idx += 512) {
        int c = idx >> 4, a = idx & 15;
        float v = __ldg(W_ih + idx);
        float hf = bfhf(v);
        int o = offW(a, c);   // row stride 768B, rows 0..15
        *(unsigned short*)(sm + OFF_BX + o)             = bfh(v);
        *(unsigned short*)(sm + OFF_BX + o + 16 * 768)  = bfh(v - hf);
    }
    // ---- stage h0 hi/lo ----
    for (int idx = tid; idx < 16 * 128; idx += 512) {
        int r = idx >> 7, k = idx & 127;
        float v = __ldg(hidden + (size_t)(grow0 + r) * H_ + k);
        float hf = bfhf(v);
        int o = offA(r, k);
        *(unsigned short*)(sm + OFF_AHHI + o) = bfh(v);
        *(unsigned short*)(sm + OFF_AHLO + o) = bfh(v - hf);
    }

    // ---- per-thread unit/bias setup ----
    const int tr = lane >> 2;                 // D row base
    const int j0 = (w << 3) + ((lane & 3) << 1);
    float br[2], bz[2], bin[2], bhn[2];
    #pragma unroll
    for (int q = 0; q < 2; ++q) {
        int j = j0 + q;
        br[q]  = __ldg(b_ih + j)       + __ldg(b_hh + j);
        bz[q]  = __ldg(b_ih + 128 + j) + __ldg(b_hh + 128 + j);
        bin[q] = __ldg(b_ih + 256 + j);
        bhn[q] = __ldg(b_hh + 256 + j);
    }
    // ---- h state in registers: hold[2s+q] = h[tr+8s][j0+q] ----
    float hold[4];
    #pragma unroll
    for (int s = 0; s < 2; ++s)
        #pragma unroll
        for (int q = 0; q < 2; ++q)
            hold[s * 2 + q] = __ldg(hidden + (size_t)(grow0 + tr + 8 * s) * H_ + j0 + q);

    // per-lane address pieces
    const int l15 = lane & 15, l7 = lane & 7, hb = lane >> 4;
    const unsigned bRow = (unsigned)(l15 * 768);
    int ctile[3];
    #pragma unroll
    for (int g = 0; g < 3; ++g) ctile[g] = (((g << 4) + w) ^ l7) << 4;

    __syncthreads();

    // ---- hoist W_hh-hi fragments: 8 ksteps x 3 tiles x 2 regs ----
    unsigned bhi[8][3][2];
    #pragma unroll
    for (int ks = 0; ks < 8; ++ks) {
        unsigned kb = sb + OFF_WHI + bRow + (unsigned)(ks * 12288);
        #pragma unroll
        for (int g = 0; g < 3; ++g)
            ldmB(kb + ctile[g], bhi[ks][g][0], bhi[ks][g][1]);
    }

    for (int t = 0; t < T_; ++t) {
        // stage x_t hi/lo (256 elements)
        if (tid < 256) {
            int r = tid >> 4, a = tid & 15;
            float v = __ldg(actions + (size_t)(grow0 + r) * (T_ * A_) + t * A_ + a);
            float hf = bfhf(v);
            *(unsigned short*)(sm + OFF_AX + offX(r, a))      = bfh(v);
            *(unsigned short*)(sm + OFF_AX + offX(r, 16 + a)) = bfh(v - hf);
        }
        __syncthreads();   // x + prev-step h visible

        float accG[3][4] = {};   // r, z, n_h
        float accNI[4]   = {};   // n_i

        // ---- h passes over 8 ksteps: hi*Whi + lo*Whi + hi*Wlo ----
        #pragma unroll
        for (int ks = 0; ks < 8; ++ks) {
            unsigned ah0, ah1, ah2, ah3, al0, al1, al2, al3;
            unsigned aoff = (unsigned)((((ks << 1) + hb) ^ l7) << 4) +
                            (unsigned)(l15 * 256);
            ldmA(sb + OFF_AHHI + aoff, ah0, ah1, ah2, ah3);
            ldmA(sb + OFF_AHLO + aoff, al0, al1, al2, al3);
            unsigned wl[3][2];
            {
                unsigned kb = sb + OFF_WLO + bRow + (unsigned)(ks * 12288);
                #pragma unroll
                for (int g = 0; g < 3; ++g)
                    ldmB(kb + ctile[g], wl[g][0], wl[g][1]);
            }
            #pragma unroll
            for (int g = 0; g < 3; ++g) {
                mma16816(accG[g], ah0, ah1, ah2, ah3, bhi[ks][g][0], bhi[ks][g][1]);
                mma16816(accG[g], al0, al1, al2, al3, bhi[ks][g][0], bhi[ks][g][1]);
            }
            #pragma unroll
            for (int g = 0; g < 3; ++g)
                mma16816(accG[g], ah0, ah1, ah2, ah3, wl[g][0], wl[g][1]);
        }
        // ---- x pass: xhi*Wxhi + xlo*Wxhi + xhi*Wxlo ----
        {
            unsigned xh0, xh1, xh2, xh3, xl0, xl1, xl2, xl3;
            unsigned xbase = sb + OFF_AX + (unsigned)(l15 * 64);
            ldmA(xbase + (unsigned)(((hb) ^ (l15 & 3)) << 4),     xh0, xh1, xh2, xh3);
            ldmA(xbase + (unsigned)(((2 + hb) ^ (l15 & 3)) << 4), xl0, xl1, xl2, xl3);
            unsigned kbh = sb + OFF_BX + bRow;
            unsigned kbl = kbh + 12288;
            #pragma unroll
            for (int g = 0; g < 3; ++g) {
                float* dst = (g < 2) ? accG[g] : accNI;
                unsigned b0, b1;
                ldmB(kbh + ctile[g], b0, b1);
                mma16816(dst, xh0, xh1, xh2, xh3, b0, b1);
                mma16816(dst, xl0, xl1, xl2, xl3, b0, b1);
                ldmB(kbl + ctile[g], b0, b1);
                mma16816(dst, xh0, xh1, xh2, xh3, b0, b1);
            }
        }

        __syncthreads();   // all smem reads of AH/AX complete

        // ---- gate math; h state stays in registers ----
        #pragma unroll
        for (int s = 0; s < 2; ++s)
            #pragma unroll
            for (int q = 0; q < 2; ++q) {
                int i = s * 2 + q;
                float pr = accG[0][i] + br[q];
                float pz = accG[1][i] + bz[q];
                float gn = accG[2][i] + bhn[q];
                float gi = accNI[i]   + bin[q];
                float rg = 1.f / (1.f + __expf(-pr));
                float zg = 1.f / (1.f + __expf(-pz));
                float pre = fmaf(rg, gn, gi);
                float e2 = __expf(2.f * pre);
                float ng = 1.f - 2.f / (e2 + 1.f);
                float hn = ng + zg * (hold[i] - ng);
                hold[i] = hn;
                int row = tr + (s << 3);
                int j = j0 + q;
                if (t == T_ - 1) {
                    h_out[(size_t)(grow0 + row) * H_ + j] = hn;
                } else {
                    float hf = bfhf(hn);
                    int o = offA(row, j);
                    *(unsigned short*)(sm + OFF_AHHI + o) = bfh(hn);
                    *(unsigned short*)(sm + OFF_AHLO + o) = bfh(hn - hf);
                }
            }
    }
}

// ===========================================================================
// Post-GRU kernels (unchanged from passing round)
// ===========================================================================
__global__ void __launch_bounds__(256) ln_scale_kernel(
    const float* __restrict__ h, const float* __restrict__ ln_g,
    const float* __restrict__ ln_b)
{
    int row  = (blockIdx.x << 3) + (threadIdx.x >> 5);
    int lane = threadIdx.x & 31;
    float4 v = __ldg(reinterpret_cast<const float4*>(h + row * H_) + lane);
    float s  = v.x + v.y + v.z + v.w;
    float ss = v.x * v.x + v.y * v.y + v.z * v.z + v.w * v.w;
    #pragma unroll
    for (int o = 16; o > 0; o >>= 1) {
        s  += __shfl_xor_sync(0xffffffffu, s, o);
        ss += __shfl_xor_sync(0xffffffffu, ss, o);
    }
    float mu  = s * (1.f / 128.f);
    float var = ss * (1.f / 128.f) - mu * mu;
    float inv = rsqrtf(var + 1e-5f);
    float dg  = g_deg_out[row];
    float ns  = dg > 0.f ? rsqrtf(dg) : 1.f;
    float4 g4 = __ldg(reinterpret_cast<const float4*>(ln_g) + lane);
    float4 b4 = __ldg(reinterpret_cast<const float4*>(ln_b) + lane);
    float4 o4;
    o4.x = ((v.x - mu) * inv * g4.x + b4.x) * ns;
    o4.y = ((v.y - mu) * inv * g4.y + b4.y) * ns;
    o4.z = ((v.z - mu) * inv * g4.z + b4.z) * ns;
    o4.w = ((v.w - mu) * inv * g4.w + b4.w) * ns;
    *reinterpret_cast<float4*>(g_xln + row * H_ + (lane << 2)) = o4;
}

__global__ void zero_deg_kernel() {
    int i = blockIdx.x * 256 + threadIdx.x;
    if (i < N_) { g_deg_in[i] = 0.f; g_deg_out[i] = 0.f; }
}
__global__ void zero_agg_kernel() {
    int i = blockIdx.x * 256 + threadIdx.x;
    reinterpret_cast<float4*>(g_agg)[i] = make_float4(0.f, 0.f, 0.f, 0.f);
}
__global__ void degree_kernel(const int* __restrict__ src, const int* __restrict__ dst) {
    int e = blockIdx.x * 256 + threadIdx.x;
    atomicAdd(&g_deg_out[__ldg(src + e)], 1.f);
    atomicAdd(&g_deg_in[__ldg(dst + e)], 1.f);
}
__global__ void scatter_kernel(const int* __restrict__ src, const int* __restrict__ dst) {
    int gid = blockIdx.x * 256 + threadIdx.x;
    int e = gid >> 5, c = gid & 31;
    int s = __ldg(src + e), d = __ldg(dst + e);
    float4 v = *reinterpret_cast<const float4*>(g_xln + s * H_ + (c << 2));
    atomicAdd(reinterpret_cast<float4*>(g_agg + d * H_ + (c << 2)), v);
}

__global__ void __launch_bounds__(256) final_kernel(
    const float* __restrict__ Wg,    const float* __restrict__ bg,
    const float* __restrict__ Wa_mu, const float* __restrict__ ba_mu,
    const float* __restrict__ Wa_sd, const float* __restrict__ ba_sd,
    const float* __restrict__ Wz_mu, const float* __restrict__ bz_mu,
    const float* __restrict__ Wz_sd, const float* __restrict__ bz_sd,
    float* __restrict__ out)
{
    extern __shared__ float fsm[];
    float* Wt = fsm;
    float* tb = fsm + 4 * 128 * 64;
    float* yb = tb + 8 * 128;

    for (int idx = threadIdx.x; idx < 4 * I_ * H_; idx += 256) {
        int head = idx >> 13;
        int rem  = idx & 8191;
        int i    = rem >> 7;
        int k    = rem & 127;
        const float* W = head == 0 ? Wa_mu : head == 1 ? Wa_sd
                       : head == 2 ? Wz_mu : Wz_sd;
        Wt[(head << 13) + (k << 6) + i] = __ldg(W + rem);
    }
    int rw   = threadIdx.x >> 5;
    int lane = threadIdx.x & 31;
    int row  = (blockIdx.x << 3) + rw;
    {
        float dg = g_deg_in[row];
        float nd = dg > 0.f ? rsqrtf(dg) : 1.f;
        float4 v = *reinterpret_cast<const float4*>(g_agg + row * H_ + (lane << 2));
        v.x *= nd; v.y *= nd; v.z *= nd; v.w *= nd;
        *reinterpret_cast<float4*>(&tb[(rw << 7) + (lane << 2)]) = v;
    }
    __syncthreads();
    float acc[4] = {0.f, 0.f, 0.f, 0.f};
    for (int k = 0; k < 128; ++k) {
        float tv = tb[(rw << 7) + k];
        #pragma unroll
        for (int q = 0; q < 4; ++q)
            acc[q] += tv * __ldg(Wg + (k << 7) + lane + (q << 5));
    }
    #pragma unroll
    for (int q = 0; q < 4; ++q)
        yb[(rw << 7) + lane + (q << 5)] = acc[q] + __ldg(bg + lane + (q << 5));
    __syncthreads();
    float ha0[2] = {0.f, 0.f}, ha1[2] = {0.f, 0.f};
    float hz0[2] = {0.f, 0.f}, hz1[2] = {0.f, 0.f};
    for (int k = 0; k < 128; ++k) {
        float yv = yb[(rw << 7) + k];
        int base = (k << 6) + lane;
        ha0[0] += yv * Wt[0 * 8192 + base];      ha0[1] += yv * Wt[0 * 8192 + base + 32];
        ha1[0] += yv * Wt[1 * 8192 + base];      ha1[1] += yv * Wt[1 * 8192 + base + 32];
        hz0[0] += yv * Wt[2 * 8192 + base];      hz0[1] += yv * Wt[2 * 8192 + base + 32];
        hz1[0] += yv * Wt[3 * 8192 + base];      hz1[1] += yv * Wt[3 * 8192 + base + 32];
    }
    const int NI = N_ * I_;
    #pragma unroll
    for (int q = 0; q < 2; ++q) {
        int i = lane + (q << 5);
        out[2 * NI + row * I_ + i] = ha0[q] + __ldg(ba_mu + i);
        out[3 * NI + row * I_ + i] = softplusf(ha1[q] + __ldg(ba_sd + i));
        out[0      + row * I_ + i] = hz0[q] + __ldg(bz_mu + i);
        out[1 * NI + row * I_ + i] = softplusf(hz1[q] + __ldg(bz_sd + i));
    }
}

// ---------------------------------------------------------------------------
extern "C" void kernel_launch(void* const* d_in, const int* in_sizes, int n_in,
                              void* d_out, int out_size) {
    const float* actions = (const float*)d_in[0];
    const float* hidden  = (const float*)d_in[1];
    const int*   src     = (const int*)d_in[2];
    const int*   dst     = (const int*)d_in[3];
    const float* W_ih    = (const float*)d_in[4];
    const float* W_hh    = (const float*)d_in[5];
    const float* b_ih    = (const float*)d_in[6];
    const float* b_hh    = (const float*)d_in[7];
    const float* ln_g    = (const float*)d_in[8];
    const float* ln_b    = (const float*)d_in[9];
    const float* Wg      = (const float*)d_in[10];
    const float* bg      = (const float*)d_in[11];
    const float* Wa_mu   = (const float*)d_in[12];
    const float* ba_mu   = (const float*)d_in[13];
    const float* Wa_sd   = (const float*)d_in[14];
    const float* ba_sd   = (const float*)d_in[15];
    const float* Wz_mu   = (const float*)d_in[16];
    const float* bz_mu   = (const float*)d_in[17];
    const float* Wz_sd   = (const float*)d_in[18];
    const float* bz_sd   = (const float*)d_in[19];

    float* out   = (float*)d_out;
    float* h_out = out + 4 * N_ * I_;

    const int FIN_SMEM = (4 * I_ * H_ + 8 * H_ + 8 * H_) * 4;
    cudaFuncSetAttribute(gru_mma_kernel, cudaFuncAttributeMaxDynamicSharedMemorySize, GRU_SMEM);
    cudaFuncSetAttribute(final_kernel, cudaFuncAttributeMaxDynamicSharedMemorySize, FIN_SMEM);

    gru_mma_kernel<<<N_ / 16, 512, GRU_SMEM>>>(actions, hidden, W_ih, W_hh, b_ih, b_hh, h_out);
    zero_deg_kernel<<<(N_ + 255) / 256, 256>>>();
    zero_agg_kernel<<<N_ * H_ / 4 / 256, 256>>>();
    degree_kernel<<<E_ / 256, 256>>>(src, dst);
    ln_scale_kernel<<<N_ / 8, 256>>>(h_out, ln_g, ln_b);
    scatter_kernel<<<E_ * 32 / 256, 256>>>(src, dst);
    final_kernel<<<N_ / 8, 256, FIN_SMEM>>>(Wg, bg, Wa_mu, ba_mu, Wa_sd, ba_sd,
                                            Wz_mu, bz_mu, Wz_sd, bz_sd, out);
}

// round 10
// speedup vs baseline: 1.8521x; 1.0243x over previous
#include <cuda_runtime.h>
#include <cuda_bf16.h>
#include <math.h>

#define N_  50000
#define T_  25
#define A_  16
#define H_  128
#define I_  64
#define E_  800000

// Scratch (no allocations allowed): device globals.
__device__ float g_xln[N_ * H_];
__device__ float g_agg[N_ * H_];
__device__ float g_deg_out[N_];
__device__ float g_deg_in[N_];

__device__ __forceinline__ float softplusf(float x) {
    return x > 0.f ? x + log1pf(expf(-x)) : log1pf(expf(x));
}

// ===========================================================================
// GRU via mma.sync bf16 (HMMA), split-bf16 3-pass. 32 rows/block, 16 warps.
// ALL W_hh fragments (hi+lo) hoisted to registers once; A tiles then alias
// the dead W smem. x_{t+1} prefetched into regs during compute.
// smem (bytes):
//   phase 1 (staging): WHI 0..98304, WLO 98304..196608  (dead after hoist)
//   loop:  AHHI 0 (32r x 128k hi, 8192), AHLO 8192, AX 16384 (32r x 32k, 2048)
//   persistent: BX 196608..221184 (W_ih hi rows 0..15, lo rows 16..31)
// ===========================================================================
#define OFF_WHI   0
#define OFF_WLO   98304
#define OFF_BX    196608
#define OFF_AHHI  0
#define OFF_AHLO  8192
#define OFF_AX    16384
#define GRU_SMEM  221184

__device__ __forceinline__ unsigned s2u(const void* p) {
    unsigned a;
    asm("{ .reg .u64 t; cvta.to.shared.u64 t, %1; cvt.u32.u64 %0, t; }"
        : "=r"(a) : "l"(p));
    return a;
}
__device__ __forceinline__ int offW(int k, int c) {   // row stride 768B
    return k * 768 + ((((c >> 3) ^ (k & 7)) << 4) + ((c & 7) << 1));
}
__device__ __forceinline__ int offA(int r, int k) {   // row stride 256B
    return r * 256 + ((((k >> 3) ^ (r & 7)) << 4) + ((k & 7) << 1));
}
__device__ __forceinline__ int offX(int r, int k) {   // row stride 64B
    return r * 64 + ((((k >> 3) ^ (r & 3)) << 4) + ((k & 7) << 1));
}

__device__ __forceinline__ void ldmA(unsigned addr, unsigned& a0, unsigned& a1,
                                     unsigned& a2, unsigned& a3) {
    asm volatile("ldmatrix.sync.aligned.m8n8.x4.shared.b16 {%0,%1,%2,%3}, [%4];"
                 : "=r"(a0), "=r"(a1), "=r"(a2), "=r"(a3) : "r"(addr));
}
__device__ __forceinline__ void ldmB(unsigned addr, unsigned& b0, unsigned& b1) {
    asm volatile("ldmatrix.sync.aligned.m8n8.x2.trans.shared.b16 {%0,%1}, [%2];"
                 : "=r"(b0), "=r"(b1) : "r"(addr));
}
__device__ __forceinline__ void mma16816(float d[4], unsigned a0, unsigned a1,
                                         unsigned a2, unsigned a3,
                                         unsigned b0, unsigned b1) {
    asm volatile(
        "mma.sync.aligned.m16n8k16.row.col.f32.bf16.bf16.f32 "
        "{%0,%1,%2,%3},{%4,%5,%6,%7},{%8,%9},{%0,%1,%2,%3};"
        : "+f"(d[0]), "+f"(d[1]), "+f"(d[2]), "+f"(d[3])
        : "r"(a0), "r"(a1), "r"(a2), "r"(a3), "r"(b0), "r"(b1));
}

__device__ __forceinline__ unsigned short bfh(float x) {
    return __bfloat16_as_ushort(__float2bfloat16(x));
}
__device__ __forceinline__ float bfhf(float x) {
    return __bfloat162float(__float2bfloat16(x));
}

__global__ void __launch_bounds__(512, 1) gru_mma_kernel(
    const float* __restrict__ actions,  // (N, T, A)
    const float* __restrict__ hidden,   // (1, N, H)
    const float* __restrict__ W_ih,     // (3H, A)
    const float* __restrict__ W_hh,     // (3H, H)
    const float* __restrict__ b_ih,     // (3H)
    const float* __restrict__ b_hh,     // (3H)
    float* __restrict__ h_out)          // (N, H)
{
    extern __shared__ char sm[];
    const unsigned sb = s2u(sm);
    const int tid  = threadIdx.x;
    const int w    = tid >> 5;        // warp 0..15
    const int lane = tid & 31;
    const int grow0 = blockIdx.x << 5;   // 32 rows per block

    // ================= phase 1: stage W to smem =================
    for (int idx = tid; idx < 384 * 128; idx += 512) {
        int c = idx >> 7, k = idx & 127;
        float v = __ldg(W_hh + idx);
        float hf = bfhf(v);
        int o = offW(k, c);
        *(unsigned short*)(sm + OFF_WHI + o) = bfh(v);
        *(unsigned short*)(sm + OFF_WLO + o) = bfh(v - hf);
    }
    for (int idx = tid; idx < 384 * 16; idx += 512) {
        int c = idx >> 4, a = idx & 15;
        float v = __ldg(W_ih + idx);
        float hf = bfhf(v);
        int o = offW(a, c);
        *(unsigned short*)(sm + OFF_BX + o)            = bfh(v);
        *(unsigned short*)(sm + OFF_BX + o + 16 * 768) = bfh(v - hf);
    }
    __syncthreads();

    // ================= phase 2: hoist W_hh fragments to registers ==========
    const int l15 = lane & 15, l7 = lane & 7, hb = lane >> 4;
    const unsigned bRow = (unsigned)(l15 * 768);
    int ctile[3];
    #pragma unroll
    for (int g = 0; g < 3; ++g) ctile[g] = (((g << 4) + w) ^ l7) << 4;

    unsigned bhi[8][3][2], blo[8][3][2];
    #pragma unroll
    for (int ks = 0; ks < 8; ++ks) {
        unsigned kb = sb + bRow + (unsigned)(ks * 12288);
        #pragma unroll
        for (int g = 0; g < 3; ++g) {
            ldmB(kb + OFF_WHI + ctile[g], bhi[ks][g][0], bhi[ks][g][1]);
            ldmB(kb + OFF_WLO + ctile[g], blo[ks][g][0], blo[ks][g][1]);
        }
    }
    __syncthreads();   // all warps done reading W smem

    // ================= phase 3: stage A tiles over dead W region ===========
    for (int idx = tid; idx < 32 * 128; idx += 512) {
        int r = idx >> 7, k = idx & 127;
        int gr = grow0 + r; if (gr >= N_) gr = N_ - 1;
        float v = __ldg(hidden + (size_t)gr * H_ + k);
        float hf = bfhf(v);
        int o = offA(r, k);
        *(unsigned short*)(sm + OFF_AHHI + o) = bfh(v);
        *(unsigned short*)(sm + OFF_AHLO + o) = bfh(v - hf);
    }
    {   // x_0: 512 elements, one per thread
        int r = tid >> 4, a = tid & 15;
        int gr = grow0 + r; if (gr >= N_) gr = N_ - 1;
        float v = __ldg(actions + (size_t)gr * (T_ * A_) + a);
        float hf = bfhf(v);
        *(unsigned short*)(sm + OFF_AX + offX(r, a))      = bfh(v);
        *(unsigned short*)(sm + OFF_AX + offX(r, 16 + a)) = bfh(v - hf);
    }

    // ---- per-thread unit/bias setup ----
    const int tr = lane >> 2;
    const int j0 = (w << 3) + ((lane & 3) << 1);
    float br[2], bz[2], bin[2], bhn[2];
    #pragma unroll
    for (int q = 0; q < 2; ++q) {
        int j = j0 + q;
        br[q]  = __ldg(b_ih + j)       + __ldg(b_hh + j);
        bz[q]  = __ldg(b_ih + 128 + j) + __ldg(b_hh + 128 + j);
        bin[q] = __ldg(b_ih + 256 + j);
        bhn[q] = __ldg(b_hh + 256 + j);
    }
    // ---- h state in fp32 registers: hold[rt*4 + s*2 + q] ----
    float hold[8];
    #pragma unroll
    for (int rt = 0; rt < 2; ++rt)
        #pragma unroll
        for (int s = 0; s < 2; ++s)
            #pragma unroll
            for (int q = 0; q < 2; ++q) {
                int gr = grow0 + 16 * rt + tr + 8 * s;
                if (gr >= N_) gr = N_ - 1;
                hold[rt * 4 + s * 2 + q] = __ldg(hidden + (size_t)gr * H_ + j0 + q);
            }

    // x prefetch identity for this thread
    const int xr = tid >> 4, xa = tid & 15;
    int xgr = grow0 + xr; if (xgr >= N_) xgr = N_ - 1;
    const float* xsrc = actions + (size_t)xgr * (T_ * A_) + xa;

    __syncthreads();

    for (int t = 0; t < T_; ++t) {
        // prefetch x_{t+1} early (hide LDG latency behind mma)
        float xpre = 0.f;
        if (t + 1 < T_) xpre = __ldg(xsrc + (t + 1) * A_);

        float accR[2][4] = {}, accZ[2][4] = {}, accN[2][4] = {}, accNI[2][4] = {};

        // ---- h passes: 8 ksteps, W entirely in registers ----
        #pragma unroll
        for (int ks = 0; ks < 8; ++ks) {
            unsigned koff = (unsigned)((((ks << 1) + hb) ^ l7) << 4);
            #pragma unroll
            for (int rt = 0; rt < 2; ++rt) {
                unsigned abase = (unsigned)((16 * rt + l15) * 256) + koff;
                unsigned ah0, ah1, ah2, ah3, al0, al1, al2, al3;
                ldmA(sb + OFF_AHHI + abase, ah0, ah1, ah2, ah3);
                ldmA(sb + OFF_AHLO + abase, al0, al1, al2, al3);
                #pragma unroll
                for (int g = 0; g < 3; ++g) {
                    float* acc = (g == 0) ? accR[rt] : (g == 1) ? accZ[rt] : accN[rt];
                    mma16816(acc, ah0, ah1, ah2, ah3, bhi[ks][g][0], bhi[ks][g][1]);
                    mma16816(acc, al0, al1, al2, al3, bhi[ks][g][0], bhi[ks][g][1]);
                    mma16816(acc, ah0, ah1, ah2, ah3, blo[ks][g][0], blo[ks][g][1]);
                }
            }
        }
        // ---- x pass: xhi*Wxhi + xlo*Wxhi + xhi*Wxlo ----
        {
            unsigned bxh[3][2], bxl[3][2];
            unsigned kbh = sb + OFF_BX + bRow;
            unsigned kbl = kbh + 12288;
            #pragma unroll
            for (int g = 0; g < 3; ++g) {
                ldmB(kbh + ctile[g], bxh[g][0], bxh[g][1]);
                ldmB(kbl + ctile[g], bxl[g][0], bxl[g][1]);
            }
            #pragma unroll
            for (int rt = 0; rt < 2; ++rt) {
                unsigned xbase = sb + OFF_AX + (unsigned)((16 * rt + l15) * 64);
                unsigned xh0, xh1, xh2, xh3, xl0, xl1, xl2, xl3;
                ldmA(xbase + (unsigned)((hb ^ (l15 & 3)) << 4),       xh0, xh1, xh2, xh3);
                ldmA(xbase + (unsigned)(((2 + hb) ^ (l15 & 3)) << 4), xl0, xl1, xl2, xl3);
                #pragma unroll
                for (int g = 0; g < 3; ++g) {
                    float* dst = (g == 0) ? accR[rt] : (g == 1) ? accZ[rt] : accNI[rt];
                    mma16816(dst, xh0, xh1, xh2, xh3, bxh[g][0], bxh[g][1]);
                    mma16816(dst, xl0, xl1, xl2, xl3, bxh[g][0], bxh[g][1]);
                    mma16816(dst, xh0, xh1, xh2, xh3, bxl[g][0], bxl[g][1]);
                }
            }
        }

        __syncthreads();   // all smem reads of AH/AX complete

        // ---- gate math; h state in registers ----
        #pragma unroll
        for (int rt = 0; rt < 2; ++rt)
            #pragma unroll
            for (int s = 0; s < 2; ++s)
                #pragma unroll
                for (int q = 0; q < 2; ++q) {
                    int i = s * 2 + q;
                    float pr = accR[rt][i] + br[q];
                    float pz = accZ[rt][i] + bz[q];
                    float gn = accN[rt][i] + bhn[q];
                    float gi = accNI[rt][i] + bin[q];
                    float rg = 1.f / (1.f + __expf(-pr));
                    float zg = 1.f / (1.f + __expf(-pz));
                    float pre = fmaf(rg, gn, gi);
                    float e2 = __expf(2.f * pre);
                    float ng = 1.f - 2.f / (e2 + 1.f);
                    float hn = ng + zg * (hold[rt * 4 + i] - ng);
                    hold[rt * 4 + i] = hn;
                    int row = 16 * rt + tr + (s << 3);
                    int j = j0 + q;
                    if (t == T_ - 1) {
                        if (grow0 + row < N_)
                            h_out[(size_t)(grow0 + row) * H_ + j] = hn;
                    } else {
                        float hf = bfhf(hn);
                        int o = offA(row, j);
                        *(unsigned short*)(sm + OFF_AHHI + o) = bfh(hn);
                        *(unsigned short*)(sm + OFF_AHLO + o) = bfh(hn - hf);
                    }
                }

        // store prefetched x_{t+1}
        if (t + 1 < T_) {
            float hf = bfhf(xpre);
            *(unsigned short*)(sm + OFF_AX + offX(xr, xa))      = bfh(xpre);
            *(unsigned short*)(sm + OFF_AX + offX(xr, 16 + xa)) = bfh(xpre - hf);
        }
        __syncthreads();   // writes visible before next step's mma
    }
}

// ===========================================================================
// Post-GRU kernels (unchanged from passing round)
// ===========================================================================
__global__ void __launch_bounds__(256) ln_scale_kernel(
    const float* __restrict__ h, const float* __restrict__ ln_g,
    const float* __restrict__ ln_b)
{
    int row  = (blockIdx.x << 3) + (threadIdx.x >> 5);
    int lane = threadIdx.x & 31;
    float4 v = __ldg(reinterpret_cast<const float4*>(h + row * H_) + lane);
    float s  = v.x + v.y + v.z + v.w;
    float ss = v.x * v.x + v.y * v.y + v.z * v.z + v.w * v.w;
    #pragma unroll
    for (int o = 16; o > 0; o >>= 1) {
        s  += __shfl_xor_sync(0xffffffffu, s, o);
        ss += __shfl_xor_sync(0xffffffffu, ss, o);
    }
    float mu  = s * (1.f / 128.f);
    float var = ss * (1.f / 128.f) - mu * mu;
    float inv = rsqrtf(var + 1e-5f);
    float dg  = g_deg_out[row];
    float ns  = dg > 0.f ? rsqrtf(dg) : 1.f;
    float4 g4 = __ldg(reinterpret_cast<const float4*>(ln_g) + lane);
    float4 b4 = __ldg(reinterpret_cast<const float4*>(ln_b) + lane);
    float4 o4;
    o4.x = ((v.x - mu) * inv * g4.x + b4.x) * ns;
    o4.y = ((v.y - mu) * inv * g4.y + b4.y) * ns;
    o4.z = ((v.z - mu) * inv * g4.z + b4.z) * ns;
    o4.w = ((v.w - mu) * inv * g4.w + b4.w) * ns;
    *reinterpret_cast<float4*>(g_xln + row * H_ + (lane << 2)) = o4;
}

__global__ void zero_deg_kernel() {
    int i = blockIdx.x * 256 + threadIdx.x;
    if (i < N_) { g_deg_in[i] = 0.f; g_deg_out[i] = 0.f; }
}
__global__ void zero_agg_kernel() {
    int i = blockIdx.x * 256 + threadIdx.x;
    reinterpret_cast<float4*>(g_agg)[i] = make_float4(0.f, 0.f, 0.f, 0.f);
}
__global__ void degree_kernel(const int* __restrict__ src, const int* __restrict__ dst) {
    int e = blockIdx.x * 256 + threadIdx.x;
    atomicAdd(&g_deg_out[__ldg(src + e)], 1.f);
    atomicAdd(&g_deg_in[__ldg(dst + e)], 1.f);
}
__global__ void scatter_kernel(const int* __restrict__ src, const int* __restrict__ dst) {
    int gid = blockIdx.x * 256 + threadIdx.x;
    int e = gid >> 5, c = gid & 31;
    int s = __ldg(src + e), d = __ldg(dst + e);
    float4 v = *reinterpret_cast<const float4*>(g_xln + s * H_ + (c << 2));
    atomicAdd(reinterpret_cast<float4*>(g_agg + d * H_ + (c << 2)), v);
}

__global__ void __launch_bounds__(256) final_kernel(
    const float* __restrict__ Wg,    const float* __restrict__ bg,
    const float* __restrict__ Wa_mu, const float* __restrict__ ba_mu,
    const float* __restrict__ Wa_sd, const float* __restrict__ ba_sd,
    const float* __restrict__ Wz_mu, const float* __restrict__ bz_mu,
    const float* __restrict__ Wz_sd, const float* __restrict__ bz_sd,
    float* __restrict__ out)
{
    extern __shared__ float fsm[];
    float* Wt = fsm;
    float* tb = fsm + 4 * 128 * 64;
    float* yb = tb + 8 * 128;

    for (int idx = threadIdx.x; idx < 4 * I_ * H_; idx += 256) {
        int head = idx >> 13;
        int rem  = idx & 8191;
        int i    = rem >> 7;
        int k    = rem & 127;
        const float* W = head == 0 ? Wa_mu : head == 1 ? Wa_sd
                       : head == 2 ? Wz_mu : Wz_sd;
        Wt[(head << 13) + (k << 6) + i] = __ldg(W + rem);
    }
    int rw   = threadIdx.x >> 5;
    int lane = threadIdx.x & 31;
    int row  = (blockIdx.x << 3) + rw;
    {
        float dg = g_deg_in[row];
        float nd = dg > 0.f ? rsqrtf(dg) : 1.f;
        float4 v = *reinterpret_cast<const float4*>(g_agg + row * H_ + (lane << 2));
        v.x *= nd; v.y *= nd; v.z *= nd; v.w *= nd;
        *reinterpret_cast<float4*>(&tb[(rw << 7) + (lane << 2)]) = v;
    }
    __syncthreads();
    float acc[4] = {0.f, 0.f, 0.f, 0.f};
    for (int k = 0; k < 128; ++k) {
        float tv = tb[(rw << 7) + k];
        #pragma unroll
        for (int q = 0; q < 4; ++q)
            acc[q] += tv * __ldg(Wg + (k << 7) + lane + (q << 5));
    }
    #pragma unroll
    for (int q = 0; q < 4; ++q)
        yb[(rw << 7) + lane + (q << 5)] = acc[q] + __ldg(bg + lane + (q << 5));
    __syncthreads();
    float ha0[2] = {0.f, 0.f}, ha1[2] = {0.f, 0.f};
    float hz0[2] = {0.f, 0.f}, hz1[2] = {0.f, 0.f};
    for (int k = 0; k < 128; ++k) {
        float yv = yb[(rw << 7) + k];
        int base = (k << 6) + lane;
        ha0[0] += yv * Wt[0 * 8192 + base];      ha0[1] += yv * Wt[0 * 8192 + base + 32];
        ha1[0] += yv * Wt[1 * 8192 + base];      ha1[1] += yv * Wt[1 * 8192 + base + 32];
        hz0[0] += yv * Wt[2 * 8192 + base];      hz0[1] += yv * Wt[2 * 8192 + base + 32];
        hz1[0] += yv * Wt[3 * 8192 + base];      hz1[1] += yv * Wt[3 * 8192 + base + 32];
    }
    const int NI = N_ * I_;
    #pragma unroll
    for (int q = 0; q < 2; ++q) {
        int i = lane + (q << 5);
        out[2 * NI + row * I_ + i] = ha0[q] + __ldg(ba_mu + i);
        out[3 * NI + row * I_ + i] = softplusf(ha1[q] + __ldg(ba_sd + i));
        out[0      + row * I_ + i] = hz0[q] + __ldg(bz_mu + i);
        out[1 * NI + row * I_ + i] = softplusf(hz1[q] + __ldg(bz_sd + i));
    }
}

// ---------------------------------------------------------------------------
extern "C" void kernel_launch(void* const* d_in, const int* in_sizes, int n_in,
                              void* d_out, int out_size) {
    const float* actions = (const float*)d_in[0];
    const float* hidden  = (const float*)d_in[1];
    const int*   src     = (const int*)d_in[2];
    const int*   dst     = (const int*)d_in[3];
    const float* W_ih    = (const float*)d_in[4];
    const float* W_hh    = (const float*)d_in[5];
    const float* b_ih    = (const float*)d_in[6];
    const float* b_hh    = (const float*)d_in[7];
    const float* ln_g    = (const float*)d_in[8];
    const float* ln_b    = (const float*)d_in[9];
    const float* Wg      = (const float*)d_in[10];
    const float* bg      = (const float*)d_in[11];
    const float* Wa_mu   = (const float*)d_in[12];
    const float* ba_mu   = (const float*)d_in[13];
    const float* Wa_sd   = (const float*)d_in[14];
    const float* ba_sd   = (const float*)d_in[15];
    const float* Wz_mu   = (const float*)d_in[16];
    const float* bz_mu   = (const float*)d_in[17];
    const float* Wz_sd   = (const float*)d_in[18];
    const float* bz_sd   = (const float*)d_in[19];

    float* out   = (float*)d_out;
    float* h_out = out + 4 * N_ * I_;

    const int FIN_SMEM = (4 * I_ * H_ + 8 * H_ + 8 * H_) * 4;
    cudaFuncSetAttribute(gru_mma_kernel, cudaFuncAttributeMaxDynamicSharedMemorySize, GRU_SMEM);
    cudaFuncSetAttribute(final_kernel, cudaFuncAttributeMaxDynamicSharedMemorySize, FIN_SMEM);

    gru_mma_kernel<<<(N_ + 31) / 32, 512, GRU_SMEM>>>(actions, hidden, W_ih, W_hh, b_ih, b_hh, h_out);
    zero_deg_kernel<<<(N_ + 255) / 256, 256>>>();
    zero_agg_kernel<<<N_ * H_ / 4 / 256, 256>>>();
    degree_kernel<<<E_ / 256, 256>>>(src, dst);
    ln_scale_kernel<<<N_ / 8, 256>>>(h_out, ln_g, ln_b);
    scatter_kernel<<<E_ * 32 / 256, 256>>>(src, dst);
    final_kernel<<<N_ / 8, 256, FIN_SMEM>>>(Wg, bg, Wa_mu, ba_mu, Wa_sd, ba_sd,
                                            Wz_mu, bz_mu, Wz_sd, bz_sd, out);
}

// round 11
// speedup vs baseline: 2.0412x; 1.1021x over previous
#include <cuda_runtime.h>
#include <cuda_bf16.h>
#include <math.h>

#define N_  50000
#define T_  25
#define A_  16
#define H_  128
#define I_  64
#define E_  800000

// Scratch (no allocations allowed): device globals.
__device__ float g_xln[N_ * H_];
__device__ float g_agg[N_ * H_];
__device__ float g_deg_out[N_];
__device__ float g_deg_in[N_];

__device__ __forceinline__ float softplusf(float x) {
    return x > 0.f ? x + log1pf(expf(-x)) : log1pf(expf(x));
}

// ===========================================================================
// GRU via mma.sync bf16 (HMMA), split-bf16 3-pass. 32 rows/block, 16 warps.
// W_hh-hi hoisted to regs (48); W_hh-lo stays in smem (no register spills —
// 512 thr @ 1 CTA caps at 128 regs/thread). A tiles double-buffered in the
// dead W-hi staging region -> ONE barrier per step.
// smem (bytes):
//   staging: WHI 0..98304 (dead after hoist), WLO 98304..196608 (persistent),
//            BX 196608..221184 (W_ih hi rows 0..15, lo rows 16..31)
//   loop (aliases WHI region):
//     AH[p] hi: p*16384, AH[p] lo: p*16384+8192  (32r x 128k each)
//     AX[p]:   32768 + p*2048                     (32r x 32k)
// ===========================================================================
#define OFF_WHI   0
#define OFF_WLO   98304
#define OFF_BX    196608
#define GRU_SMEM  221184

__device__ __forceinline__ unsigned s2u(const void* p) {
    unsigned a;
    asm("{ .reg .u64 t; cvta.to.shared.u64 t, %1; cvt.u32.u64 %0, t; }"
        : "=r"(a) : "l"(p));
    return a;
}
__device__ __forceinline__ int offW(int k, int c) {   // row stride 768B
    return k * 768 + ((((c >> 3) ^ (k & 7)) << 4) + ((c & 7) << 1));
}
__device__ __forceinline__ int offA(int r, int k) {   // row stride 256B
    return r * 256 + ((((k >> 3) ^ (r & 7)) << 4) + ((k & 7) << 1));
}
__device__ __forceinline__ int offX(int r, int k) {   // row stride 64B
    return r * 64 + ((((k >> 3) ^ (r & 3)) << 4) + ((k & 7) << 1));
}

__device__ __forceinline__ void ldmA(unsigned addr, unsigned& a0, unsigned& a1,
                                     unsigned& a2, unsigned& a3) {
    asm volatile("ldmatrix.sync.aligned.m8n8.x4.shared.b16 {%0,%1,%2,%3}, [%4];"
                 : "=r"(a0), "=r"(a1), "=r"(a2), "=r"(a3) : "r"(addr));
}
__device__ __forceinline__ void ldmB(unsigned addr, unsigned& b0, unsigned& b1) {
    asm volatile("ldmatrix.sync.aligned.m8n8.x2.trans.shared.b16 {%0,%1}, [%2];"
                 : "=r"(b0), "=r"(b1) : "r"(addr));
}
__device__ __forceinline__ void mma16816(float d[4], unsigned a0, unsigned a1,
                                         unsigned a2, unsigned a3,
                                         unsigned b0, unsigned b1) {
    asm volatile(
        "mma.sync.aligned.m16n8k16.row.col.f32.bf16.bf16.f32 "
        "{%0,%1,%2,%3},{%4,%5,%6,%7},{%8,%9},{%0,%1,%2,%3};"
        : "+f"(d[0]), "+f"(d[1]), "+f"(d[2]), "+f"(d[3])
        : "r"(a0), "r"(a1), "r"(a2), "r"(a3), "r"(b0), "r"(b1));
}

__device__ __forceinline__ unsigned short bfh(float x) {
    return __bfloat16_as_ushort(__float2bfloat16(x));
}
__device__ __forceinline__ float bfhf(float x) {
    return __bfloat162float(__float2bfloat16(x));
}

__global__ void __launch_bounds__(512, 1) gru_mma_kernel(
    const float* __restrict__ actions,  // (N, T, A)
    const float* __restrict__ hidden,   // (1, N, H)
    const float* __restrict__ W_ih,     // (3H, A)
    const float* __restrict__ W_hh,     // (3H, H)
    const float* __restrict__ b_ih,     // (3H)
    const float* __restrict__ b_hh,     // (3H)
    float* __restrict__ h_out)          // (N, H)
{
    extern __shared__ char sm[];
    const unsigned sb = s2u(sm);
    const int tid  = threadIdx.x;
    const int w    = tid >> 5;        // warp 0..15
    const int lane = tid & 31;
    const int grow0 = blockIdx.x << 5;   // 32 rows per block

    // ================= phase 1: stage W to smem =================
    for (int idx = tid; idx < 384 * 128; idx += 512) {
        int c = idx >> 7, k = idx & 127;
        float v = __ldg(W_hh + idx);
        float hf = bfhf(v);
        int o = offW(k, c);
        *(unsigned short*)(sm + OFF_WHI + o) = bfh(v);
        *(unsigned short*)(sm + OFF_WLO + o) = bfh(v - hf);
    }
    for (int idx = tid; idx < 384 * 16; idx += 512) {
        int c = idx >> 4, a = idx & 15;
        float v = __ldg(W_ih + idx);
        float hf = bfhf(v);
        int o = offW(a, c);
        *(unsigned short*)(sm + OFF_BX + o)            = bfh(v);
        *(unsigned short*)(sm + OFF_BX + o + 16 * 768) = bfh(v - hf);
    }
    __syncthreads();

    // ================= phase 2: hoist W_hh-hi fragments to registers =======
    const int l15 = lane & 15, l7 = lane & 7, hb = lane >> 4;
    const unsigned bRow = (unsigned)(l15 * 768);
    int ctile[3];
    #pragma unroll
    for (int g = 0; g < 3; ++g) ctile[g] = (((g << 4) + w) ^ l7) << 4;

    unsigned bhi[8][3][2];
    #pragma unroll
    for (int ks = 0; ks < 8; ++ks) {
        unsigned kb = sb + OFF_WHI + bRow + (unsigned)(ks * 12288);
        #pragma unroll
        for (int g = 0; g < 3; ++g)
            ldmB(kb + ctile[g], bhi[ks][g][0], bhi[ks][g][1]);
    }
    __syncthreads();   // all warps done reading W-hi smem

    // ================= phase 3: stage A tiles (buffer 0) ===========
    for (int idx = tid; idx < 32 * 128; idx += 512) {
        int r = idx >> 7, k = idx & 127;
        int gr = grow0 + r; if (gr >= N_) gr = N_ - 1;
        float v = __ldg(hidden + (size_t)gr * H_ + k);
        float hf = bfhf(v);
        int o = offA(r, k);
        *(unsigned short*)(sm + o)        = bfh(v);       // AH[0] hi
        *(unsigned short*)(sm + 8192 + o) = bfh(v - hf);  // AH[0] lo
    }
    {   // x_0: 512 elements, one per thread -> AX[0] at 32768
        int r = tid >> 4, a = tid & 15;
        int gr = grow0 + r; if (gr >= N_) gr = N_ - 1;
        float v = __ldg(actions + (size_t)gr * (T_ * A_) + a);
        float hf = bfhf(v);
        *(unsigned short*)(sm + 32768 + offX(r, a))      = bfh(v);
        *(unsigned short*)(sm + 32768 + offX(r, 16 + a)) = bfh(v - hf);
    }

    // ---- per-thread unit/bias setup ----
    const int tr = lane >> 2;
    const int j0 = (w << 3) + ((lane & 3) << 1);
    float br[2], bz[2], bin[2], bhn[2];
    #pragma unroll
    for (int q = 0; q < 2; ++q) {
        int j = j0 + q;
        br[q]  = __ldg(b_ih + j)       + __ldg(b_hh + j);
        bz[q]  = __ldg(b_ih + 128 + j) + __ldg(b_hh + 128 + j);
        bin[q] = __ldg(b_ih + 256 + j);
        bhn[q] = __ldg(b_hh + 256 + j);
    }
    // ---- h state in fp32 registers: hold[rt*4 + s*2 + q] ----
    float hold[8];
    #pragma unroll
    for (int rt = 0; rt < 2; ++rt)
        #pragma unroll
        for (int s = 0; s < 2; ++s)
            #pragma unroll
            for (int q = 0; q < 2; ++q) {
                int gr = grow0 + 16 * rt + tr + 8 * s;
                if (gr >= N_) gr = N_ - 1;
                hold[rt * 4 + s * 2 + q] = __ldg(hidden + (size_t)gr * H_ + j0 + q);
            }

    // x prefetch identity for this thread
    const int xr = tid >> 4, xa = tid & 15;
    int xgr = grow0 + xr; if (xgr >= N_) xgr = N_ - 1;
    const float* xsrc = actions + (size_t)xgr * (T_ * A_) + xa;

    __syncthreads();

    for (int t = 0; t < T_; ++t) {
        const int p = t & 1;
        const unsigned rdAH = sb + (unsigned)(p * 16384);          // hi; +8192 lo
        const unsigned rdAX = sb + 32768u + (unsigned)(p * 2048);
        const unsigned wrAH = sb + (unsigned)((1 - p) * 16384);
        const unsigned wrAX = sb + 32768u + (unsigned)((1 - p) * 2048);

        // prefetch x_{t+1} early (hide LDG latency behind mma)
        float xpre = 0.f;
        if (t + 1 < T_) xpre = __ldg(xsrc + (t + 1) * A_);

        float accR[2][4] = {}, accZ[2][4] = {}, accN[2][4] = {}, accNI[2][4] = {};

        // ---- h passes: 8 ksteps; W-hi in regs, W-lo from smem ----
        #pragma unroll
        for (int ks = 0; ks < 8; ++ks) {
            unsigned wl[3][2];
            {
                unsigned kb = sb + OFF_WLO + bRow + (unsigned)(ks * 12288);
                #pragma unroll
                for (int g = 0; g < 3; ++g)
                    ldmB(kb + ctile[g], wl[g][0], wl[g][1]);
            }
            unsigned koff = (unsigned)((((ks << 1) + hb) ^ l7) << 4);
            #pragma unroll
            for (int rt = 0; rt < 2; ++rt) {
                unsigned abase = rdAH + (unsigned)((16 * rt + l15) * 256) + koff;
                unsigned ah0, ah1, ah2, ah3, al0, al1, al2, al3;
                ldmA(abase, ah0, ah1, ah2, ah3);
                ldmA(abase + 8192, al0, al1, al2, al3);
                #pragma unroll
                for (int g = 0; g < 3; ++g) {
                    float* acc = (g == 0) ? accR[rt] : (g == 1) ? accZ[rt] : accN[rt];
                    mma16816(acc, ah0, ah1, ah2, ah3, bhi[ks][g][0], bhi[ks][g][1]);
                    mma16816(acc, al0, al1, al2, al3, bhi[ks][g][0], bhi[ks][g][1]);
                    mma16816(acc, ah0, ah1, ah2, ah3, wl[g][0], wl[g][1]);
                }
            }
        }
        // ---- x pass: xhi*Wxhi + xlo*Wxhi + xhi*Wxlo ----
        {
            unsigned bxh[3][2], bxl[3][2];
            unsigned kbh = sb + OFF_BX + bRow;
            unsigned kbl = kbh + 12288;
            #pragma unroll
            for (int g = 0; g < 3; ++g) {
                ldmB(kbh + ctile[g], bxh[g][0], bxh[g][1]);
                ldmB(kbl + ctile[g], bxl[g][0], bxl[g][1]);
            }
            #pragma unroll
            for (int rt = 0; rt < 2; ++rt) {
                unsigned xbase = rdAX + (unsigned)((16 * rt + l15) * 64);
                unsigned xh0, xh1, xh2, xh3, xl0, xl1, xl2, xl3;
                ldmA(xbase + (unsigned)((hb ^ (l15 & 3)) << 4),       xh0, xh1, xh2, xh3);
                ldmA(xbase + (unsigned)(((2 + hb) ^ (l15 & 3)) << 4), xl0, xl1, xl2, xl3);
                #pragma unroll
                for (int g = 0; g < 3; ++g) {
                    float* dst = (g == 0) ? accR[rt] : (g == 1) ? accZ[rt] : accNI[rt];
                    mma16816(dst, xh0, xh1, xh2, xh3, bxh[g][0], bxh[g][1]);
                    mma16816(dst, xl0, xl1, xl2, xl3, bxh[g][0], bxh[g][1]);
                    mma16816(dst, xh0, xh1, xh2, xh3, bxl[g][0], bxl[g][1]);
                }
            }
        }

        // ---- gate math; writes go to the OTHER buffer (no barrier needed) ----
        #pragma unroll
        for (int rt = 0; rt < 2; ++rt)
            #pragma unroll
            for (int s = 0; s < 2; ++s) {
                float hn2[2];
                #pragma unroll
                for (int q = 0; q < 2; ++q) {
                    int i = s * 2 + q;
                    float pr = accR[rt][i] + br[q];
                    float pz = accZ[rt][i] + bz[q];
                    float gn = accN[rt][i] + bhn[q];
                    float gi = accNI[rt][i] + bin[q];
                    float rg = 1.f / (1.f + __expf(-pr));
                    float zg = 1.f / (1.f + __expf(-pz));
                    float pre = fmaf(rg, gn, gi);
                    float e2 = __expf(2.f * pre);
                    float ng = 1.f - 2.f / (e2 + 1.f);
                    float hn = ng + zg * (hold[rt * 4 + i] - ng);
                    hold[rt * 4 + i] = hn;
                    hn2[q] = hn;
                }
                int row = 16 * rt + tr + (s << 3);
                if (t == T_ - 1) {
                    if (grow0 + row < N_) {
                        h_out[(size_t)(grow0 + row) * H_ + j0]     = hn2[0];
                        h_out[(size_t)(grow0 + row) * H_ + j0 + 1] = hn2[1];
                    }
                } else {
                    int o = offA(row, j0);   // 4-byte aligned (j0 even)
                    unsigned uh = (unsigned)bfh(hn2[0]) | ((unsigned)bfh(hn2[1]) << 16);
                    unsigned ul = (unsigned)bfh(hn2[0] - bfhf(hn2[0])) |
                                  ((unsigned)bfh(hn2[1] - bfhf(hn2[1])) << 16);
                    *(unsigned*)(sm + (wrAH - sb) + o)        = uh;
                    *(unsigned*)(sm + (wrAH - sb) + 8192 + o) = ul;
                }
            }

        // store prefetched x_{t+1} into write buffer
        if (t + 1 < T_) {
            float hf = bfhf(xpre);
            *(unsigned short*)(sm + (wrAX - sb) + offX(xr, xa))      = bfh(xpre);
            *(unsigned short*)(sm + (wrAX - sb) + offX(xr, 16 + xa)) = bfh(xpre - hf);
            __syncthreads();   // single barrier per step
        }
    }
}

// ===========================================================================
// Post-GRU kernels (unchanged from passing round)
// ===========================================================================
__global__ void __launch_bounds__(256) ln_scale_kernel(
    const float* __restrict__ h, const float* __restrict__ ln_g,
    const float* __restrict__ ln_b)
{
    int row  = (blockIdx.x << 3) + (threadIdx.x >> 5);
    int lane = threadIdx.x & 31;
    float4 v = __ldg(reinterpret_cast<const float4*>(h + row * H_) + lane);
    float s  = v.x + v.y + v.z + v.w;
    float ss = v.x * v.x + v.y * v.y + v.z * v.z + v.w * v.w;
    #pragma unroll
    for (int o = 16; o > 0; o >>= 1) {
        s  += __shfl_xor_sync(0xffffffffu, s, o);
        ss += __shfl_xor_sync(0xffffffffu, ss, o);
    }
    float mu  = s * (1.f / 128.f);
    float var = ss * (1.f / 128.f) - mu * mu;
    float inv = rsqrtf(var + 1e-5f);
    float dg  = g_deg_out[row];
    float ns  = dg > 0.f ? rsqrtf(dg) : 1.f;
    float4 g4 = __ldg(reinterpret_cast<const float4*>(ln_g) + lane);
    float4 b4 = __ldg(reinterpret_cast<const float4*>(ln_b) + lane);
    float4 o4;
    o4.x = ((v.x - mu) * inv * g4.x + b4.x) * ns;
    o4.y = ((v.y - mu) * inv * g4.y + b4.y) * ns;
    o4.z = ((v.z - mu) * inv * g4.z + b4.z) * ns;
    o4.w = ((v.w - mu) * inv * g4.w + b4.w) * ns;
    *reinterpret_cast<float4*>(g_xln + row * H_ + (lane << 2)) = o4;
}

__global__ void zero_deg_kernel() {
    int i = blockIdx.x * 256 + threadIdx.x;
    if (i < N_) { g_deg_in[i] = 0.f; g_deg_out[i] = 0.f; }
}
__global__ void zero_agg_kernel() {
    int i = blockIdx.x * 256 + threadIdx.x;
    reinterpret_cast<float4*>(g_agg)[i] = make_float4(0.f, 0.f, 0.f, 0.f);
}
__global__ void degree_kernel(const int* __restrict__ src, const int* __restrict__ dst) {
    int e = blockIdx.x * 256 + threadIdx.x;
    atomicAdd(&g_deg_out[__ldg(src + e)], 1.f);
    atomicAdd(&g_deg_in[__ldg(dst + e)], 1.f);
}
__global__ void scatter_kernel(const int* __restrict__ src, const int* __restrict__ dst) {
    int gid = blockIdx.x * 256 + threadIdx.x;
    int e = gid >> 5, c = gid & 31;
    int s = __ldg(src + e), d = __ldg(dst + e);
    float4 v = *reinterpret_cast<const float4*>(g_xln + s * H_ + (c << 2));
    atomicAdd(reinterpret_cast<float4*>(g_agg + d * H_ + (c << 2)), v);
}

__global__ void __launch_bounds__(256) final_kernel(
    const float* __restrict__ Wg,    const float* __restrict__ bg,
    const float* __restrict__ Wa_mu, const float* __restrict__ ba_mu,
    const float* __restrict__ Wa_sd, const float* __restrict__ ba_sd,
    const float* __restrict__ Wz_mu, const float* __restrict__ bz_mu,
    const float* __restrict__ Wz_sd, const float* __restrict__ bz_sd,
    float* __restrict__ out)
{
    extern __shared__ float fsm[];
    float* Wt = fsm;
    float* tb = fsm + 4 * 128 * 64;
    float* yb = tb + 8 * 128;

    for (int idx = threadIdx.x; idx < 4 * I_ * H_; idx += 256) {
        int head = idx >> 13;
        int rem  = idx & 8191;
        int i    = rem >> 7;
        int k    = rem & 127;
        const float* W = head == 0 ? Wa_mu : head == 1 ? Wa_sd
                       : head == 2 ? Wz_mu : Wz_sd;
        Wt[(head << 13) + (k << 6) + i] = __ldg(W + rem);
    }
    int rw   = threadIdx.x >> 5;
    int lane = threadIdx.x & 31;
    int row  = (blockIdx.x << 3) + rw;
    {
        float dg = g_deg_in[row];
        float nd = dg > 0.f ? rsqrtf(dg) : 1.f;
        float4 v = *reinterpret_cast<const float4*>(g_agg + row * H_ + (lane << 2));
        v.x *= nd; v.y *= nd; v.z *= nd; v.w *= nd;
        *reinterpret_cast<float4*>(&tb[(rw << 7) + (lane << 2)]) = v;
    }
    __syncthreads();
    float acc[4] = {0.f, 0.f, 0.f, 0.f};
    for (int k = 0; k < 128; ++k) {
        float tv = tb[(rw << 7) + k];
        #pragma unroll
        for (int q = 0; q < 4; ++q)
            acc[q] += tv * __ldg(Wg + (k << 7) + lane + (q << 5));
    }
    #pragma unroll
    for (int q = 0; q < 4; ++q)
        yb[(rw << 7) + lane + (q << 5)] = acc[q] + __ldg(bg + lane + (q << 5));
    __syncthreads();
    float ha0[2] = {0.f, 0.f}, ha1[2] = {0.f, 0.f};
    float hz0[2] = {0.f, 0.f}, hz1[2] = {0.f, 0.f};
    for (int k = 0; k < 128; ++k) {
        float yv = yb[(rw << 7) + k];
        int base = (k << 6) + lane;
        ha0[0] += yv * Wt[0 * 8192 + base];      ha0[1] += yv * Wt[0 * 8192 + base + 32];
        ha1[0] += yv * Wt[1 * 8192 + base];      ha1[1] += yv * Wt[1 * 8192 + base + 32];
        hz0[0] += yv * Wt[2 * 8192 + base];      hz0[1] += yv * Wt[2 * 8192 + base + 32];
        hz1[0] += yv * Wt[3 * 8192 + base];      hz1[1] += yv * Wt[3 * 8192 + base + 32];
    }
    const int NI = N_ * I_;
    #pragma unroll
    for (int q = 0; q < 2; ++q) {
        int i = lane + (q << 5);
        out[2 * NI + row * I_ + i] = ha0[q] + __ldg(ba_mu + i);
        out[3 * NI + row * I_ + i] = softplusf(ha1[q] + __ldg(ba_sd + i));
        out[0      + row * I_ + i] = hz0[q] + __ldg(bz_mu + i);
        out[1 * NI + row * I_ + i] = softplusf(hz1[q] + __ldg(bz_sd + i));
    }
}

// ---------------------------------------------------------------------------
extern "C" void kernel_launch(void* const* d_in, const int* in_sizes, int n_in,
                              void* d_out, int out_size) {
    const float* actions = (const float*)d_in[0];
    const float* hidden  = (const float*)d_in[1];
    const int*   src     = (const int*)d_in[2];
    const int*   dst     = (const int*)d_in[3];
    const float* W_ih    = (const float*)d_in[4];
    const float* W_hh    = (const float*)d_in[5];
    const float* b_ih    = (const float*)d_in[6];
    const float* b_hh    = (const float*)d_in[7];
    const float* ln_g    = (const float*)d_in[8];
    const float* ln_b    = (const float*)d_in[9];
    const float* Wg      = (const float*)d_in[10];
    const float* bg      = (const float*)d_in[11];
    const float* Wa_mu   = (const float*)d_in[12];
    const float* ba_mu   = (const float*)d_in[13];
    const float* Wa_sd   = (const float*)d_in[14];
    const float* ba_sd   = (const float*)d_in[15];
    const float* Wz_mu   = (const float*)d_in[16];
    const float* bz_mu   = (const float*)d_in[17];
    const float* Wz_sd   = (const float*)d_in[18];
    const float* bz_sd   = (const float*)d_in[19];

    float* out   = (float*)d_out;
    float* h_out = out + 4 * N_ * I_;

    const int FIN_SMEM = (4 * I_ * H_ + 8 * H_ + 8 * H_) * 4;
    cudaFuncSetAttribute(gru_mma_kernel, cudaFuncAttributeMaxDynamicSharedMemorySize, GRU_SMEM);
    cudaFuncSetAttribute(final_kernel, cudaFuncAttributeMaxDynamicSharedMemorySize, FIN_SMEM);

    gru_mma_kernel<<<(N_ + 31) / 32, 512, GRU_SMEM>>>(actions, hidden, W_ih, W_hh, b_ih, b_hh, h_out);
    zero_deg_kernel<<<(N_ + 255) / 256, 256>>>();
    zero_agg_kernel<<<N_ * H_ / 4 / 256, 256>>>();
    degree_kernel<<<E_ / 256, 256>>>(src, dst);
    ln_scale_kernel<<<N_ / 8, 256>>>(h_out, ln_g, ln_b);
    scatter_kernel<<<E_ * 32 / 256, 256>>>(src, dst);
    final_kernel<<<N_ / 8, 256, FIN_SMEM>>>(Wg, bg, Wa_mu, ba_mu, Wa_sd, ba_sd,
                                            Wz_mu, bz_mu, Wz_sd, bz_sd, out);
}

// round 12
// speedup vs baseline: 2.2964x; 1.1250x over previous
#include <cuda_runtime.h>
#include <cuda_fp16.h>
#include <math.h>

#define N_  50000
#define T_  25
#define A_  16
#define H_  128
#define I_  64
#define E_  800000

// Scratch (no allocations allowed): device globals.
__device__ float g_xln[N_ * H_];
__device__ float g_agg[N_ * H_];
__device__ float g_deg_out[N_];
__device__ float g_deg_in[N_];

__device__ __forceinline__ float softplusf(float x) {
    return x > 0.f ? x + log1pf(expf(-x)) : log1pf(expf(x));
}

// ===========================================================================
// GRU via mma.sync fp16 (HMMA), 2-pass A-split: (h_hi + h_lo) @ W_fp16.
// W error 2^-11, A error ~2^-22 -> output rel_err ~3e-4 (<1e-3 gate).
// 32 rows/block, 16 warps. ALL weights live in registers after the hoist
// (W_hh 48 regs + W_ih 6 regs) -> NO ldmB in the loop. A tiles double-
// buffered -> ONE barrier per step.
// smem (bytes):
//   staging: WHI 0..98304 (W_hh fp16, dead after hoist)
//   persistent: BX 98304..110592 (W_ih fp16, 16 rows x 384 cols)
//   loop (aliases WHI): AH[p] hi p*16384, lo p*16384+8192; AX[p] 32768+p*2048
// ===========================================================================
#define OFF_WHI   0
#define OFF_BX    98304
#define GRU_SMEM  110592

__device__ __forceinline__ unsigned s2u(const void* p) {
    unsigned a;
    asm("{ .reg .u64 t; cvta.to.shared.u64 t, %1; cvt.u32.u64 %0, t; }"
        : "=r"(a) : "l"(p));
    return a;
}
__device__ __forceinline__ int offW(int k, int c) {   // row stride 768B
    return k * 768 + ((((c >> 3) ^ (k & 7)) << 4) + ((c & 7) << 1));
}
__device__ __forceinline__ int offA(int r, int k) {   // row stride 256B
    return r * 256 + ((((k >> 3) ^ (r & 7)) << 4) + ((k & 7) << 1));
}
__device__ __forceinline__ int offX(int r, int k) {   // row stride 64B
    return r * 64 + ((((k >> 3) ^ (r & 3)) << 4) + ((k & 7) << 1));
}

__device__ __forceinline__ void ldmA(unsigned addr, unsigned& a0, unsigned& a1,
                                     unsigned& a2, unsigned& a3) {
    asm volatile("ldmatrix.sync.aligned.m8n8.x4.shared.b16 {%0,%1,%2,%3}, [%4];"
                 : "=r"(a0), "=r"(a1), "=r"(a2), "=r"(a3) : "r"(addr));
}
__device__ __forceinline__ void ldmB(unsigned addr, unsigned& b0, unsigned& b1) {
    asm volatile("ldmatrix.sync.aligned.m8n8.x2.trans.shared.b16 {%0,%1}, [%2];"
                 : "=r"(b0), "=r"(b1) : "r"(addr));
}
__device__ __forceinline__ void mma16816(float d[4], unsigned a0, unsigned a1,
                                         unsigned a2, unsigned a3,
                                         unsigned b0, unsigned b1) {
    asm volatile(
        "mma.sync.aligned.m16n8k16.row.col.f32.f16.f16.f32 "
        "{%0,%1,%2,%3},{%4,%5,%6,%7},{%8,%9},{%0,%1,%2,%3};"
        : "+f"(d[0]), "+f"(d[1]), "+f"(d[2]), "+f"(d[3])
        : "r"(a0), "r"(a1), "r"(a2), "r"(a3), "r"(b0), "r"(b1));
}

__device__ __forceinline__ unsigned short fh(float x) {
    return __half_as_ushort(__float2half(x));
}
__device__ __forceinline__ float fhf(float x) {
    return __half2float(__float2half(x));
}

__global__ void __launch_bounds__(512, 1) gru_mma_kernel(
    const float* __restrict__ actions,  // (N, T, A)
    const float* __restrict__ hidden,   // (1, N, H)
    const float* __restrict__ W_ih,     // (3H, A)
    const float* __restrict__ W_hh,     // (3H, H)
    const float* __restrict__ b_ih,     // (3H)
    const float* __restrict__ b_hh,     // (3H)
    float* __restrict__ h_out)          // (N, H)
{
    extern __shared__ char sm[];
    const unsigned sb = s2u(sm);
    const int tid  = threadIdx.x;
    const int w    = tid >> 5;        // warp 0..15
    const int lane = tid & 31;
    const int grow0 = blockIdx.x << 5;   // 32 rows per block

    // ================= phase 1: stage W (fp16 single-rounded) ==============
    for (int idx = tid; idx < 384 * 128; idx += 512) {
        int c = idx >> 7, k = idx & 127;
        *(unsigned short*)(sm + OFF_WHI + offW(k, c)) = fh(__ldg(W_hh + idx));
    }
    for (int idx = tid; idx < 384 * 16; idx += 512) {
        int c = idx >> 4, a = idx & 15;
        *(unsigned short*)(sm + OFF_BX + offW(a, c)) = fh(__ldg(W_ih + idx));
    }
    __syncthreads();

    // ================= phase 2: hoist ALL weight fragments to registers ====
    const int l15 = lane & 15, l7 = lane & 7, hb = lane >> 4;
    const unsigned bRow = (unsigned)(l15 * 768);
    int ctile[3];
    #pragma unroll
    for (int g = 0; g < 3; ++g) ctile[g] = (((g << 4) + w) ^ l7) << 4;

    unsigned bhi[8][3][2];
    #pragma unroll
    for (int ks = 0; ks < 8; ++ks) {
        unsigned kb = sb + OFF_WHI + bRow + (unsigned)(ks * 12288);
        #pragma unroll
        for (int g = 0; g < 3; ++g)
            ldmB(kb + ctile[g], bhi[ks][g][0], bhi[ks][g][1]);
    }
    unsigned bx[3][2];
    {
        unsigned kb = sb + OFF_BX + bRow;
        #pragma unroll
        for (int g = 0; g < 3; ++g)
            ldmB(kb + ctile[g], bx[g][0], bx[g][1]);
    }
    __syncthreads();   // all warps done reading W smem

    // ================= phase 3: stage A tiles (buffer 0) ====================
    for (int idx = tid; idx < 32 * 128; idx += 512) {
        int r = idx >> 7, k = idx & 127;
        int gr = grow0 + r; if (gr >= N_) gr = N_ - 1;
        float v = __ldg(hidden + (size_t)gr * H_ + k);
        float hf = fhf(v);
        int o = offA(r, k);
        *(unsigned short*)(sm + o)        = fh(v);       // AH[0] hi
        *(unsigned short*)(sm + 8192 + o) = fh(v - hf);  // AH[0] lo
    }
    {   // x_0: 512 elements, one per thread -> AX[0] at 32768
        int r = tid >> 4, a = tid & 15;
        int gr = grow0 + r; if (gr >= N_) gr = N_ - 1;
        float v = __ldg(actions + (size_t)gr * (T_ * A_) + a);
        float hf = fhf(v);
        *(unsigned short*)(sm + 32768 + offX(r, a))      = fh(v);
        *(unsigned short*)(sm + 32768 + offX(r, 16 + a)) = fh(v - hf);
    }

    // ---- per-thread unit/bias setup ----
    const int tr = lane >> 2;
    const int j0 = (w << 3) + ((lane & 3) << 1);
    float br[2], bz[2], bin[2], bhn[2];
    #pragma unroll
    for (int q = 0; q < 2; ++q) {
        int j = j0 + q;
        br[q]  = __ldg(b_ih + j)       + __ldg(b_hh + j);
        bz[q]  = __ldg(b_ih + 128 + j) + __ldg(b_hh + 128 + j);
        bin[q] = __ldg(b_ih + 256 + j);
        bhn[q] = __ldg(b_hh + 256 + j);
    }
    // ---- h state in fp32 registers: hold[rt*4 + s*2 + q] ----
    float hold[8];
    #pragma unroll
    for (int rt = 0; rt < 2; ++rt)
        #pragma unroll
        for (int s = 0; s < 2; ++s)
            #pragma unroll
            for (int q = 0; q < 2; ++q) {
                int gr = grow0 + 16 * rt + tr + 8 * s;
                if (gr >= N_) gr = N_ - 1;
                hold[rt * 4 + s * 2 + q] = __ldg(hidden + (size_t)gr * H_ + j0 + q);
            }

    // x prefetch identity for this thread
    const int xr = tid >> 4, xa = tid & 15;
    int xgr = grow0 + xr; if (xgr >= N_) xgr = N_ - 1;
    const float* xsrc = actions + (size_t)xgr * (T_ * A_) + xa;

    __syncthreads();

    for (int t = 0; t < T_; ++t) {
        const int p = t & 1;
        const unsigned rdAH = sb + (unsigned)(p * 16384);          // hi; +8192 lo
        const unsigned rdAX = sb + 32768u + (unsigned)(p * 2048);
        const unsigned wrAHo = (unsigned)((1 - p) * 16384);        // offsets in sm
        const unsigned wrAXo = 32768u + (unsigned)((1 - p) * 2048);

        // prefetch x_{t+1} early (hide LDG latency behind mma)
        float xpre = 0.f;
        if (t + 1 < T_) xpre = __ldg(xsrc + (t + 1) * A_);

        float accR[2][4] = {}, accZ[2][4] = {}, accN[2][4] = {}, accNI[2][4] = {};

        // ---- h passes: 8 ksteps; 2-pass (A hi + A lo) x W-reg ----
        #pragma unroll
        for (int ks = 0; ks < 8; ++ks) {
            unsigned koff = (unsigned)((((ks << 1) + hb) ^ l7) << 4);
            #pragma unroll
            for (int rt = 0; rt < 2; ++rt) {
                unsigned abase = rdAH + (unsigned)((16 * rt + l15) * 256) + koff;
                unsigned ah0, ah1, ah2, ah3, al0, al1, al2, al3;
                ldmA(abase, ah0, ah1, ah2, ah3);
                ldmA(abase + 8192, al0, al1, al2, al3);
                #pragma unroll
                for (int g = 0; g < 3; ++g) {
                    float* acc = (g == 0) ? accR[rt] : (g == 1) ? accZ[rt] : accN[rt];
                    mma16816(acc, ah0, ah1, ah2, ah3, bhi[ks][g][0], bhi[ks][g][1]);
                    mma16816(acc, al0, al1, al2, al3, bhi[ks][g][0], bhi[ks][g][1]);
                }
            }
        }
        // ---- x pass: (x hi + x lo) x Wx-reg ----
        #pragma unroll
        for (int rt = 0; rt < 2; ++rt) {
            unsigned xbase = rdAX + (unsigned)((16 * rt + l15) * 64);
            unsigned xh0, xh1, xh2, xh3, xl0, xl1, xl2, xl3;
            ldmA(xbase + (unsigned)((hb ^ (l15 & 3)) << 4),       xh0, xh1, xh2, xh3);
            ldmA(xbase + (unsigned)(((2 + hb) ^ (l15 & 3)) << 4), xl0, xl1, xl2, xl3);
            #pragma unroll
            for (int g = 0; g < 3; ++g) {
                float* dst = (g == 0) ? accR[rt] : (g == 1) ? accZ[rt] : accNI[rt];
                mma16816(dst, xh0, xh1, xh2, xh3, bx[g][0], bx[g][1]);
                mma16816(dst, xl0, xl1, xl2, xl3, bx[g][0], bx[g][1]);
            }
        }

        // ---- gate math; writes go to the OTHER buffer (no barrier needed) ----
        #pragma unroll
        for (int rt = 0; rt < 2; ++rt)
            #pragma unroll
            for (int s = 0; s < 2; ++s) {
                float hn2[2];
                #pragma unroll
                for (int q = 0; q < 2; ++q) {
                    int i = s * 2 + q;
                    float pr = accR[rt][i] + br[q];
                    float pz = accZ[rt][i] + bz[q];
                    float gn = accN[rt][i] + bhn[q];
                    float gi = accNI[rt][i] + bin[q];
                    float rg = 1.f / (1.f + __expf(-pr));
                    float zg = 1.f / (1.f + __expf(-pz));
                    float pre = fmaf(rg, gn, gi);
                    float e2 = __expf(2.f * pre);
                    float ng = 1.f - 2.f / (e2 + 1.f);
                    float hn = ng + zg * (hold[rt * 4 + i] - ng);
                    hold[rt * 4 + i] = hn;
                    hn2[q] = hn;
                }
                int row = 16 * rt + tr + (s << 3);
                if (t == T_ - 1) {
                    if (grow0 + row < N_) {
                        h_out[(size_t)(grow0 + row) * H_ + j0]     = hn2[0];
                        h_out[(size_t)(grow0 + row) * H_ + j0 + 1] = hn2[1];
                    }
                } else {
                    int o = offA(row, j0);   // 4-byte aligned (j0 even)
                    unsigned uh = (unsigned)fh(hn2[0]) | ((unsigned)fh(hn2[1]) << 16);
                    unsigned ul = (unsigned)fh(hn2[0] - fhf(hn2[0])) |
                                  ((unsigned)fh(hn2[1] - fhf(hn2[1])) << 16);
                    *(unsigned*)(sm + wrAHo + o)        = uh;
                    *(unsigned*)(sm + wrAHo + 8192 + o) = ul;
                }
            }

        // store prefetched x_{t+1} into write buffer
        if (t + 1 < T_) {
            float hf = fhf(xpre);
            *(unsigned short*)(sm + wrAXo + offX(xr, xa))      = fh(xpre);
            *(unsigned short*)(sm + wrAXo + offX(xr, 16 + xa)) = fh(xpre - hf);
            __syncthreads();   // single barrier per step
        }
    }
}

// ===========================================================================
// Post-GRU kernels (unchanged from passing round)
// ===========================================================================
__global__ void __launch_bounds__(256) ln_scale_kernel(
    const float* __restrict__ h, const float* __restrict__ ln_g,
    const float* __restrict__ ln_b)
{
    int row  = (blockIdx.x << 3) + (threadIdx.x >> 5);
    int lane = threadIdx.x & 31;
    float4 v = __ldg(reinterpret_cast<const float4*>(h + row * H_) + lane);
    float s  = v.x + v.y + v.z + v.w;
    float ss = v.x * v.x + v.y * v.y + v.z * v.z + v.w * v.w;
    #pragma unroll
    for (int o = 16; o > 0; o >>= 1) {
        s  += __shfl_xor_sync(0xffffffffu, s, o);
        ss += __shfl_xor_sync(0xffffffffu, ss, o);
    }
    float mu  = s * (1.f / 128.f);
    float var = ss * (1.f / 128.f) - mu * mu;
    float inv = rsqrtf(var + 1e-5f);
    float dg  = g_deg_out[row];
    float ns  = dg > 0.f ? rsqrtf(dg) : 1.f;
    float4 g4 = __ldg(reinterpret_cast<const float4*>(ln_g) + lane);
    float4 b4 = __ldg(reinterpret_cast<const float4*>(ln_b) + lane);
    float4 o4;
    o4.x = ((v.x - mu) * inv * g4.x + b4.x) * ns;
    o4.y = ((v.y - mu) * inv * g4.y + b4.y) * ns;
    o4.z = ((v.z - mu) * inv * g4.z + b4.z) * ns;
    o4.w = ((v.w - mu) * inv * g4.w + b4.w) * ns;
    *reinterpret_cast<float4*>(g_xln + row * H_ + (lane << 2)) = o4;
}

__global__ void zero_deg_kernel() {
    int i = blockIdx.x * 256 + threadIdx.x;
    if (i < N_) { g_deg_in[i] = 0.f; g_deg_out[i] = 0.f; }
}
__global__ void zero_agg_kernel() {
    int i = blockIdx.x * 256 + threadIdx.x;
    reinterpret_cast<float4*>(g_agg)[i] = make_float4(0.f, 0.f, 0.f, 0.f);
}
__global__ void degree_kernel(const int* __restrict__ src, const int* __restrict__ dst) {
    int e = blockIdx.x * 256 + threadIdx.x;
    atomicAdd(&g_deg_out[__ldg(src + e)], 1.f);
    atomicAdd(&g_deg_in[__ldg(dst + e)], 1.f);
}
__global__ void scatter_kernel(const int* __restrict__ src, const int* __restrict__ dst) {
    int gid = blockIdx.x * 256 + threadIdx.x;
    int e = gid >> 5, c = gid & 31;
    int s = __ldg(src + e), d = __ldg(dst + e);
    float4 v = *reinterpret_cast<const float4*>(g_xln + s * H_ + (c << 2));
    atomicAdd(reinterpret_cast<float4*>(g_agg + d * H_ + (c << 2)), v);
}

__global__ void __launch_bounds__(256) final_kernel(
    const float* __restrict__ Wg,    const float* __restrict__ bg,
    const float* __restrict__ Wa_mu, const float* __restrict__ ba_mu,
    const float* __restrict__ Wa_sd, const float* __restrict__ ba_sd,
    const float* __restrict__ Wz_mu, const float* __restrict__ bz_mu,
    const float* __restrict__ Wz_sd, const float* __restrict__ bz_sd,
    float* __restrict__ out)
{
    extern __shared__ float fsm[];
    float* Wt = fsm;
    float* tb = fsm + 4 * 128 * 64;
    float* yb = tb + 8 * 128;

    for (int idx = threadIdx.x; idx < 4 * I_ * H_; idx += 256) {
        int head = idx >> 13;
        int rem  = idx & 8191;
        int i    = rem >> 7;
        int k    = rem & 127;
        const float* W = head == 0 ? Wa_mu : head == 1 ? Wa_sd
                       : head == 2 ? Wz_mu : Wz_sd;
        Wt[(head << 13) + (k << 6) + i] = __ldg(W + rem);
    }
    int rw   = threadIdx.x >> 5;
    int lane = threadIdx.x & 31;
    int row  = (blockIdx.x << 3) + rw;
    {
        float dg = g_deg_in[row];
        float nd = dg > 0.f ? rsqrtf(dg) : 1.f;
        float4 v = *reinterpret_cast<const float4*>(g_agg + row * H_ + (lane << 2));
        v.x *= nd; v.y *= nd; v.z *= nd; v.w *= nd;
        *reinterpret_cast<float4*>(&tb[(rw << 7) + (lane << 2)]) = v;
    }
    __syncthreads();
    float acc[4] = {0.f, 0.f, 0.f, 0.f};
    for (int k = 0; k < 128; ++k) {
        float tv = tb[(rw << 7) + k];
        #pragma unroll
        for (int q = 0; q < 4; ++q)
            acc[q] += tv * __ldg(Wg + (k << 7) + lane + (q << 5));
    }
    #pragma unroll
    for (int q = 0; q < 4; ++q)
        yb[(rw << 7) + lane + (q << 5)] = acc[q] + __ldg(bg + lane + (q << 5));
    __syncthreads();
    float ha0[2] = {0.f, 0.f}, ha1[2] = {0.f, 0.f};
    float hz0[2] = {0.f, 0.f}, hz1[2] = {0.f, 0.f};
    for (int k = 0; k < 128; ++k) {
        float yv = yb[(rw << 7) + k];
        int base = (k << 6) + lane;
        ha0[0] += yv * Wt[0 * 8192 + base];      ha0[1] += yv * Wt[0 * 8192 + base + 32];
        ha1[0] += yv * Wt[1 * 8192 + base];      ha1[1] += yv * Wt[1 * 8192 + base + 32];
        hz0[0] += yv * Wt[2 * 8192 + base];      hz0[1] += yv * Wt[2 * 8192 + base + 32];
        hz1[0] += yv * Wt[3 * 8192 + base];      hz1[1] += yv * Wt[3 * 8192 + base + 32];
    }
    const int NI = N_ * I_;
    #pragma unroll
    for (int q = 0; q < 2; ++q) {
        int i = lane + (q << 5);
        out[2 * NI + row * I_ + i] = ha0[q] + __ldg(ba_mu + i);
        out[3 * NI + row * I_ + i] = softplusf(ha1[q] + __ldg(ba_sd + i));
        out[0      + row * I_ + i] = hz0[q] + __ldg(bz_mu + i);
        out[1 * NI + row * I_ + i] = softplusf(hz1[q] + __ldg(bz_sd + i));
    }
}

// ---------------------------------------------------------------------------
extern "C" void kernel_launch(void* const* d_in, const int* in_sizes, int n_in,
                              void* d_out, int out_size) {
    const float* actions = (const float*)d_in[0];
    const float* hidden  = (const float*)d_in[1];
    const int*   src     = (const int*)d_in[2];
    const int*   dst     = (const int*)d_in[3];
    const float* W_ih    = (const float*)d_in[4];
    const float* W_hh    = (const float*)d_in[5];
    const float* b_ih    = (const float*)d_in[6];
    const float* b_hh    = (const float*)d_in[7];
    const float* ln_g    = (const float*)d_in[8];
    const float* ln_b    = (const float*)d_in[9];
    const float* Wg      = (const float*)d_in[10];
    const float* bg      = (const float*)d_in[11];
    const float* Wa_mu   = (const float*)d_in[12];
    const float* ba_mu   = (const float*)d_in[13];
    const float* Wa_sd   = (const float*)d_in[14];
    const float* ba_sd   = (const float*)d_in[15];
    const float* Wz_mu   = (const float*)d_in[16];
    const float* bz_mu   = (const float*)d_in[17];
    const float* Wz_sd   = (const float*)d_in[18];
    const float* bz_sd   = (const float*)d_in[19];

    float* out   = (float*)d_out;
    float* h_out = out + 4 * N_ * I_;

    const int FIN_SMEM = (4 * I_ * H_ + 8 * H_ + 8 * H_) * 4;
    cudaFuncSetAttribute(gru_mma_kernel, cudaFuncAttributeMaxDynamicSharedMemorySize, GRU_SMEM);
    cudaFuncSetAttribute(final_kernel, cudaFuncAttributeMaxDynamicSharedMemorySize, FIN_SMEM);

    gru_mma_kernel<<<(N_ + 31) / 32, 512, GRU_SMEM>>>(actions, hidden, W_ih, W_hh, b_ih, b_hh, h_out);
    zero_deg_kernel<<<(N_ + 255) / 256, 256>>>();
    zero_agg_kernel<<<N_ * H_ / 4 / 256, 256>>>();
    degree_kernel<<<E_ / 256, 256>>>(src, dst);
    ln_scale_kernel<<<N_ / 8, 256>>>(h_out, ln_g, ln_b);
    scatter_kernel<<<E_ * 32 / 256, 256>>>(src, dst);
    final_kernel<<<N_ / 8, 256, FIN_SMEM>>>(Wg, bg, Wa_mu, ba_mu, Wa_sd, ba_sd,
                                            Wz_mu, bz_mu, Wz_sd, bz_sd, out);
}

// round 13
// speedup vs baseline: 2.5377x; 1.1051x over previous
#include <cuda_runtime.h>
#include <cuda_fp16.h>
#include <math.h>

#define N_  50000
#define T_  25
#define A_  16
#define H_  128
#define I_  64
#define E_  800000

// Scratch (no allocations allowed): device globals.
__device__ float g_xln[N_ * H_];
__device__ float g_agg[N_ * H_];
__device__ float g_deg_out[N_];
__device__ float g_deg_in[N_];

__device__ __forceinline__ float softplusf(float x) {
    return x > 0.f ? x + log1pf(expf(-x)) : log1pf(expf(x));
}

// ===========================================================================
// GRU via mma.sync fp16 (HMMA), SINGLE-PASS: h_fp16 @ W_fp16, f32 accum.
// W error 2^-11 + A error 2^-11 -> output rel_err ~3e-4 (<1e-3 gate).
// 32 rows/block, 16 warps, 54 MMA/warp/step. All weights in registers after
// hoist (48 + 6 regs) -> NO ldmB in loop. A tiles double-buffered -> ONE
// barrier per step.
// smem (bytes):
//   staging: WHI 0..98304 (W_hh fp16, dead after hoist)
//   persistent: BX 98304..110592 (W_ih fp16, 16 rows x 384 cols)
//   loop (aliases WHI): AH[p] at p*8192 (32r x 128k); AX[p] 16384+p*2048
// ===========================================================================
#define OFF_WHI   0
#define OFF_BX    98304
#define GRU_SMEM  110592

__device__ __forceinline__ unsigned s2u(const void* p) {
    unsigned a;
    asm("{ .reg .u64 t; cvta.to.shared.u64 t, %1; cvt.u32.u64 %0, t; }"
        : "=r"(a) : "l"(p));
    return a;
}
__device__ __forceinline__ int offW(int k, int c) {   // row stride 768B
    return k * 768 + ((((c >> 3) ^ (k & 7)) << 4) + ((c & 7) << 1));
}
__device__ __forceinline__ int offA(int r, int k) {   // row stride 256B
    return r * 256 + ((((k >> 3) ^ (r & 7)) << 4) + ((k & 7) << 1));
}
__device__ __forceinline__ int offX(int r, int k) {   // row stride 64B
    return r * 64 + ((((k >> 3) ^ (r & 3)) << 4) + ((k & 7) << 1));
}

__device__ __forceinline__ void ldmA(unsigned addr, unsigned& a0, unsigned& a1,
                                     unsigned& a2, unsigned& a3) {
    asm volatile("ldmatrix.sync.aligned.m8n8.x4.shared.b16 {%0,%1,%2,%3}, [%4];"
                 : "=r"(a0), "=r"(a1), "=r"(a2), "=r"(a3) : "r"(addr));
}
__device__ __forceinline__ void ldmB(unsigned addr, unsigned& b0, unsigned& b1) {
    asm volatile("ldmatrix.sync.aligned.m8n8.x2.trans.shared.b16 {%0,%1}, [%2];"
                 : "=r"(b0), "=r"(b1) : "r"(addr));
}
__device__ __forceinline__ void mma16816(float d[4], unsigned a0, unsigned a1,
                                         unsigned a2, unsigned a3,
                                         unsigned b0, unsigned b1) {
    asm volatile(
        "mma.sync.aligned.m16n8k16.row.col.f32.f16.f16.f32 "
        "{%0,%1,%2,%3},{%4,%5,%6,%7},{%8,%9},{%0,%1,%2,%3};"
        : "+f"(d[0]), "+f"(d[1]), "+f"(d[2]), "+f"(d[3])
        : "r"(a0), "r"(a1), "r"(a2), "r"(a3), "r"(b0), "r"(b1));
}

__device__ __forceinline__ unsigned short fh(float x) {
    return __half_as_ushort(__float2half(x));
}

__global__ void __launch_bounds__(512, 1) gru_mma_kernel(
    const float* __restrict__ actions,  // (N, T, A)
    const float* __restrict__ hidden,   // (1, N, H)
    const float* __restrict__ W_ih,     // (3H, A)
    const float* __restrict__ W_hh,     // (3H, H)
    const float* __restrict__ b_ih,     // (3H)
    const float* __restrict__ b_hh,     // (3H)
    float* __restrict__ h_out)          // (N, H)
{
    extern __shared__ char sm[];
    const unsigned sb = s2u(sm);
    const int tid  = threadIdx.x;
    const int w    = tid >> 5;        // warp 0..15
    const int lane = tid & 31;
    const int grow0 = blockIdx.x << 5;   // 32 rows per block

    // ================= phase 1: stage W (fp16 single-rounded) ==============
    for (int idx = tid; idx < 384 * 128; idx += 512) {
        int c = idx >> 7, k = idx & 127;
        *(unsigned short*)(sm + OFF_WHI + offW(k, c)) = fh(__ldg(W_hh + idx));
    }
    for (int idx = tid; idx < 384 * 16; idx += 512) {
        int c = idx >> 4, a = idx & 15;
        *(unsigned short*)(sm + OFF_BX + offW(a, c)) = fh(__ldg(W_ih + idx));
    }
    __syncthreads();

    // ================= phase 2: hoist ALL weight fragments to registers ====
    const int l15 = lane & 15, l7 = lane & 7, hb = lane >> 4;
    const unsigned bRow = (unsigned)(l15 * 768);
    int ctile[3];
    #pragma unroll
    for (int g = 0; g < 3; ++g) ctile[g] = (((g << 4) + w) ^ l7) << 4;

    unsigned bhi[8][3][2];
    #pragma unroll
    for (int ks = 0; ks < 8; ++ks) {
        unsigned kb = sb + OFF_WHI + bRow + (unsigned)(ks * 12288);
        #pragma unroll
        for (int g = 0; g < 3; ++g)
            ldmB(kb + ctile[g], bhi[ks][g][0], bhi[ks][g][1]);
    }
    unsigned bx[3][2];
    {
        unsigned kb = sb + OFF_BX + bRow;
        #pragma unroll
        for (int g = 0; g < 3; ++g)
            ldmB(kb + ctile[g], bx[g][0], bx[g][1]);
    }
    __syncthreads();   // all warps done reading W smem

    // ================= phase 3: stage A tiles (buffer 0) ====================
    for (int idx = tid; idx < 32 * 128; idx += 512) {
        int r = idx >> 7, k = idx & 127;
        int gr = grow0 + r; if (gr >= N_) gr = N_ - 1;
        float v = __ldg(hidden + (size_t)gr * H_ + k);
        *(unsigned short*)(sm + offA(r, k)) = fh(v);     // AH[0]
    }
    {   // x_0: 512 elements, one per thread -> AX[0] at 16384
        int r = tid >> 4, a = tid & 15;
        int gr = grow0 + r; if (gr >= N_) gr = N_ - 1;
        float v = __ldg(actions + (size_t)gr * (T_ * A_) + a);
        *(unsigned short*)(sm + 16384 + offX(r, a)) = fh(v);
    }

    // ---- per-thread unit/bias setup ----
    const int tr = lane >> 2;
    const int j0 = (w << 3) + ((lane & 3) << 1);
    float br[2], bz[2], bin[2], bhn[2];
    #pragma unroll
    for (int q = 0; q < 2; ++q) {
        int j = j0 + q;
        br[q]  = __ldg(b_ih + j)       + __ldg(b_hh + j);
        bz[q]  = __ldg(b_ih + 128 + j) + __ldg(b_hh + 128 + j);
        bin[q] = __ldg(b_ih + 256 + j);
        bhn[q] = __ldg(b_hh + 256 + j);
    }
    // ---- h state in fp32 registers: hold[rt*4 + s*2 + q] ----
    float hold[8];
    #pragma unroll
    for (int rt = 0; rt < 2; ++rt)
        #pragma unroll
        for (int s = 0; s < 2; ++s)
            #pragma unroll
            for (int q = 0; q < 2; ++q) {
                int gr = grow0 + 16 * rt + tr + 8 * s;
                if (gr >= N_) gr = N_ - 1;
                hold[rt * 4 + s * 2 + q] = __ldg(hidden + (size_t)gr * H_ + j0 + q);
            }

    // x prefetch identity for this thread
    const int xr = tid >> 4, xa = tid & 15;
    int xgr = grow0 + xr; if (xgr >= N_) xgr = N_ - 1;
    const float* xsrc = actions + (size_t)xgr * (T_ * A_) + xa;

    __syncthreads();

    for (int t = 0; t < T_; ++t) {
        const int p = t & 1;
        const unsigned rdAH = sb + (unsigned)(p * 8192);
        const unsigned rdAX = sb + 16384u + (unsigned)(p * 2048);
        const unsigned wrAHo = (unsigned)((1 - p) * 8192);        // offsets in sm
        const unsigned wrAXo = 16384u + (unsigned)((1 - p) * 2048);

        // prefetch x_{t+1} early (hide LDG latency behind mma)
        float xpre = 0.f;
        if (t + 1 < T_) xpre = __ldg(xsrc + (t + 1) * A_);

        float accR[2][4] = {}, accZ[2][4] = {}, accN[2][4] = {}, accNI[2][4] = {};

        // ---- h pass: 8 ksteps, single-pass fp16 ----
        #pragma unroll
        for (int ks = 0; ks < 8; ++ks) {
            unsigned koff = (unsigned)((((ks << 1) + hb) ^ l7) << 4);
            #pragma unroll
            for (int rt = 0; rt < 2; ++rt) {
                unsigned abase = rdAH + (unsigned)((16 * rt + l15) * 256) + koff;
                unsigned ah0, ah1, ah2, ah3;
                ldmA(abase, ah0, ah1, ah2, ah3);
                #pragma unroll
                for (int g = 0; g < 3; ++g) {
                    float* acc = (g == 0) ? accR[rt] : (g == 1) ? accZ[rt] : accN[rt];
                    mma16816(acc, ah0, ah1, ah2, ah3, bhi[ks][g][0], bhi[ks][g][1]);
                }
            }
        }
        // ---- x pass: single-pass fp16 ----
        #pragma unroll
        for (int rt = 0; rt < 2; ++rt) {
            unsigned xbase = rdAX + (unsigned)((16 * rt + l15) * 64);
            unsigned xh0, xh1, xh2, xh3;
            ldmA(xbase + (unsigned)((hb ^ (l15 & 3)) << 4), xh0, xh1, xh2, xh3);
            #pragma unroll
            for (int g = 0; g < 3; ++g) {
                float* dst = (g == 0) ? accR[rt] : (g == 1) ? accZ[rt] : accNI[rt];
                mma16816(dst, xh0, xh1, xh2, xh3, bx[g][0], bx[g][1]);
            }
        }

        // ---- gate math; writes go to the OTHER buffer (no barrier needed) ----
        #pragma unroll
        for (int rt = 0; rt < 2; ++rt)
            #pragma unroll
            for (int s = 0; s < 2; ++s) {
                float hn2[2];
                #pragma unroll
                for (int q = 0; q < 2; ++q) {
                    int i = s * 2 + q;
                    float pr = accR[rt][i] + br[q];
                    float pz = accZ[rt][i] + bz[q];
                    float gn = accN[rt][i] + bhn[q];
                    float gi = accNI[rt][i] + bin[q];
                    float rg = 1.f / (1.f + __expf(-pr));
                    float zg = 1.f / (1.f + __expf(-pz));
                    float pre = fmaf(rg, gn, gi);
                    float e2 = __expf(2.f * pre);
                    float ng = 1.f - 2.f / (e2 + 1.f);
                    float hn = ng + zg * (hold[rt * 4 + i] - ng);
                    hold[rt * 4 + i] = hn;
                    hn2[q] = hn;
                }
                int row = 16 * rt + tr + (s << 3);
                if (t == T_ - 1) {
                    if (grow0 + row < N_) {
                        h_out[(size_t)(grow0 + row) * H_ + j0]     = hn2[0];
                        h_out[(size_t)(grow0 + row) * H_ + j0 + 1] = hn2[1];
                    }
                } else {
                    int o = offA(row, j0);   // 4-byte aligned (j0 even)
                    unsigned uh = (unsigned)fh(hn2[0]) | ((unsigned)fh(hn2[1]) << 16);
                    *(unsigned*)(sm + wrAHo + o) = uh;
                }
            }

        // store prefetched x_{t+1} into write buffer
        if (t + 1 < T_) {
            *(unsigned short*)(sm + wrAXo + offX(xr, xa)) = fh(xpre);
            __syncthreads();   // single barrier per step
        }
    }
}

// ===========================================================================
// Post-GRU kernels (unchanged from passing round)
// ===========================================================================
__global__ void __launch_bounds__(256) ln_scale_kernel(
    const float* __restrict__ h, const float* __restrict__ ln_g,
    const float* __restrict__ ln_b)
{
    int row  = (blockIdx.x << 3) + (threadIdx.x >> 5);
    int lane = threadIdx.x & 31;
    float4 v = __ldg(reinterpret_cast<const float4*>(h + row * H_) + lane);
    float s  = v.x + v.y + v.z + v.w;
    float ss = v.x * v.x + v.y * v.y + v.z * v.z + v.w * v.w;
    #pragma unroll
    for (int o = 16; o > 0; o >>= 1) {
        s  += __shfl_xor_sync(0xffffffffu, s, o);
        ss += __shfl_xor_sync(0xffffffffu, ss, o);
    }
    float mu  = s * (1.f / 128.f);
    float var = ss * (1.f / 128.f) - mu * mu;
    float inv = rsqrtf(var + 1e-5f);
    float dg  = g_deg_out[row];
    float ns  = dg > 0.f ? rsqrtf(dg) : 1.f;
    float4 g4 = __ldg(reinterpret_cast<const float4*>(ln_g) + lane);
    float4 b4 = __ldg(reinterpret_cast<const float4*>(ln_b) + lane);
    float4 o4;
    o4.x = ((v.x - mu) * inv * g4.x + b4.x) * ns;
    o4.y = ((v.y - mu) * inv * g4.y + b4.y) * ns;
    o4.z = ((v.z - mu) * inv * g4.z + b4.z) * ns;
    o4.w = ((v.w - mu) * inv * g4.w + b4.w) * ns;
    *reinterpret_cast<float4*>(g_xln + row * H_ + (lane << 2)) = o4;
}

__global__ void zero_deg_kernel() {
    int i = blockIdx.x * 256 + threadIdx.x;
    if (i < N_) { g_deg_in[i] = 0.f; g_deg_out[i] = 0.f; }
}
__global__ void zero_agg_kernel() {
    int i = blockIdx.x * 256 + threadIdx.x;
    reinterpret_cast<float4*>(g_agg)[i] = make_float4(0.f, 0.f, 0.f, 0.f);
}
__global__ void degree_kernel(const int* __restrict__ src, const int* __restrict__ dst) {
    int e = blockIdx.x * 256 + threadIdx.x;
    atomicAdd(&g_deg_out[__ldg(src + e)], 1.f);
    atomicAdd(&g_deg_in[__ldg(dst + e)], 1.f);
}
__global__ void scatter_kernel(const int* __restrict__ src, const int* __restrict__ dst) {
    int gid = blockIdx.x * 256 + threadIdx.x;
    int e = gid >> 5, c = gid & 31;
    int s = __ldg(src + e), d = __ldg(dst + e);
    float4 v = *reinterpret_cast<const float4*>(g_xln + s * H_ + (c << 2));
    atomicAdd(reinterpret_cast<float4*>(g_agg + d * H_ + (c << 2)), v);
}

__global__ void __launch_bounds__(256) final_kernel(
    const float* __restrict__ Wg,    const float* __restrict__ bg,
    const float* __restrict__ Wa_mu, const float* __restrict__ ba_mu,
    const float* __restrict__ Wa_sd, const float* __restrict__ ba_sd,
    const float* __restrict__ Wz_mu, const float* __restrict__ bz_mu,
    const float* __restrict__ Wz_sd, const float* __restrict__ bz_sd,
    float* __restrict__ out)
{
    extern __shared__ float fsm[];
    float* Wt = fsm;
    float* tb = fsm + 4 * 128 * 64;
    float* yb = tb + 8 * 128;

    for (int idx = threadIdx.x; idx < 4 * I_ * H_; idx += 256) {
        int head = idx >> 13;
        int rem  = idx & 8191;
        int i    = rem >> 7;
        int k    = rem & 127;
        const float* W = head == 0 ? Wa_mu : head == 1 ? Wa_sd
                       : head == 2 ? Wz_mu : Wz_sd;
        Wt[(head << 13) + (k << 6) + i] = __ldg(W + rem);
    }
    int rw   = threadIdx.x >> 5;
    int lane = threadIdx.x & 31;
    int row  = (blockIdx.x << 3) + rw;
    {
        float dg = g_deg_in[row];
        float nd = dg > 0.f ? rsqrtf(dg) : 1.f;
        float4 v = *reinterpret_cast<const float4*>(g_agg + row * H_ + (lane << 2));
        v.x *= nd; v.y *= nd; v.z *= nd; v.w *= nd;
        *reinterpret_cast<float4*>(&tb[(rw << 7) + (lane << 2)]) = v;
    }
    __syncthreads();
    float acc[4] = {0.f, 0.f, 0.f, 0.f};
    for (int k = 0; k < 128; ++k) {
        float tv = tb[(rw << 7) + k];
        #pragma unroll
        for (int q = 0; q < 4; ++q)
            acc[q] += tv * __ldg(Wg + (k << 7) + lane + (q << 5));
    }
    #pragma unroll
    for (int q = 0; q < 4; ++q)
        yb[(rw << 7) + lane + (q << 5)] = acc[q] + __ldg(bg + lane + (q << 5));
    __syncthreads();
    float ha0[2] = {0.f, 0.f}, ha1[2] = {0.f, 0.f};
    float hz0[2] = {0.f, 0.f}, hz1[2] = {0.f, 0.f};
    for (int k = 0; k < 128; ++k) {
        float yv = yb[(rw << 7) + k];
        int base = (k << 6) + lane;
        ha0[0] += yv * Wt[0 * 8192 + base];      ha0[1] += yv * Wt[0 * 8192 + base + 32];
        ha1[0] += yv * Wt[1 * 8192 + base];      ha1[1] += yv * Wt[1 * 8192 + base + 32];
        hz0[0] += yv * Wt[2 * 8192 + base];      hz0[1] += yv * Wt[2 * 8192 + base + 32];
        hz1[0] += yv * Wt[3 * 8192 + base];      hz1[1] += yv * Wt[3 * 8192 + base + 32];
    }
    const int NI = N_ * I_;
    #pragma unroll
    for (int q = 0; q < 2; ++q) {
        int i = lane + (q << 5);
        out[2 * NI + row * I_ + i] = ha0[q] + __ldg(ba_mu + i);
        out[3 * NI + row * I_ + i] = softplusf(ha1[q] + __ldg(ba_sd + i));
        out[0      + row * I_ + i] = hz0[q] + __ldg(bz_mu + i);
        out[1 * NI + row * I_ + i] = softplusf(hz1[q] + __ldg(bz_sd + i));
    }
}

// ---------------------------------------------------------------------------
extern "C" void kernel_launch(void* const* d_in, const int* in_sizes, int n_in,
                              void* d_out, int out_size) {
    const float* actions = (const float*)d_in[0];
    const float* hidden  = (const float*)d_in[1];
    const int*   src     = (const int*)d_in[2];
    const int*   dst     = (const int*)d_in[3];
    const float* W_ih    = (const float*)d_in[4];
    const float* W_hh    = (const float*)d_in[5];
    const float* b_ih    = (const float*)d_in[6];
    const float* b_hh    = (const float*)d_in[7];
    const float* ln_g    = (const float*)d_in[8];
    const float* ln_b    = (const float*)d_in[9];
    const float* Wg      = (const float*)d_in[10];
    const float* bg      = (const float*)d_in[11];
    const float* Wa_mu   = (const float*)d_in[12];
    const float* ba_mu   = (const float*)d_in[13];
    const float* Wa_sd   = (const float*)d_in[14];
    const float* ba_sd   = (const float*)d_in[15];
    const float* Wz_mu   = (const float*)d_in[16];
    const float* bz_mu   = (const float*)d_in[17];
    const float* Wz_sd   = (const float*)d_in[18];
    const float* bz_sd   = (const float*)d_in[19];

    float* out   = (float*)d_out;
    float* h_out = out + 4 * N_ * I_;

    const int FIN_SMEM = (4 * I_ * H_ + 8 * H_ + 8 * H_) * 4;
    cudaFuncSetAttribute(gru_mma_kernel, cudaFuncAttributeMaxDynamicSharedMemorySize, GRU_SMEM);
    cudaFuncSetAttribute(final_kernel, cudaFuncAttributeMaxDynamicSharedMemorySize, FIN_SMEM);

    gru_mma_kernel<<<(N_ + 31) / 32, 512, GRU_SMEM>>>(actions, hidden, W_ih, W_hh, b_ih, b_hh, h_out);
    zero_deg_kernel<<<(N_ + 255) / 256, 256>>>();
    zero_agg_kernel<<<N_ * H_ / 4 / 256, 256>>>();
    degree_kernel<<<E_ / 256, 256>>>(src, dst);
    ln_scale_kernel<<<N_ / 8, 256>>>(h_out, ln_g, ln_b);
    scatter_kernel<<<E_ * 32 / 256, 256>>>(src, dst);
    final_kernel<<<N_ / 8, 256, FIN_SMEM>>>(Wg, bg, Wa_mu, ba_mu, Wa_sd, ba_sd,
                                            Wz_mu, bz_mu, Wz_sd, bz_sd, out);
}

// round 14
// speedup vs baseline: 3.0223x; 1.1910x over previous
#include <cuda_runtime.h>
#include <cuda_fp16.h>
#include <math.h>

#define N_  50000
#define T_  25
#define A_  16
#define H_  128
#define I_  64
#define E_  800000

// Scratch (no allocations allowed): device globals.
__device__ float g_xln[N_ * H_];
__device__ float g_agg[N_ * H_];
__device__ float g_deg_out[N_];
__device__ float g_deg_in[N_];

__device__ __forceinline__ float softplusf(float x) {
    return x > 0.f ? x + log1pf(expf(-x)) : log1pf(expf(x));
}

// ===========================================================================
// GRU via mma.sync fp16 (HMMA), single-pass, 2 CTAs/SM for 8 warps/SMSP.
// 32 rows/CTA, 16 warps. W_hh read from smem per step (ldmB); W_ih hoisted
// (6 regs). tanh.approx.f32 epilogue (24 MUFU/thread/step).
// smem (110592 B/CTA -> 2 CTAs fit the 228KB carveout):
//   WHH 0..98304       (fp16, k-major swizzled, persistent)
//   BX  98304..110592  (W_ih staging; after bx hoist, aliased by A tiles:)
//   AH  98304..106496  (32r x 128k fp16, single buffer)
//   AX  106496..108544 (32r x 16k fp16)
// ===========================================================================
#define OFF_WHH   0
#define OFF_BX    98304
#define OFF_AH    98304
#define OFF_AX    106496
#define GRU_SMEM  110592

__device__ __forceinline__ unsigned s2u(const void* p) {
    unsigned a;
    asm("{ .reg .u64 t; cvta.to.shared.u64 t, %1; cvt.u32.u64 %0, t; }"
        : "=r"(a) : "l"(p));
    return a;
}
__device__ __forceinline__ int offW(int k, int c) {   // row stride 768B
    return k * 768 + ((((c >> 3) ^ (k & 7)) << 4) + ((c & 7) << 1));
}
__device__ __forceinline__ int offA(int r, int k) {   // row stride 256B
    return r * 256 + ((((k >> 3) ^ (r & 7)) << 4) + ((k & 7) << 1));
}
__device__ __forceinline__ int offX(int r, int k) {   // row stride 64B
    return r * 64 + ((((k >> 3) ^ (r & 3)) << 4) + ((k & 7) << 1));
}

__device__ __forceinline__ void ldmA(unsigned addr, unsigned& a0, unsigned& a1,
                                     unsigned& a2, unsigned& a3) {
    asm volatile("ldmatrix.sync.aligned.m8n8.x4.shared.b16 {%0,%1,%2,%3}, [%4];"
                 : "=r"(a0), "=r"(a1), "=r"(a2), "=r"(a3) : "r"(addr));
}
__device__ __forceinline__ void ldmB(unsigned addr, unsigned& b0, unsigned& b1) {
    asm volatile("ldmatrix.sync.aligned.m8n8.x2.trans.shared.b16 {%0,%1}, [%2];"
                 : "=r"(b0), "=r"(b1) : "r"(addr));
}
__device__ __forceinline__ void mma16816(float d[4], unsigned a0, unsigned a1,
                                         unsigned a2, unsigned a3,
                                         unsigned b0, unsigned b1) {
    asm volatile(
        "mma.sync.aligned.m16n8k16.row.col.f32.f16.f16.f32 "
        "{%0,%1,%2,%3},{%4,%5,%6,%7},{%8,%9},{%0,%1,%2,%3};"
        : "+f"(d[0]), "+f"(d[1]), "+f"(d[2]), "+f"(d[3])
        : "r"(a0), "r"(a1), "r"(a2), "r"(a3), "r"(b0), "r"(b1));
}

__device__ __forceinline__ unsigned short fh(float x) {
    return __half_as_ushort(__float2half(x));
}
__device__ __forceinline__ float tanha(float x) {
    float y;
    asm("tanh.approx.f32 %0, %1;" : "=f"(y) : "f"(x));
    return y;
}

__global__ void __launch_bounds__(512, 2) gru_mma_kernel(
    const float* __restrict__ actions,  // (N, T, A)
    const float* __restrict__ hidden,   // (1, N, H)
    const float* __restrict__ W_ih,     // (3H, A)
    const float* __restrict__ W_hh,     // (3H, H)
    const float* __restrict__ b_ih,     // (3H)
    const float* __restrict__ b_hh,     // (3H)
    float* __restrict__ h_out)          // (N, H)
{
    extern __shared__ char sm[];
    const unsigned sb = s2u(sm);
    const int tid  = threadIdx.x;
    const int w    = tid >> 5;        // warp 0..15
    const int lane = tid & 31;
    const int grow0 = blockIdx.x << 5;   // 32 rows per block

    // ================= phase 1: stage W (fp16 single-rounded) ==============
    for (int idx = tid; idx < 384 * 128; idx += 512) {
        int c = idx >> 7, k = idx & 127;
        *(unsigned short*)(sm + OFF_WHH + offW(k, c)) = fh(__ldg(W_hh + idx));
    }
    for (int idx = tid; idx < 384 * 16; idx += 512) {
        int c = idx >> 4, a = idx & 15;
        *(unsigned short*)(sm + OFF_BX + offW(a, c)) = fh(__ldg(W_ih + idx));
    }
    __syncthreads();

    // ================= phase 2: hoist W_ih fragments only (6 regs) =========
    const int l15 = lane & 15, l7 = lane & 7, hb = lane >> 4;
    const unsigned bRow = (unsigned)(l15 * 768);
    int ctile[3];
    #pragma unroll
    for (int g = 0; g < 3; ++g) ctile[g] = (((g << 4) + w) ^ l7) << 4;

    unsigned bx[3][2];
    {
        unsigned kb = sb + OFF_BX + bRow;
        #pragma unroll
        for (int g = 0; g < 3; ++g)
            ldmB(kb + ctile[g], bx[g][0], bx[g][1]);
    }
    __syncthreads();   // all warps done reading BX staging

    // ================= phase 3: stage A tiles (alias BX region) ============
    for (int idx = tid; idx < 32 * 128; idx += 512) {
        int r = idx >> 7, k = idx & 127;
        int gr = grow0 + r; if (gr >= N_) gr = N_ - 1;
        float v = __ldg(hidden + (size_t)gr * H_ + k);
        *(unsigned short*)(sm + OFF_AH + offA(r, k)) = fh(v);
    }
    {   // x_0: 512 elements, one per thread
        int r = tid >> 4, a = tid & 15;
        int gr = grow0 + r; if (gr >= N_) gr = N_ - 1;
        float v = __ldg(actions + (size_t)gr * (T_ * A_) + a);
        *(unsigned short*)(sm + OFF_AX + offX(r, a)) = fh(v);
    }

    // ---- per-thread unit/bias setup ----
    const int tr = lane >> 2;
    const int j0 = (w << 3) + ((lane & 3) << 1);
    float br[2], bz[2], bin[2], bhn[2];
    #pragma unroll
    for (int q = 0; q < 2; ++q) {
        int j = j0 + q;
        br[q]  = __ldg(b_ih + j)       + __ldg(b_hh + j);
        bz[q]  = __ldg(b_ih + 128 + j) + __ldg(b_hh + 128 + j);
        bin[q] = __ldg(b_ih + 256 + j);
        bhn[q] = __ldg(b_hh + 256 + j);
    }
    // ---- h state in fp32 registers: hold[rt*4 + s*2 + q] ----
    float hold[8];
    #pragma unroll
    for (int rt = 0; rt < 2; ++rt)
        #pragma unroll
        for (int s = 0; s < 2; ++s)
            #pragma unroll
            for (int q = 0; q < 2; ++q) {
                int gr = grow0 + 16 * rt + tr + 8 * s;
                if (gr >= N_) gr = N_ - 1;
                hold[rt * 4 + s * 2 + q] = __ldg(hidden + (size_t)gr * H_ + j0 + q);
            }

    // x prefetch identity for this thread
    const int xr = tid >> 4, xa = tid & 15;
    int xgr = grow0 + xr; if (xgr >= N_) xgr = N_ - 1;
    const float* xsrc = actions + (size_t)xgr * (T_ * A_) + xa;

    __syncthreads();

    for (int t = 0; t < T_; ++t) {
        // prefetch x_{t+1} early (hide LDG latency behind mma)
        float xpre = 0.f;
        if (t + 1 < T_) xpre = __ldg(xsrc + (t + 1) * A_);

        float accR[2][4] = {}, accZ[2][4] = {}, accN[2][4] = {}, accNI[2][4] = {};

        // ---- h pass: 8 ksteps; W from smem (ldmB), A from smem (ldmA) ----
        #pragma unroll
        for (int ks = 0; ks < 8; ++ks) {
            unsigned wl[3][2];
            {
                unsigned kb = sb + OFF_WHH + bRow + (unsigned)(ks * 12288);
                #pragma unroll
                for (int g = 0; g < 3; ++g)
                    ldmB(kb + ctile[g], wl[g][0], wl[g][1]);
            }
            unsigned koff = (unsigned)((((ks << 1) + hb) ^ l7) << 4);
            #pragma unroll
            for (int rt = 0; rt < 2; ++rt) {
                unsigned abase = sb + OFF_AH + (unsigned)((16 * rt + l15) * 256) + koff;
                unsigned ah0, ah1, ah2, ah3;
                ldmA(abase, ah0, ah1, ah2, ah3);
                #pragma unroll
                for (int g = 0; g < 3; ++g) {
                    float* acc = (g == 0) ? accR[rt] : (g == 1) ? accZ[rt] : accN[rt];
                    mma16816(acc, ah0, ah1, ah2, ah3, wl[g][0], wl[g][1]);
                }
            }
        }
        // ---- x pass: weights in regs ----
        #pragma unroll
        for (int rt = 0; rt < 2; ++rt) {
            unsigned xbase = sb + OFF_AX + (unsigned)((16 * rt + l15) * 64);
            unsigned xh0, xh1, xh2, xh3;
            ldmA(xbase + (unsigned)((hb ^ (l15 & 3)) << 4), xh0, xh1, xh2, xh3);
            #pragma unroll
            for (int g = 0; g < 3; ++g) {
                float* dst = (g == 0) ? accR[rt] : (g == 1) ? accZ[rt] : accNI[rt];
                mma16816(dst, xh0, xh1, xh2, xh3, bx[g][0], bx[g][1]);
            }
        }

        __syncthreads();   // all smem reads of AH/AX complete

        // ---- gate math (tanh.approx); h state in registers ----
        #pragma unroll
        for (int rt = 0; rt < 2; ++rt)
            #pragma unroll
            for (int s = 0; s < 2; ++s) {
                float hn2[2];
                #pragma unroll
                for (int q = 0; q < 2; ++q) {
                    int i = s * 2 + q;
                    float pr = accR[rt][i] + br[q];
                    float pz = accZ[rt][i] + bz[q];
                    float gn = accN[rt][i] + bhn[q];
                    float gi = accNI[rt][i] + bin[q];
                    float rg = fmaf(0.5f, tanha(0.5f * pr), 0.5f);
                    float zg = fmaf(0.5f, tanha(0.5f * pz), 0.5f);
                    float pre = fmaf(rg, gn, gi);
                    float ng = tanha(pre);
                    float hn = fmaf(zg, hold[rt * 4 + i] - ng, ng);
                    hold[rt * 4 + i] = hn;
                    hn2[q] = hn;
                }
                int row = 16 * rt + tr + (s << 3);
                if (t == T_ - 1) {
                    if (grow0 + row < N_) {
                        h_out[(size_t)(grow0 + row) * H_ + j0]     = hn2[0];
                        h_out[(size_t)(grow0 + row) * H_ + j0 + 1] = hn2[1];
                    }
                } else {
                    int o = offA(row, j0);   // 4-byte aligned (j0 even)
                    unsigned uh = (unsigned)fh(hn2[0]) | ((unsigned)fh(hn2[1]) << 16);
                    *(unsigned*)(sm + OFF_AH + o) = uh;
                }
            }

        // store prefetched x_{t+1}
        if (t + 1 < T_) {
            *(unsigned short*)(sm + OFF_AX + offX(xr, xa)) = fh(xpre);
            __syncthreads();   // writes visible before next step's mma
        }
    }
}

// ===========================================================================
// Post-GRU kernels (unchanged from passing round)
// ===========================================================================
__global__ void __launch_bounds__(256) ln_scale_kernel(
    const float* __restrict__ h, const float* __restrict__ ln_g,
    const float* __restrict__ ln_b)
{
    int row  = (blockIdx.x << 3) + (threadIdx.x >> 5);
    int lane = threadIdx.x & 31;
    float4 v = __ldg(reinterpret_cast<const float4*>(h + row * H_) + lane);
    float s  = v.x + v.y + v.z + v.w;
    float ss = v.x * v.x + v.y * v.y + v.z * v.z + v.w * v.w;
    #pragma unroll
    for (int o = 16; o > 0; o >>= 1) {
        s  += __shfl_xor_sync(0xffffffffu, s, o);
        ss += __shfl_xor_sync(0xffffffffu, ss, o);
    }
    float mu  = s * (1.f / 128.f);
    float var = ss * (1.f / 128.f) - mu * mu;
    float inv = rsqrtf(var + 1e-5f);
    float dg  = g_deg_out[row];
    float ns  = dg > 0.f ? rsqrtf(dg) : 1.f;
    float4 g4 = __ldg(reinterpret_cast<const float4*>(ln_g) + lane);
    float4 b4 = __ldg(reinterpret_cast<const float4*>(ln_b) + lane);
    float4 o4;
    o4.x = ((v.x - mu) * inv * g4.x + b4.x) * ns;
    o4.y = ((v.y - mu) * inv * g4.y + b4.y) * ns;
    o4.z = ((v.z - mu) * inv * g4.z + b4.z) * ns;
    o4.w = ((v.w - mu) * inv * g4.w + b4.w) * ns;
    *reinterpret_cast<float4*>(g_xln + row * H_ + (lane << 2)) = o4;
}

__global__ void zero_deg_kernel() {
    int i = blockIdx.x * 256 + threadIdx.x;
    if (i < N_) { g_deg_in[i] = 0.f; g_deg_out[i] = 0.f; }
}
__global__ void zero_agg_kernel() {
    int i = blockIdx.x * 256 + threadIdx.x;
    reinterpret_cast<float4*>(g_agg)[i] = make_float4(0.f, 0.f, 0.f, 0.f);
}
__global__ void degree_kernel(const int* __restrict__ src, const int* __restrict__ dst) {
    int e = blockIdx.x * 256 + threadIdx.x;
    atomicAdd(&g_deg_out[__ldg(src + e)], 1.f);
    atomicAdd(&g_deg_in[__ldg(dst + e)], 1.f);
}
__global__ void scatter_kernel(const int* __restrict__ src, const int* __restrict__ dst) {
    int gid = blockIdx.x * 256 + threadIdx.x;
    int e = gid >> 5, c = gid & 31;
    int s = __ldg(src + e), d = __ldg(dst + e);
    float4 v = *reinterpret_cast<const float4*>(g_xln + s * H_ + (c << 2));
    atomicAdd(reinterpret_cast<float4*>(g_agg + d * H_ + (c << 2)), v);
}

__global__ void __launch_bounds__(256) final_kernel(
    const float* __restrict__ Wg,    const float* __restrict__ bg,
    const float* __restrict__ Wa_mu, const float* __restrict__ ba_mu,
    const float* __restrict__ Wa_sd, const float* __restrict__ ba_sd,
    const float* __restrict__ Wz_mu, const float* __restrict__ bz_mu,
    const float* __restrict__ Wz_sd, const float* __restrict__ bz_sd,
    float* __restrict__ out)
{
    extern __shared__ float fsm[];
    float* Wt = fsm;
    float* tb = fsm + 4 * 128 * 64;
    float* yb = tb + 8 * 128;

    for (int idx = threadIdx.x; idx < 4 * I_ * H_; idx += 256) {
        int head = idx >> 13;
        int rem  = idx & 8191;
        int i    = rem >> 7;
        int k    = rem & 127;
        const float* W = head == 0 ? Wa_mu : head == 1 ? Wa_sd
                       : head == 2 ? Wz_mu : Wz_sd;
        Wt[(head << 13) + (k << 6) + i] = __ldg(W + rem);
    }
    int rw   = threadIdx.x >> 5;
    int lane = threadIdx.x & 31;
    int row  = (blockIdx.x << 3) + rw;
    {
        float dg = g_deg_in[row];
        float nd = dg > 0.f ? rsqrtf(dg) : 1.f;
        float4 v = *reinterpret_cast<const float4*>(g_agg + row * H_ + (lane << 2));
        v.x *= nd; v.y *= nd; v.z *= nd; v.w *= nd;
        *reinterpret_cast<float4*>(&tb[(rw << 7) + (lane << 2)]) = v;
    }
    __syncthreads();
    float acc[4] = {0.f, 0.f, 0.f, 0.f};
    for (int k = 0; k < 128; ++k) {
        float tv = tb[(rw << 7) + k];
        #pragma unroll
        for (int q = 0; q < 4; ++q)
            acc[q] += tv * __ldg(Wg + (k << 7) + lane + (q << 5));
    }
    #pragma unroll
    for (int q = 0; q < 4; ++q)
        yb[(rw << 7) + lane + (q << 5)] = acc[q] + __ldg(bg + lane + (q << 5));
    __syncthreads();
    float ha0[2] = {0.f, 0.f}, ha1[2] = {0.f, 0.f};
    float hz0[2] = {0.f, 0.f}, hz1[2] = {0.f, 0.f};
    for (int k = 0; k < 128; ++k) {
        float yv = yb[(rw << 7) + k];
        int base = (k << 6) + lane;
        ha0[0] += yv * Wt[0 * 8192 + base];      ha0[1] += yv * Wt[0 * 8192 + base + 32];
        ha1[0] += yv * Wt[1 * 8192 + base];      ha1[1] += yv * Wt[1 * 8192 + base + 32];
        hz0[0] += yv * Wt[2 * 8192 + base];      hz0[1] += yv * Wt[2 * 8192 + base + 32];
        hz1[0] += yv * Wt[3 * 8192 + base];      hz1[1] += yv * Wt[3 * 8192 + base + 32];
    }
    const int NI = N_ * I_;
    #pragma unroll
    for (int q = 0; q < 2; ++q) {
        int i = lane + (q << 5);
        out[2 * NI + row * I_ + i] = ha0[q] + __ldg(ba_mu + i);
        out[3 * NI + row * I_ + i] = softplusf(ha1[q] + __ldg(ba_sd + i));
        out[0      + row * I_ + i] = hz0[q] + __ldg(bz_mu + i);
        out[1 * NI + row * I_ + i] = softplusf(hz1[q] + __ldg(bz_sd + i));
    }
}

// ---------------------------------------------------------------------------
extern "C" void kernel_launch(void* const* d_in, const int* in_sizes, int n_in,
                              void* d_out, int out_size) {
    const float* actions = (const float*)d_in[0];
    const float* hidden  = (const float*)d_in[1];
    const int*   src     = (const int*)d_in[2];
    const int*   dst     = (const int*)d_in[3];
    const float* W_ih    = (const float*)d_in[4];
    const float* W_hh    = (const float*)d_in[5];
    const float* b_ih    = (const float*)d_in[6];
    const float* b_hh    = (const float*)d_in[7];
    const float* ln_g    = (const float*)d_in[8];
    const float* ln_b    = (const float*)d_in[9];
    const float* Wg      = (const float*)d_in[10];
    const float* bg      = (const float*)d_in[11];
    const float* Wa_mu   = (const float*)d_in[12];
    const float* ba_mu   = (const float*)d_in[13];
    const float* Wa_sd   = (const float*)d_in[14];
    const float* ba_sd   = (const float*)d_in[15];
    const float* Wz_mu   = (const float*)d_in[16];
    const float* bz_mu   = (const float*)d_in[17];
    const float* Wz_sd   = (const float*)d_in[18];
    const float* bz_sd   = (const float*)d_in[19];

    float* out   = (float*)d_out;
    float* h_out = out + 4 * N_ * I_;

    const int FIN_SMEM = (4 * I_ * H_ + 8 * H_ + 8 * H_) * 4;
    cudaFuncSetAttribute(gru_mma_kernel, cudaFuncAttributeMaxDynamicSharedMemorySize, GRU_SMEM);
    cudaFuncSetAttribute(final_kernel, cudaFuncAttributeMaxDynamicSharedMemorySize, FIN_SMEM);

    gru_mma_kernel<<<(N_ + 31) / 32, 512, GRU_SMEM>>>(actions, hidden, W_ih, W_hh, b_ih, b_hh, h_out);
    zero_deg_kernel<<<(N_ + 255) / 256, 256>>>();
    zero_agg_kernel<<<N_ * H_ / 4 / 256, 256>>>();
    degree_kernel<<<E_ / 256, 256>>>(src, dst);
    ln_scale_kernel<<<N_ / 8, 256>>>(h_out, ln_g, ln_b);
    scatter_kernel<<<E_ * 32 / 256, 256>>>(src, dst);
    final_kernel<<<N_ / 8, 256, FIN_SMEM>>>(Wg, bg, Wa_mu, ba_mu, Wa_sd, ba_sd,
                                            Wz_mu, bz_mu, Wz_sd, bz_sd, out);
}

// round 15
// speedup vs baseline: 6.0725x; 2.0092x over previous
#include <cuda_runtime.h>
#include <cuda_fp16.h>
#include <math.h>

#define N_  50000
#define T_  25
#define A_  16
#define H_  128
#define I_  64
#define E_  800000

// Scratch (no allocations allowed): device globals.
__device__ float g_xln[N_ * H_];
__device__ float g_agg[N_ * H_];
__device__ float g_deg_out[N_];
__device__ float g_deg_in[N_];

__device__ __forceinline__ float softplusf(float x) {
    return x > 0.f ? x + log1pf(expf(-x)) : log1pf(expf(x));
}

// ===========================================================================
// GRU via mma.sync fp16 (HMMA), single-pass, 2 CTAs/SM (unchanged from R14).
// ===========================================================================
#define OFF_WHH   0
#define OFF_BX    98304
#define OFF_AH    98304
#define OFF_AX    106496
#define GRU_SMEM  110592

__device__ __forceinline__ unsigned s2u(const void* p) {
    unsigned a;
    asm("{ .reg .u64 t; cvta.to.shared.u64 t, %1; cvt.u32.u64 %0, t; }"
        : "=r"(a) : "l"(p));
    return a;
}
__device__ __forceinline__ int offW(int k, int c) {   // row stride 768B
    return k * 768 + ((((c >> 3) ^ (k & 7)) << 4) + ((c & 7) << 1));
}
__device__ __forceinline__ int offA(int r, int k) {   // row stride 256B
    return r * 256 + ((((k >> 3) ^ (r & 7)) << 4) + ((k & 7) << 1));
}
__device__ __forceinline__ int offX(int r, int k) {   // row stride 64B
    return r * 64 + ((((k >> 3) ^ (r & 3)) << 4) + ((k & 7) << 1));
}

__device__ __forceinline__ void ldmA(unsigned addr, unsigned& a0, unsigned& a1,
                                     unsigned& a2, unsigned& a3) {
    asm volatile("ldmatrix.sync.aligned.m8n8.x4.shared.b16 {%0,%1,%2,%3}, [%4];"
                 : "=r"(a0), "=r"(a1), "=r"(a2), "=r"(a3) : "r"(addr));
}
__device__ __forceinline__ void ldmB(unsigned addr, unsigned& b0, unsigned& b1) {
    asm volatile("ldmatrix.sync.aligned.m8n8.x2.trans.shared.b16 {%0,%1}, [%2];"
                 : "=r"(b0), "=r"(b1) : "r"(addr));
}
__device__ __forceinline__ void mma16816(float d[4], unsigned a0, unsigned a1,
                                         unsigned a2, unsigned a3,
                                         unsigned b0, unsigned b1) {
    asm volatile(
        "mma.sync.aligned.m16n8k16.row.col.f32.f16.f16.f32 "
        "{%0,%1,%2,%3},{%4,%5,%6,%7},{%8,%9},{%0,%1,%2,%3};"
        : "+f"(d[0]), "+f"(d[1]), "+f"(d[2]), "+f"(d[3])
        : "r"(a0), "r"(a1), "r"(a2), "r"(a3), "r"(b0), "r"(b1));
}

__device__ __forceinline__ unsigned short fh(float x) {
    return __half_as_ushort(__float2half(x));
}
__device__ __forceinline__ float tanha(float x) {
    float y;
    asm("tanh.approx.f32 %0, %1;" : "=f"(y) : "f"(x));
    return y;
}

__global__ void __launch_bounds__(512, 2) gru_mma_kernel(
    const float* __restrict__ actions,  // (N, T, A)
    const float* __restrict__ hidden,   // (1, N, H)
    const float* __restrict__ W_ih,     // (3H, A)
    const float* __restrict__ W_hh,     // (3H, H)
    const float* __restrict__ b_ih,     // (3H)
    const float* __restrict__ b_hh,     // (3H)
    float* __restrict__ h_out)          // (N, H)
{
    extern __shared__ char sm[];
    const unsigned sb = s2u(sm);
    const int tid  = threadIdx.x;
    const int w    = tid >> 5;        // warp 0..15
    const int lane = tid & 31;
    const int grow0 = blockIdx.x << 5;   // 32 rows per block

    // ================= phase 1: stage W (fp16 single-rounded) ==============
    for (int idx = tid; idx < 384 * 128; idx += 512) {
        int c = idx >> 7, k = idx & 127;
        *(unsigned short*)(sm + OFF_WHH + offW(k, c)) = fh(__ldg(W_hh + idx));
    }
    for (int idx = tid; idx < 384 * 16; idx += 512) {
        int c = idx >> 4, a = idx & 15;
        *(unsigned short*)(sm + OFF_BX + offW(a, c)) = fh(__ldg(W_ih + idx));
    }
    __syncthreads();

    // ================= phase 2: hoist W_ih fragments only (6 regs) =========
    const int l15 = lane & 15, l7 = lane & 7, hb = lane >> 4;
    const unsigned bRow = (unsigned)(l15 * 768);
    int ctile[3];
    #pragma unroll
    for (int g = 0; g < 3; ++g) ctile[g] = (((g << 4) + w) ^ l7) << 4;

    unsigned bx[3][2];
    {
        unsigned kb = sb + OFF_BX + bRow;
        #pragma unroll
        for (int g = 0; g < 3; ++g)
            ldmB(kb + ctile[g], bx[g][0], bx[g][1]);
    }
    __syncthreads();   // all warps done reading BX staging

    // ================= phase 3: stage A tiles (alias BX region) ============
    for (int idx = tid; idx < 32 * 128; idx += 512) {
        int r = idx >> 7, k = idx & 127;
        int gr = grow0 + r; if (gr >= N_) gr = N_ - 1;
        float v = __ldg(hidden + (size_t)gr * H_ + k);
        *(unsigned short*)(sm + OFF_AH + offA(r, k)) = fh(v);
    }
    {   // x_0: 512 elements, one per thread
        int r = tid >> 4, a = tid & 15;
        int gr = grow0 + r; if (gr >= N_) gr = N_ - 1;
        float v = __ldg(actions + (size_t)gr * (T_ * A_) + a);
        *(unsigned short*)(sm + OFF_AX + offX(r, a)) = fh(v);
    }

    // ---- per-thread unit/bias setup ----
    const int tr = lane >> 2;
    const int j0 = (w << 3) + ((lane & 3) << 1);
    float br[2], bz[2], bin[2], bhn[2];
    #pragma unroll
    for (int q = 0; q < 2; ++q) {
        int j = j0 + q;
        br[q]  = __ldg(b_ih + j)       + __ldg(b_hh + j);
        bz[q]  = __ldg(b_ih + 128 + j) + __ldg(b_hh + 128 + j);
        bin[q] = __ldg(b_ih + 256 + j);
        bhn[q] = __ldg(b_hh + 256 + j);
    }
    // ---- h state in fp32 registers: hold[rt*4 + s*2 + q] ----
    float hold[8];
    #pragma unroll
    for (int rt = 0; rt < 2; ++rt)
        #pragma unroll
        for (int s = 0; s < 2; ++s)
            #pragma unroll
            for (int q = 0; q < 2; ++q) {
                int gr = grow0 + 16 * rt + tr + 8 * s;
                if (gr >= N_) gr = N_ - 1;
                hold[rt * 4 + s * 2 + q] = __ldg(hidden + (size_t)gr * H_ + j0 + q);
            }

    // x prefetch identity for this thread
    const int xr = tid >> 4, xa = tid & 15;
    int xgr = grow0 + xr; if (xgr >= N_) xgr = N_ - 1;
    const float* xsrc = actions + (size_t)xgr * (T_ * A_) + xa;

    __syncthreads();

    for (int t = 0; t < T_; ++t) {
        // prefetch x_{t+1} early (hide LDG latency behind mma)
        float xpre = 0.f;
        if (t + 1 < T_) xpre = __ldg(xsrc + (t + 1) * A_);

        float accR[2][4] = {}, accZ[2][4] = {}, accN[2][4] = {}, accNI[2][4] = {};

        // ---- h pass: 8 ksteps; W from smem (ldmB), A from smem (ldmA) ----
        #pragma unroll
        for (int ks = 0; ks < 8; ++ks) {
            unsigned wl[3][2];
            {
                unsigned kb = sb + OFF_WHH + bRow + (unsigned)(ks * 12288);
                #pragma unroll
                for (int g = 0; g < 3; ++g)
                    ldmB(kb + ctile[g], wl[g][0], wl[g][1]);
            }
            unsigned koff = (unsigned)((((ks << 1) + hb) ^ l7) << 4);
            #pragma unroll
            for (int rt = 0; rt < 2; ++rt) {
                unsigned abase = sb + OFF_AH + (unsigned)((16 * rt + l15) * 256) + koff;
                unsigned ah0, ah1, ah2, ah3;
                ldmA(abase, ah0, ah1, ah2, ah3);
                #pragma unroll
                for (int g = 0; g < 3; ++g) {
                    float* acc = (g == 0) ? accR[rt] : (g == 1) ? accZ[rt] : accN[rt];
                    mma16816(acc, ah0, ah1, ah2, ah3, wl[g][0], wl[g][1]);
                }
            }
        }
        // ---- x pass: weights in regs ----
        #pragma unroll
        for (int rt = 0; rt < 2; ++rt) {
            unsigned xbase = sb + OFF_AX + (unsigned)((16 * rt + l15) * 64);
            unsigned xh0, xh1, xh2, xh3;
            ldmA(xbase + (unsigned)((hb ^ (l15 & 3)) << 4), xh0, xh1, xh2, xh3);
            #pragma unroll
            for (int g = 0; g < 3; ++g) {
                float* dst = (g == 0) ? accR[rt] : (g == 1) ? accZ[rt] : accNI[rt];
                mma16816(dst, xh0, xh1, xh2, xh3, bx[g][0], bx[g][1]);
            }
        }

        __syncthreads();   // all smem reads of AH/AX complete

        // ---- gate math (tanh.approx); h state in registers ----
        #pragma unroll
        for (int rt = 0; rt < 2; ++rt)
            #pragma unroll
            for (int s = 0; s < 2; ++s) {
                float hn2[2];
                #pragma unroll
                for (int q = 0; q < 2; ++q) {
                    int i = s * 2 + q;
                    float pr = accR[rt][i] + br[q];
                    float pz = accZ[rt][i] + bz[q];
                    float gn = accN[rt][i] + bhn[q];
                    float gi = accNI[rt][i] + bin[q];
                    float rg = fmaf(0.5f, tanha(0.5f * pr), 0.5f);
                    float zg = fmaf(0.5f, tanha(0.5f * pz), 0.5f);
                    float pre = fmaf(rg, gn, gi);
                    float ng = tanha(pre);
                    float hn = fmaf(zg, hold[rt * 4 + i] - ng, ng);
                    hold[rt * 4 + i] = hn;
                    hn2[q] = hn;
                }
                int row = 16 * rt + tr + (s << 3);
                if (t == T_ - 1) {
                    if (grow0 + row < N_) {
                        h_out[(size_t)(grow0 + row) * H_ + j0]     = hn2[0];
                        h_out[(size_t)(grow0 + row) * H_ + j0 + 1] = hn2[1];
                    }
                } else {
                    int o = offA(row, j0);   // 4-byte aligned (j0 even)
                    unsigned uh = (unsigned)fh(hn2[0]) | ((unsigned)fh(hn2[1]) << 16);
                    *(unsigned*)(sm + OFF_AH + o) = uh;
                }
            }

        // store prefetched x_{t+1}
        if (t + 1 < T_) {
            *(unsigned short*)(sm + OFF_AX + offX(xr, xa)) = fh(xpre);
            __syncthreads();   // writes visible before next step's mma
        }
    }
}

// ===========================================================================
// Small graph kernels (unchanged)
// ===========================================================================
__global__ void __launch_bounds__(256) ln_scale_kernel(
    const float* __restrict__ h, const float* __restrict__ ln_g,
    const float* __restrict__ ln_b)
{
    int row  = (blockIdx.x << 3) + (threadIdx.x >> 5);
    int lane = threadIdx.x & 31;
    float4 v = __ldg(reinterpret_cast<const float4*>(h + row * H_) + lane);
    float s  = v.x + v.y + v.z + v.w;
    float ss = v.x * v.x + v.y * v.y + v.z * v.z + v.w * v.w;
    #pragma unroll
    for (int o = 16; o > 0; o >>= 1) {
        s  += __shfl_xor_sync(0xffffffffu, s, o);
        ss += __shfl_xor_sync(0xffffffffu, ss, o);
    }
    float mu  = s * (1.f / 128.f);
    float var = ss * (1.f / 128.f) - mu * mu;
    float inv = rsqrtf(var + 1e-5f);
    float dg  = g_deg_out[row];
    float ns  = dg > 0.f ? rsqrtf(dg) : 1.f;
    float4 g4 = __ldg(reinterpret_cast<const float4*>(ln_g) + lane);
    float4 b4 = __ldg(reinterpret_cast<const float4*>(ln_b) + lane);
    float4 o4;
    o4.x = ((v.x - mu) * inv * g4.x + b4.x) * ns;
    o4.y = ((v.y - mu) * inv * g4.y + b4.y) * ns;
    o4.z = ((v.z - mu) * inv * g4.z + b4.z) * ns;
    o4.w = ((v.w - mu) * inv * g4.w + b4.w) * ns;
    *reinterpret_cast<float4*>(g_xln + row * H_ + (lane << 2)) = o4;
}

__global__ void zero_deg_kernel() {
    int i = blockIdx.x * 256 + threadIdx.x;
    if (i < N_) { g_deg_in[i] = 0.f; g_deg_out[i] = 0.f; }
}
__global__ void zero_agg_kernel() {
    int i = blockIdx.x * 256 + threadIdx.x;
    reinterpret_cast<float4*>(g_agg)[i] = make_float4(0.f, 0.f, 0.f, 0.f);
}
__global__ void degree_kernel(const int* __restrict__ src, const int* __restrict__ dst) {
    int e = blockIdx.x * 256 + threadIdx.x;
    atomicAdd(&g_deg_out[__ldg(src + e)], 1.f);
    atomicAdd(&g_deg_in[__ldg(dst + e)], 1.f);
}
__global__ void scatter_kernel(const int* __restrict__ src, const int* __restrict__ dst) {
    int gid = blockIdx.x * 256 + threadIdx.x;
    int e = gid >> 5, c = gid & 31;
    int s = __ldg(src + e), d = __ldg(dst + e);
    float4 v = *reinterpret_cast<const float4*>(g_xln + s * H_ + (c << 2));
    atomicAdd(reinterpret_cast<float4*>(g_agg + d * H_ + (c << 2)), v);
}

// ===========================================================================
// Persistent fused GraphConv + heads. Grid 148, 512 thr (warp-per-row, 16-row
// tiles, 3125 tiles). Weights staged ONCE per block, packed for LDS.128:
//   Wg4[k][j]  = {Wg[k][j], [k][j+32], [k][j+64], [k][j+96]}       (64 KB)
//   Wt4[k][i]  = {Wa_mu, Wa_sd, Wz_mu, Wz_sd}[i][k]                (128 KB)
//   tb/yb [16][128] f32                                            (16 KB)
// No block barriers in the tile loop (tiles are warp-local).
// ===========================================================================
#define FIN_SMEM ((128 * 32 + 128 * 64) * 16 + 2 * 16 * 128 * 4)   // 212992

__global__ void __launch_bounds__(512, 1) final_kernel(
    const float* __restrict__ Wg,    const float* __restrict__ bg,
    const float* __restrict__ Wa_mu, const float* __restrict__ ba_mu,
    const float* __restrict__ Wa_sd, const float* __restrict__ ba_sd,
    const float* __restrict__ Wz_mu, const float* __restrict__ bz_mu,
    const float* __restrict__ Wz_sd, const float* __restrict__ bz_sd,
    float* __restrict__ out)
{
    extern __shared__ float fsm[];
    float4* Wg4 = reinterpret_cast<float4*>(fsm);            // [128][32]
    float4* Wt4 = Wg4 + 128 * 32;                            // [128][64]
    float*  tb  = reinterpret_cast<float*>(Wt4 + 128 * 64);  // [16][128]
    float*  yb  = tb + 16 * 128;                             // [16][128]

    const int tid  = threadIdx.x;
    const int rw   = tid >> 5;
    const int lane = tid & 31;

    // ---- stage Wg4: [k][j] ----
    for (int idx = tid; idx < 128 * 32; idx += 512) {
        int k = idx >> 5, j = idx & 31;
        Wg4[(k << 5) + j] = make_float4(
            __ldg(Wg + (k << 7) + j),      __ldg(Wg + (k << 7) + j + 32),
            __ldg(Wg + (k << 7) + j + 64), __ldg(Wg + (k << 7) + j + 96));
    }
    // ---- stage Wt4: [k][i] = 4 heads at (i,k) ----
    for (int idx = tid; idx < 128 * 64; idx += 512) {
        int k = idx >> 6, i = idx & 63;
        int o = (i << 7) + k;
        Wt4[(k << 6) + i] = make_float4(__ldg(Wa_mu + o), __ldg(Wa_sd + o),
                                        __ldg(Wz_mu + o), __ldg(Wz_sd + o));
    }
    __syncthreads();

    // ---- per-thread constants (bias for units lane, lane+32) ----
    float bgq[4];
    #pragma unroll
    for (int q = 0; q < 4; ++q) bgq[q] = __ldg(bg + lane + (q << 5));
    float bam[2], bas[2], bzm[2], bzs[2];
    #pragma unroll
    for (int q = 0; q < 2; ++q) {
        int i = lane + (q << 5);
        bam[q] = __ldg(ba_mu + i);  bas[q] = __ldg(ba_sd + i);
        bzm[q] = __ldg(bz_mu + i);  bzs[q] = __ldg(bz_sd + i);
    }

    const int NI = N_ * I_;
    float* tbr = tb + (rw << 7);
    float* ybr = yb + (rw << 7);

    for (int tile = blockIdx.x; tile < N_ / 16; tile += 148) {
        int row = (tile << 4) + rw;

        // phase 1: t = agg * dst-norm (warp-local)
        {
            float dg = g_deg_in[row];
            float nd = dg > 0.f ? rsqrtf(dg) : 1.f;
            float4 v = *reinterpret_cast<const float4*>(g_agg + (size_t)row * H_ + (lane << 2));
            v.x *= nd; v.y *= nd; v.z *= nd; v.w *= nd;
            *reinterpret_cast<float4*>(tbr + (lane << 2)) = v;
        }
        __syncwarp();

        // phase 2: y = t @ Wg + bg
        float acc[4] = {0.f, 0.f, 0.f, 0.f};
        #pragma unroll 4
        for (int k = 0; k < 128; ++k) {
            float tv = tbr[k];
            float4 wg = Wg4[(k << 5) + lane];
            acc[0] = fmaf(tv, wg.x, acc[0]);
            acc[1] = fmaf(tv, wg.y, acc[1]);
            acc[2] = fmaf(tv, wg.z, acc[2]);
            acc[3] = fmaf(tv, wg.w, acc[3]);
        }
        #pragma unroll
        for (int q = 0; q < 4; ++q)
            ybr[lane + (q << 5)] = acc[q] + bgq[q];
        __syncwarp();

        // phase 3: 4 heads
        float am[2] = {0.f, 0.f}, as[2] = {0.f, 0.f};
        float zm[2] = {0.f, 0.f}, zs[2] = {0.f, 0.f};
        #pragma unroll 4
        for (int k = 0; k < 128; ++k) {
            float yv = ybr[k];
            float4 w0 = Wt4[(k << 6) + lane];
            float4 w1 = Wt4[(k << 6) + lane + 32];
            am[0] = fmaf(yv, w0.x, am[0]);  am[1] = fmaf(yv, w1.x, am[1]);
            as[0] = fmaf(yv, w0.y, as[0]);  as[1] = fmaf(yv, w1.y, as[1]);
            zm[0] = fmaf(yv, w0.z, zm[0]);  zm[1] = fmaf(yv, w1.z, zm[1]);
            zs[0] = fmaf(yv, w0.w, zs[0]);  zs[1] = fmaf(yv, w1.w, zs[1]);
        }
        #pragma unroll
        for (int q = 0; q < 2; ++q) {
            int i = lane + (q << 5);
            out[2 * NI + (size_t)row * I_ + i] = am[q] + bam[q];
            out[3 * NI + (size_t)row * I_ + i] = softplusf(as[q] + bas[q]);
            out[0      + (size_t)row * I_ + i] = zm[q] + bzm[q];
            out[1 * NI + (size_t)row * I_ + i] = softplusf(zs[q] + bzs[q]);
        }
        __syncwarp();   // yb/tb reuse safe (warp-local)
    }
}

// ---------------------------------------------------------------------------
extern "C" void kernel_launch(void* const* d_in, const int* in_sizes, int n_in,
                              void* d_out, int out_size) {
    const float* actions = (const float*)d_in[0];
    const float* hidden  = (const float*)d_in[1];
    const int*   src     = (const int*)d_in[2];
    const int*   dst     = (const int*)d_in[3];
    const float* W_ih    = (const float*)d_in[4];
    const float* W_hh    = (const float*)d_in[5];
    const float* b_ih    = (const float*)d_in[6];
    const float* b_hh    = (const float*)d_in[7];
    const float* ln_g    = (const float*)d_in[8];
    const float* ln_b    = (const float*)d_in[9];
    const float* Wg      = (const float*)d_in[10];
    const float* bg      = (const float*)d_in[11];
    const float* Wa_mu   = (const float*)d_in[12];
    const float* ba_mu   = (const float*)d_in[13];
    const float* Wa_sd   = (const float*)d_in[14];
    const float* ba_sd   = (const float*)d_in[15];
    const float* Wz_mu   = (const float*)d_in[16];
    const float* bz_mu   = (const float*)d_in[17];
    const float* Wz_sd   = (const float*)d_in[18];
    const float* bz_sd   = (const float*)d_in[19];

    float* out   = (float*)d_out;
    float* h_out = out + 4 * N_ * I_;

    cudaFuncSetAttribute(gru_mma_kernel, cudaFuncAttributeMaxDynamicSharedMemorySize, GRU_SMEM);
    cudaFuncSetAttribute(final_kernel, cudaFuncAttributeMaxDynamicSharedMemorySize, FIN_SMEM);

    gru_mma_kernel<<<(N_ + 31) / 32, 512, GRU_SMEM>>>(actions, hidden, W_ih, W_hh, b_ih, b_hh, h_out);
    zero_deg_kernel<<<(N_ + 255) / 256, 256>>>();
    zero_agg_kernel<<<N_ * H_ / 4 / 256, 256>>>();
    degree_kernel<<<E_ / 256, 256>>>(src, dst);
    ln_scale_kernel<<<N_ / 8, 256>>>(h_out, ln_g, ln_b);
    scatter_kernel<<<E_ * 32 / 256, 256>>>(src, dst);
    final_kernel<<<148, 512, FIN_SMEM>>>(Wg, bg, Wa_mu, ba_mu, Wa_sd, ba_sd,
                                         Wz_mu, bz_mu, Wz_sd, bz_sd, out);
}

// round 16
// speedup vs baseline: 6.4137x; 1.0562x over previous
#include <cuda_runtime.h>
#include <cuda_fp16.h>
#include <math.h>

#define N_  50000
#define T_  25
#define A_  16
#define H_  128
#define I_  64
#define E_  800000
#define NTILES 1563   // ceil(N/32)
#define GRID_GRU 296  // 2 CTAs/SM * 148 SMs

// Scratch (no allocations allowed): device globals.
__device__ float g_xln[N_ * H_];
__device__ float g_agg[N_ * H_];
__device__ float g_deg_out[N_];
__device__ float g_deg_in[N_];

__device__ __forceinline__ float softplusf(float x) {
    return x > 0.f ? x + log1pf(expf(-x)) : log1pf(expf(x));
}

// ===========================================================================
// GRU via mma.sync fp16 (HMMA), single-pass, 2 CTAs/SM, PERSISTENT (296
// blocks loop over 32-row tiles; W staged once per block). LayerNorm +
// deg_out^-0.5 scaling fused into the epilogue of the last step (two 16-row
// passes through an 8KB f32 buffer aliasing the AH region) -> writes g_xln
// and h_out directly; ln_scale kernel deleted. degree runs BEFORE gru.
// smem (110592 B/CTA -> 2 CTAs fit 228KB):
//   WHH 0..98304       (fp16, persistent across tiles)
//   BX  98304..110592  (W_ih staging; after hoist aliased by AH/AX/LNbuf)
//   AH  98304..106496  (32r x 128k fp16; also 16r x 128 f32 LN buffer)
//   AX  106496..108544 (32r x 16k fp16)
// ===========================================================================
#define OFF_WHH   0
#define OFF_BX    98304
#define OFF_AH    98304
#define OFF_AX    106496
#define GRU_SMEM  110592

__device__ __forceinline__ unsigned s2u(const void* p) {
    unsigned a;
    asm("{ .reg .u64 t; cvta.to.shared.u64 t, %1; cvt.u32.u64 %0, t; }"
        : "=r"(a) : "l"(p));
    return a;
}
__device__ __forceinline__ int offW(int k, int c) {   // row stride 768B
    return k * 768 + ((((c >> 3) ^ (k & 7)) << 4) + ((c & 7) << 1));
}
__device__ __forceinline__ int offA(int r, int k) {   // row stride 256B
    return r * 256 + ((((k >> 3) ^ (r & 7)) << 4) + ((k & 7) << 1));
}
__device__ __forceinline__ int offX(int r, int k) {   // row stride 64B
    return r * 64 + ((((k >> 3) ^ (r & 3)) << 4) + ((k & 7) << 1));
}

__device__ __forceinline__ void ldmA(unsigned addr, unsigned& a0, unsigned& a1,
                                     unsigned& a2, unsigned& a3) {
    asm volatile("ldmatrix.sync.aligned.m8n8.x4.shared.b16 {%0,%1,%2,%3}, [%4];"
                 : "=r"(a0), "=r"(a1), "=r"(a2), "=r"(a3) : "r"(addr));
}
__device__ __forceinline__ void ldmB(unsigned addr, unsigned& b0, unsigned& b1) {
    asm volatile("ldmatrix.sync.aligned.m8n8.x2.trans.shared.b16 {%0,%1}, [%2];"
                 : "=r"(b0), "=r"(b1) : "r"(addr));
}
__device__ __forceinline__ void mma16816(float d[4], unsigned a0, unsigned a1,
                                         unsigned a2, unsigned a3,
                                         unsigned b0, unsigned b1) {
    asm volatile(
        "mma.sync.aligned.m16n8k16.row.col.f32.f16.f16.f32 "
        "{%0,%1,%2,%3},{%4,%5,%6,%7},{%8,%9},{%0,%1,%2,%3};"
        : "+f"(d[0]), "+f"(d[1]), "+f"(d[2]), "+f"(d[3])
        : "r"(a0), "r"(a1), "r"(a2), "r"(a3), "r"(b0), "r"(b1));
}

__device__ __forceinline__ unsigned short fh(float x) {
    return __half_as_ushort(__float2half(x));
}
__device__ __forceinline__ float tanha(float x) {
    float y;
    asm("tanh.approx.f32 %0, %1;" : "=f"(y) : "f"(x));
    return y;
}

__global__ void __launch_bounds__(512, 2) gru_mma_kernel(
    const float* __restrict__ actions,  // (N, T, A)
    const float* __restrict__ hidden,   // (1, N, H)
    const float* __restrict__ W_ih,     // (3H, A)
    const float* __restrict__ W_hh,     // (3H, H)
    const float* __restrict__ b_ih,     // (3H)
    const float* __restrict__ b_hh,     // (3H)
    const float* __restrict__ ln_g,     // (H)
    const float* __restrict__ ln_b,     // (H)
    float* __restrict__ h_out)          // (N, H)
{
    extern __shared__ char sm[];
    const unsigned sb = s2u(sm);
    const int tid  = threadIdx.x;
    const int w    = tid >> 5;        // warp 0..15
    const int lane = tid & 31;

    // ================= stage W once per block ==============
    for (int idx = tid; idx < 384 * 128; idx += 512) {
        int c = idx >> 7, k = idx & 127;
        *(unsigned short*)(sm + OFF_WHH + offW(k, c)) = fh(__ldg(W_hh + idx));
    }
    for (int idx = tid; idx < 384 * 16; idx += 512) {
        int c = idx >> 4, a = idx & 15;
        *(unsigned short*)(sm + OFF_BX + offW(a, c)) = fh(__ldg(W_ih + idx));
    }
    __syncthreads();

    // ================= hoist W_ih fragments (6 regs) =========
    const int l15 = lane & 15, l7 = lane & 7, hb = lane >> 4;
    const unsigned bRow = (unsigned)(l15 * 768);
    int ctile[3];
    #pragma unroll
    for (int g = 0; g < 3; ++g) ctile[g] = (((g << 4) + w) ^ l7) << 4;

    unsigned bx[3][2];
    {
        unsigned kb = sb + OFF_BX + bRow;
        #pragma unroll
        for (int g = 0; g < 3; ++g)
            ldmB(kb + ctile[g], bx[g][0], bx[g][1]);
    }

    // ---- per-thread unit/bias setup (tile-invariant) ----
    const int tr = lane >> 2;
    const int j0 = (w << 3) + ((lane & 3) << 1);
    float br[2], bz[2], bin[2], bhn[2];
    #pragma unroll
    for (int q = 0; q < 2; ++q) {
        int j = j0 + q;
        br[q]  = __ldg(b_ih + j)       + __ldg(b_hh + j);
        bz[q]  = __ldg(b_ih + 128 + j) + __ldg(b_hh + 128 + j);
        bin[q] = __ldg(b_ih + 256 + j);
        bhn[q] = __ldg(b_hh + 256 + j);
    }
    float* bufA = (float*)(sm + OFF_AH);   // 16r x 128 f32 LN buffer (aliases AH)

    __syncthreads();   // bx hoist reads done

    // ===================== persistent tile loop ============================
    for (int tile = blockIdx.x; tile < NTILES; tile += GRID_GRU) {
        const int grow0 = tile << 5;

        // ---- stage A tiles ----
        for (int idx = tid; idx < 32 * 128; idx += 512) {
            int r = idx >> 7, k = idx & 127;
            int gr = grow0 + r; if (gr >= N_) gr = N_ - 1;
            float v = __ldg(hidden + (size_t)gr * H_ + k);
            *(unsigned short*)(sm + OFF_AH + offA(r, k)) = fh(v);
        }
        {   // x_0
            int r = tid >> 4, a = tid & 15;
            int gr = grow0 + r; if (gr >= N_) gr = N_ - 1;
            float v = __ldg(actions + (size_t)gr * (T_ * A_) + a);
            *(unsigned short*)(sm + OFF_AX + offX(r, a)) = fh(v);
        }

        // ---- h state in fp32 registers ----
        float hold[8];
        #pragma unroll
        for (int rt = 0; rt < 2; ++rt)
            #pragma unroll
            for (int s = 0; s < 2; ++s) {
                int gr = grow0 + 16 * rt + tr + 8 * s;
                if (gr >= N_) gr = N_ - 1;
                float2 hv = *reinterpret_cast<const float2*>(hidden + (size_t)gr * H_ + j0);
                hold[rt * 4 + s * 2]     = hv.x;
                hold[rt * 4 + s * 2 + 1] = hv.y;
            }

        const int xr = tid >> 4, xa = tid & 15;
        int xgr = grow0 + xr; if (xgr >= N_) xgr = N_ - 1;
        const float* xsrc = actions + (size_t)xgr * (T_ * A_) + xa;

        __syncthreads();

        for (int t = 0; t < T_; ++t) {
            float xpre = 0.f;
            if (t + 1 < T_) xpre = __ldg(xsrc + (t + 1) * A_);

            float accR[2][4] = {}, accZ[2][4] = {}, accN[2][4] = {}, accNI[2][4] = {};

            // ---- h pass: 8 ksteps ----
            #pragma unroll
            for (int ks = 0; ks < 8; ++ks) {
                unsigned wl[3][2];
                {
                    unsigned kb = sb + OFF_WHH + bRow + (unsigned)(ks * 12288);
                    #pragma unroll
                    for (int g = 0; g < 3; ++g)
                        ldmB(kb + ctile[g], wl[g][0], wl[g][1]);
                }
                unsigned koff = (unsigned)((((ks << 1) + hb) ^ l7) << 4);
                #pragma unroll
                for (int rt = 0; rt < 2; ++rt) {
                    unsigned abase = sb + OFF_AH + (unsigned)((16 * rt + l15) * 256) + koff;
                    unsigned ah0, ah1, ah2, ah3;
                    ldmA(abase, ah0, ah1, ah2, ah3);
                    #pragma unroll
                    for (int g = 0; g < 3; ++g) {
                        float* acc = (g == 0) ? accR[rt] : (g == 1) ? accZ[rt] : accN[rt];
                        mma16816(acc, ah0, ah1, ah2, ah3, wl[g][0], wl[g][1]);
                    }
                }
            }
            // ---- x pass ----
            #pragma unroll
            for (int rt = 0; rt < 2; ++rt) {
                unsigned xbase = sb + OFF_AX + (unsigned)((16 * rt + l15) * 64);
                unsigned xh0, xh1, xh2, xh3;
                ldmA(xbase + (unsigned)((hb ^ (l15 & 3)) << 4), xh0, xh1, xh2, xh3);
                #pragma unroll
                for (int g = 0; g < 3; ++g) {
                    float* dst = (g == 0) ? accR[rt] : (g == 1) ? accZ[rt] : accNI[rt];
                    mma16816(dst, xh0, xh1, xh2, xh3, bx[g][0], bx[g][1]);
                }
            }

            __syncthreads();   // all smem reads of AH/AX complete

            // ---- gate math ----
            #pragma unroll
            for (int rt = 0; rt < 2; ++rt)
                #pragma unroll
                for (int s = 0; s < 2; ++s) {
                    float hn2[2];
                    #pragma unroll
                    for (int q = 0; q < 2; ++q) {
                        int i = s * 2 + q;
                        float pr = accR[rt][i] + br[q];
                        float pz = accZ[rt][i] + bz[q];
                        float gn = accN[rt][i] + bhn[q];
                        float gi = accNI[rt][i] + bin[q];
                        float rg = fmaf(0.5f, tanha(0.5f * pr), 0.5f);
                        float zg = fmaf(0.5f, tanha(0.5f * pz), 0.5f);
                        float pre = fmaf(rg, gn, gi);
                        float ng = tanha(pre);
                        float hn = fmaf(zg, hold[rt * 4 + i] - ng, ng);
                        hold[rt * 4 + i] = hn;
                        hn2[q] = hn;
                    }
                    int row = 16 * rt + tr + (s << 3);
                    if (t == T_ - 1) {
                        if (rt == 0)   // rows 0..15 -> f32 LN buffer
                            *reinterpret_cast<float2*>(bufA + (row << 7) + j0) =
                                make_float2(hn2[0], hn2[1]);
                        // rt==1 stays in hold[4..7] for pass B
                    } else {
                        int o = offA(row, j0);
                        unsigned uh = (unsigned)fh(hn2[0]) | ((unsigned)fh(hn2[1]) << 16);
                        *(unsigned*)(sm + OFF_AH + o) = uh;
                    }
                }

            if (t + 1 < T_) {
                *(unsigned short*)(sm + OFF_AX + offX(xr, xa)) = fh(xpre);
                __syncthreads();
            }
        }

        // ================= fused LayerNorm + src-scale ======================
        #pragma unroll
        for (int pass = 0; pass < 2; ++pass) {
            __syncthreads();   // buffer writes visible
            // warp w handles local row (pass*16 + w), buffer row w
            float4 v = reinterpret_cast<float4*>(bufA)[(w << 5) + lane];
            float s  = v.x + v.y + v.z + v.w;
            float ss = v.x * v.x + v.y * v.y + v.z * v.z + v.w * v.w;
            #pragma unroll
            for (int o = 16; o > 0; o >>= 1) {
                s  += __shfl_xor_sync(0xffffffffu, s, o);
                ss += __shfl_xor_sync(0xffffffffu, ss, o);
            }
            float mu  = s * (1.f / 128.f);
            float var = ss * (1.f / 128.f) - mu * mu;
            float inv = rsqrtf(var + 1e-5f);
            int grow = grow0 + pass * 16 + w;
            if (grow < N_) {
                float dg = g_deg_out[grow];
                float ns = dg > 0.f ? rsqrtf(dg) : 1.f;
                float4 g4 = __ldg(reinterpret_cast<const float4*>(ln_g) + lane);
                float4 b4 = __ldg(reinterpret_cast<const float4*>(ln_b) + lane);
                float4 o4;
                o4.x = ((v.x - mu) * inv * g4.x + b4.x) * ns;
                o4.y = ((v.y - mu) * inv * g4.y + b4.y) * ns;
                o4.z = ((v.z - mu) * inv * g4.z + b4.z) * ns;
                o4.w = ((v.w - mu) * inv * g4.w + b4.w) * ns;
                *reinterpret_cast<float4*>(g_xln + (size_t)grow * H_ + (lane << 2)) = o4;
                *reinterpret_cast<float4*>(h_out + (size_t)grow * H_ + (lane << 2)) = v;
            }
            __syncthreads();   // pass reads done
            if (pass == 0) {
                // write rt=1 rows (local 16..31) into buffer rows 0..15
                #pragma unroll
                for (int s2 = 0; s2 < 2; ++s2) {
                    int browi = tr + (s2 << 3);
                    *reinterpret_cast<float2*>(bufA + (browi << 7) + j0) =
                        make_float2(hold[4 + s2 * 2], hold[4 + s2 * 2 + 1]);
                }
            }
        }
        __syncthreads();   // LN done before next tile restages AH
    }
}

// ===========================================================================
// Small graph kernels
// ===========================================================================
__global__ void zero_deg_kernel() {
    int i = blockIdx.x * 256 + threadIdx.x;
    if (i < N_) { g_deg_in[i] = 0.f; g_deg_out[i] = 0.f; }
}
__global__ void zero_agg_kernel() {
    int i = blockIdx.x * 256 + threadIdx.x;
    reinterpret_cast<float4*>(g_agg)[i] = make_float4(0.f, 0.f, 0.f, 0.f);
}
__global__ void degree_kernel(const int* __restrict__ src, const int* __restrict__ dst) {
    int e = blockIdx.x * 256 + threadIdx.x;
    atomicAdd(&g_deg_out[__ldg(src + e)], 1.f);
    atomicAdd(&g_deg_in[__ldg(dst + e)], 1.f);
}
__global__ void scatter_kernel(const int* __restrict__ src, const int* __restrict__ dst) {
    int gid = blockIdx.x * 256 + threadIdx.x;
    int e = gid >> 5, c = gid & 31;
    int s = __ldg(src + e), d = __ldg(dst + e);
    float4 v = *reinterpret_cast<const float4*>(g_xln + (size_t)s * H_ + (c << 2));
    atomicAdd(reinterpret_cast<float4*>(g_agg + (size_t)d * H_ + (c << 2)), v);
}

// ===========================================================================
// Persistent fused GraphConv + heads (unchanged from R15).
// ===========================================================================
#define FIN_SMEM ((128 * 32 + 128 * 64) * 16 + 2 * 16 * 128 * 4)   // 212992

__global__ void __launch_bounds__(512, 1) final_kernel(
    const float* __restrict__ Wg,    const float* __restrict__ bg,
    const float* __restrict__ Wa_mu, const float* __restrict__ ba_mu,
    const float* __restrict__ Wa_sd, const float* __restrict__ ba_sd,
    const float* __restrict__ Wz_mu, const float* __restrict__ bz_mu,
    const float* __restrict__ Wz_sd, const float* __restrict__ bz_sd,
    float* __restrict__ out)
{
    extern __shared__ float fsm[];
    float4* Wg4 = reinterpret_cast<float4*>(fsm);            // [128][32]
    float4* Wt4 = Wg4 + 128 * 32;                            // [128][64]
    float*  tb  = reinterpret_cast<float*>(Wt4 + 128 * 64);  // [16][128]
    float*  yb  = tb + 16 * 128;                             // [16][128]

    const int tid  = threadIdx.x;
    const int rw   = tid >> 5;
    const int lane = tid & 31;

    for (int idx = tid; idx < 128 * 32; idx += 512) {
        int k = idx >> 5, j = idx & 31;
        Wg4[(k << 5) + j] = make_float4(
            __ldg(Wg + (k << 7) + j),      __ldg(Wg + (k << 7) + j + 32),
            __ldg(Wg + (k << 7) + j + 64), __ldg(Wg + (k << 7) + j + 96));
    }
    for (int idx = tid; idx < 128 * 64; idx += 512) {
        int k = idx >> 6, i = idx & 63;
        int o = (i << 7) + k;
        Wt4[(k << 6) + i] = make_float4(__ldg(Wa_mu + o), __ldg(Wa_sd + o),
                                        __ldg(Wz_mu + o), __ldg(Wz_sd + o));
    }
    __syncthreads();

    float bgq[4];
    #pragma unroll
    for (int q = 0; q < 4; ++q) bgq[q] = __ldg(bg + lane + (q << 5));
    float bam[2], bas[2], bzm[2], bzs[2];
    #pragma unroll
    for (int q = 0; q < 2; ++q) {
        int i = lane + (q << 5);
        bam[q] = __ldg(ba_mu + i);  bas[q] = __ldg(ba_sd + i);
        bzm[q] = __ldg(bz_mu + i);  bzs[q] = __ldg(bz_sd + i);
    }

    const int NI = N_ * I_;
    float* tbr = tb + (rw << 7);
    float* ybr = yb + (rw << 7);

    for (int tile = blockIdx.x; tile < N_ / 16; tile += 148) {
        int row = (tile << 4) + rw;

        {
            float dg = g_deg_in[row];
            float nd = dg > 0.f ? rsqrtf(dg) : 1.f;
            float4 v = *reinterpret_cast<const float4*>(g_agg + (size_t)row * H_ + (lane << 2));
            v.x *= nd; v.y *= nd; v.z *= nd; v.w *= nd;
            *reinterpret_cast<float4*>(tbr + (lane << 2)) = v;
        }
        __syncwarp();

        float acc[4] = {0.f, 0.f, 0.f, 0.f};
        #pragma unroll 4
        for (int k = 0; k < 128; ++k) {
            float tv = tbr[k];
            float4 wg = Wg4[(k << 5) + lane];
            acc[0] = fmaf(tv, wg.x, acc[0]);
            acc[1] = fmaf(tv, wg.y, acc[1]);
            acc[2] = fmaf(tv, wg.z, acc[2]);
            acc[3] = fmaf(tv, wg.w, acc[3]);
        }
        #pragma unroll
        for (int q = 0; q < 4; ++q)
            ybr[lane + (q << 5)] = acc[q] + bgq[q];
        __syncwarp();

        float am[2] = {0.f, 0.f}, as[2] = {0.f, 0.f};
        float zm[2] = {0.f, 0.f}, zs[2] = {0.f, 0.f};
        #pragma unroll 4
        for (int k = 0; k < 128; ++k) {
            float yv = ybr[k];
            float4 w0 = Wt4[(k << 6) + lane];
            float4 w1 = Wt4[(k << 6) + lane + 32];
            am[0] = fmaf(yv, w0.x, am[0]);  am[1] = fmaf(yv, w1.x, am[1]);
            as[0] = fmaf(yv, w0.y, as[0]);  as[1] = fmaf(yv, w1.y, as[1]);
            zm[0] = fmaf(yv, w0.z, zm[0]);  zm[1] = fmaf(yv, w1.z, zm[1]);
            zs[0] = fmaf(yv, w0.w, zs[0]);  zs[1] = fmaf(yv, w1.w, zs[1]);
        }
        #pragma unroll
        for (int q = 0; q < 2; ++q) {
            int i = lane + (q << 5);
            out[2 * NI + (size_t)row * I_ + i] = am[q] + bam[q];
            out[3 * NI + (size_t)row * I_ + i] = softplusf(as[q] + bas[q]);
            out[0      + (size_t)row * I_ + i] = zm[q] + bzm[q];
            out[1 * NI + (size_t)row * I_ + i] = softplusf(zs[q] + bzs[q]);
        }
        __syncwarp();
    }
}

// ---------------------------------------------------------------------------
extern "C" void kernel_launch(void* const* d_in, const int* in_sizes, int n_in,
                              void* d_out, int out_size) {
    const float* actions = (const float*)d_in[0];
    const float* hidden  = (const float*)d_in[1];
    const int*   src     = (const int*)d_in[2];
    const int*   dst     = (const int*)d_in[3];
    const float* W_ih    = (const float*)d_in[4];
    const float* W_hh    = (const float*)d_in[5];
    const float* b_ih    = (const float*)d_in[6];
    const float* b_hh    = (const float*)d_in[7];
    const float* ln_g    = (const float*)d_in[8];
    const float* ln_b    = (const float*)d_in[9];
    const float* Wg      = (const float*)d_in[10];
    const float* bg      = (const float*)d_in[11];
    const float* Wa_mu   = (const float*)d_in[12];
    const float* ba_mu   = (const float*)d_in[13];
    const float* Wa_sd   = (const float*)d_in[14];
    const float* ba_sd   = (const float*)d_in[15];
    const float* Wz_mu   = (const float*)d_in[16];
    const float* bz_mu   = (const float*)d_in[17];
    const float* Wz_sd   = (const float*)d_in[18];
    const float* bz_sd   = (const float*)d_in[19];

    float* out   = (float*)d_out;
    float* h_out = out + 4 * N_ * I_;

    cudaFuncSetAttribute(gru_mma_kernel, cudaFuncAttributeMaxDynamicSharedMemorySize, GRU_SMEM);
    cudaFuncSetAttribute(final_kernel, cudaFuncAttributeMaxDynamicSharedMemorySize, FIN_SMEM);

    // degree/zeroing first (independent of GRU; deg_out needed by fused LN)
    zero_deg_kernel<<<(N_ + 255) / 256, 256>>>();
    zero_agg_kernel<<<N_ * H_ / 4 / 256, 256>>>();
    degree_kernel<<<E_ / 256, 256>>>(src, dst);
    gru_mma_kernel<<<GRID_GRU, 512, GRU_SMEM>>>(actions, hidden, W_ih, W_hh,
                                                b_ih, b_hh, ln_g, ln_b, h_out);
    scatter_kernel<<<E_ * 32 / 256, 256>>>(src, dst);
    final_kernel<<<148, 512, FIN_SMEM>>>(Wg, bg, Wa_mu, ba_mu, Wa_sd, ba_sd,
                                         Wz_mu, bz_mu, Wz_sd, bz_sd, out);
}